// round 3
// baseline (speedup 1.0000x reference)
#include <cuda_runtime.h>
#include <stddef.h>

#define N_NODES 100000
#define N_EDGES 300000
#define NGRAPHS 3000
#define D 256
#define MSG_EPS 1e-7f
#define LN_EPS  1e-5f

// ---------------- scratch (static device allocations; no cudaMalloc) ----------------
__device__ __align__(16) float g_h  [(size_t)N_NODES * D];
__device__ __align__(16) float g_h2 [(size_t)N_NODES * D];
__device__ __align__(16) float g_agg[(size_t)N_NODES * D];
__device__ __align__(16) float g_vn [(size_t)NGRAPHS * D];
__device__ int g_off[NGRAPHS + 1];

// ---------------- node init: atom embedding sum, h_init out, h = h0 + vn_emb ----------------
__global__ void node_init_kernel(const int* __restrict__ x,
                                 const float* __restrict__ atom_emb,
                                 const float* __restrict__ vn_emb,
                                 float* __restrict__ h,
                                 float* __restrict__ agg,
                                 float* __restrict__ vn,
                                 float* __restrict__ out_hinit)
{
    int n = blockIdx.x;
    int d = threadIdx.x;
    __shared__ int xi[9];
    if (d < 9) xi[d] = x[n * 9 + d];
    __syncthreads();
    float s = 0.f;
#pragma unroll
    for (int f = 0; f < 9; f++)
        s += atom_emb[((size_t)f * 64 + xi[f]) * D + d];
    size_t idx = (size_t)n * D + d;
    out_hinit[idx] = s;
    h[idx] = s + vn_emb[d];
    agg[idx] = 0.f;
    if (n < NGRAPHS) vn[(size_t)n * D + d] = vn_emb[d];
}

// ---------------- graph segment offsets via binary search (batch is sorted) ----------------
__global__ void offsets_kernel(const int* __restrict__ batch, int* __restrict__ off)
{
    int g = blockIdx.x * blockDim.x + threadIdx.x;
    if (g > NGRAPHS) return;
    int lo = 0, hi = N_NODES;
    while (lo < hi) {
        int mid = (lo + hi) >> 1;
        if (batch[mid] < g) lo = mid + 1; else hi = mid;
    }
    off[g] = lo;
}

// ---------------- edge messages: msg = relu(h[src]+edge_emb)+eps, scatter-add to agg[dst] ----------------
__global__ void edge_msg_kernel(const float4* __restrict__ hin,
                                const int* __restrict__ ei,
                                const int* __restrict__ ea,
                                const float4* __restrict__ bond,   // [3][8][64] float4
                                float* __restrict__ agg)
{
    int e = blockIdx.x * 4 + (threadIdx.x >> 6);
    if (e >= N_EDGES) return;
    int q = threadIdx.x & 63;
    int src = __ldg(&ei[e]);
    int dst = __ldg(&ei[N_EDGES + e]);
    int a0 = __ldg(&ea[3 * e + 0]);
    int a1 = __ldg(&ea[3 * e + 1]);
    int a2 = __ldg(&ea[3 * e + 2]);
    float4 v  = hin[(size_t)src * 64 + q];
    float4 b0 = bond[(size_t)(0 * 8 + a0) * 64 + q];
    float4 b1 = bond[(size_t)(1 * 8 + a1) * 64 + q];
    float4 b2 = bond[(size_t)(2 * 8 + a2) * 64 + q];
    float mx = fmaxf(v.x + b0.x + b1.x + b2.x, 0.f) + MSG_EPS;
    float my = fmaxf(v.y + b0.y + b1.y + b2.y, 0.f) + MSG_EPS;
    float mz = fmaxf(v.z + b0.z + b1.z + b2.z, 0.f) + MSG_EPS;
    float mw = fmaxf(v.w + b0.w + b1.w + b2.w, 0.f) + MSG_EPS;
    float* base = &agg[(size_t)dst * D + q * 4];
    atomicAdd(base + 0, mx);
    atomicAdd(base + 1, my);
    atomicAdd(base + 2, mz);
    atomicAdd(base + 3, mw);
}

// ---------------- generic GEMM: out = (A1 [+A2]) @ W + bias [+ res] ----------------
// A: [M, 256] fp32 row-major. W: [256, BN] row-major. out row stride ldout.
template<int BN>
__global__ __launch_bounds__(256)
void gemm_kernel(const float* __restrict__ A1, const float* __restrict__ A2,
                 const float* __restrict__ W, const float* __restrict__ bias,
                 const float* __restrict__ res, float* __restrict__ out,
                 int M, int ldout)
{
    constexpr int BM = 64, BK = 32, K = D;
    constexpr int NG = BN / 64;
    __shared__ float As[BK][BM];
    __shared__ float Bs[BK][BN];
    const int tid = threadIdx.x;
    const int tx = tid & 15;        // 16 col-groups
    const int ty = tid >> 4;        // 16 row-groups
    const int m0 = blockIdx.x * BM;

    float acc[4][NG * 4];
#pragma unroll
    for (int i = 0; i < 4; i++)
#pragma unroll
        for (int j = 0; j < NG * 4; j++) acc[i][j] = 0.f;

    for (int k0 = 0; k0 < K; k0 += BK) {
        // --- load A tile (64 x 32), transposed into As[k][m], zero-padded past M ---
        {
            int r  = tid >> 3;            // 0..31
            int kc = (tid & 7) * 4;       // 0..28
#pragma unroll
            for (int it = 0; it < 2; it++) {
                int row = r + it * 32;
                int m = m0 + row;
                float4 v = make_float4(0.f, 0.f, 0.f, 0.f);
                if (m < M) {
                    v = *reinterpret_cast<const float4*>(&A1[(size_t)m * K + k0 + kc]);
                    if (A2) {
                        float4 w = *reinterpret_cast<const float4*>(&A2[(size_t)m * K + k0 + kc]);
                        v.x += w.x; v.y += w.y; v.z += w.z; v.w += w.w;
                    }
                }
                As[kc + 0][row] = v.x;
                As[kc + 1][row] = v.y;
                As[kc + 2][row] = v.z;
                As[kc + 3][row] = v.w;
            }
        }
        // --- load B tile (32 x BN) ---
        {
            constexpr int PASS = (BK * BN) / 1024;
            constexpr int RP   = 1024 / BN;
            int c4 = (tid % (BN / 4)) * 4;
            int rr = tid / (BN / 4);
#pragma unroll
            for (int it = 0; it < PASS; it++) {
                int kk = rr + it * RP;
                float4 v = *reinterpret_cast<const float4*>(&W[(size_t)(k0 + kk) * BN + c4]);
                *reinterpret_cast<float4*>(&Bs[kk][c4]) = v;
            }
        }
        __syncthreads();
#pragma unroll
        for (int k = 0; k < BK; k++) {
            float4 a4 = *reinterpret_cast<const float4*>(&As[k][ty * 4]);
            float av[4] = {a4.x, a4.y, a4.z, a4.w};
#pragma unroll
            for (int g = 0; g < NG; g++) {
                float4 b4 = *reinterpret_cast<const float4*>(&Bs[k][g * 64 + tx * 4]);
                float bv[4] = {b4.x, b4.y, b4.z, b4.w};
#pragma unroll
                for (int i = 0; i < 4; i++)
#pragma unroll
                    for (int j = 0; j < 4; j++)
                        acc[i][g * 4 + j] = fmaf(av[i], bv[j], acc[i][g * 4 + j]);
            }
        }
        __syncthreads();
    }
    // --- epilogue ---
#pragma unroll
    for (int i = 0; i < 4; i++) {
        int m = m0 + ty * 4 + i;
        if (m >= M) continue;
#pragma unroll
        for (int g = 0; g < NG; g++) {
            int c = g * 64 + tx * 4;
            float4 v;
            v.x = acc[i][g * 4 + 0] + bias[c + 0];
            v.y = acc[i][g * 4 + 1] + bias[c + 1];
            v.z = acc[i][g * 4 + 2] + bias[c + 2];
            v.w = acc[i][g * 4 + 3] + bias[c + 3];
            if (res) {
                float4 r4 = *reinterpret_cast<const float4*>(&res[(size_t)m * D + c]);
                v.x += r4.x; v.y += r4.y; v.z += r4.z; v.w += r4.w;
            }
            *reinterpret_cast<float4*>(&out[(size_t)m * ldout + c]) = v;
        }
    }
}

// ---------------- LayerNorm + ReLU per node (also zeroes agg for next conv) ----------------
__global__ void ln_relu_kernel(const float* __restrict__ h,
                               const float* __restrict__ gam,
                               const float* __restrict__ bet,
                               float* __restrict__ h2,
                               float* __restrict__ agg)
{
    int n = blockIdx.x, d = threadIdx.x;
    size_t idx = (size_t)n * D + d;
    float v = h[idx];
    float a = v, b = v * v;
    __shared__ float sa[8], sb[8];
    int lane = d & 31, w = d >> 5;
#pragma unroll
    for (int o = 16; o; o >>= 1) {
        a += __shfl_down_sync(0xffffffffu, a, o);
        b += __shfl_down_sync(0xffffffffu, b, o);
    }
    if (lane == 0) { sa[w] = a; sb[w] = b; }
    __syncthreads();
    if (w == 0) {
        a = (lane < 8) ? sa[lane] : 0.f;
        b = (lane < 8) ? sb[lane] : 0.f;
#pragma unroll
        for (int o = 4; o; o >>= 1) {
            a += __shfl_down_sync(0xffffffffu, a, o);
            b += __shfl_down_sync(0xffffffffu, b, o);
        }
        if (lane == 0) { sa[0] = a; sb[0] = b; }
    }
    __syncthreads();
    float mu  = sa[0] * (1.f / D);
    float var = sb[0] * (1.f / D) - mu * mu;
    float y = (v - mu) * rsqrtf(var + LN_EPS) * gam[d] + bet[d];
    h2[idx]  = fmaxf(y, 0.f);
    agg[idx] = 0.f;
}

// ---------------- virtual-node path: vn = MLP(segment_sum(h2) + vn), 8 graphs/block ----------------
__device__ __forceinline__ void ln_rows8(float (*t)[D], float (*s)[D],
                                         const float* __restrict__ gam,
                                         const float* __restrict__ bet,
                                         float* smu, float* srs)
{
    int lane = threadIdx.x & 31, w = threadIdx.x >> 5;   // warp w handles graph w
    float a = 0.f, b = 0.f;
#pragma unroll
    for (int i = 0; i < 8; i++) {
        float v = t[w][lane + 32 * i];
        a += v; b += v * v;
    }
#pragma unroll
    for (int o = 16; o; o >>= 1) {
        a += __shfl_down_sync(0xffffffffu, a, o);
        b += __shfl_down_sync(0xffffffffu, b, o);
    }
    if (lane == 0) {
        float mu = a * (1.f / D);
        float var = b * (1.f / D) - mu * mu;
        smu[w] = mu;
        srs[w] = rsqrtf(var + LN_EPS);
    }
    __syncthreads();
    int d = threadIdx.x;
    float gd = gam[d], bd = bet[d];
#pragma unroll
    for (int gg = 0; gg < 8; gg++) {
        float v = (t[gg][d] - smu[gg]) * srs[gg] * gd + bd;
        s[gg][d] = fmaxf(v, 0.f);
    }
}

__global__ void vn_mlp_kernel(const float* __restrict__ h2, const int* __restrict__ off,
                              const float* __restrict__ W1, const float* __restrict__ b1,
                              const float* __restrict__ g1, const float* __restrict__ be1,
                              const float* __restrict__ W2, const float* __restrict__ b2,
                              const float* __restrict__ g2, const float* __restrict__ be2,
                              float* __restrict__ vn)
{
    __shared__ float s[8][D];
    __shared__ float t[8][D];
    __shared__ float smu[8], srs[8];
    int d = threadIdx.x;
    int g0 = blockIdx.x * 8;

    // segment sum + current vn
#pragma unroll
    for (int gg = 0; gg < 8; gg++) {
        int g = g0 + gg;
        float acc = vn[(size_t)g * D + d];
        int n1 = off[g + 1];
        for (int n = off[g]; n < n1; n++)
            acc += h2[(size_t)n * D + d];
        s[gg][d] = acc;
    }
    __syncthreads();

    // linear 1
    float y[8];
#pragma unroll
    for (int gg = 0; gg < 8; gg++) y[gg] = b1[d];
    for (int k = 0; k < D; k++) {
        float w = W1[(size_t)k * D + d];
#pragma unroll
        for (int gg = 0; gg < 8; gg++) y[gg] = fmaf(s[gg][k], w, y[gg]);
    }
    __syncthreads();
#pragma unroll
    for (int gg = 0; gg < 8; gg++) t[gg][d] = y[gg];
    __syncthreads();
    ln_rows8(t, s, g1, be1, smu, srs);   // s = relu(LN(t))
    __syncthreads();

    // linear 2
#pragma unroll
    for (int gg = 0; gg < 8; gg++) y[gg] = b2[d];
    for (int k = 0; k < D; k++) {
        float w = W2[(size_t)k * D + d];
#pragma unroll
        for (int gg = 0; gg < 8; gg++) y[gg] = fmaf(s[gg][k], w, y[gg]);
    }
    __syncthreads();
#pragma unroll
    for (int gg = 0; gg < 8; gg++) t[gg][d] = y[gg];
    __syncthreads();
    ln_rows8(t, s, g2, be2, smu, srs);
    __syncthreads();
#pragma unroll
    for (int gg = 0; gg < 8; gg++)
        vn[(size_t)(g0 + gg) * D + d] = s[gg][d];
}

// ---------------- h2 += vn[batch] ----------------
__global__ void add_vn_kernel(float* __restrict__ h2, const int* __restrict__ batch,
                              const float* __restrict__ vn)
{
    int n = blockIdx.x, d = threadIdx.x;
    __shared__ int bg;
    if (d == 0) bg = batch[n];
    __syncthreads();
    h2[(size_t)n * D + d] += vn[(size_t)bg * D + d];
}

// ---------------- launcher ----------------
extern "C" void kernel_launch(void* const* d_in, const int* in_sizes, int n_in,
                              void* d_out, int out_size)
{
    const int*   x          = (const int*)  d_in[0];
    const int*   edge_attr  = (const int*)  d_in[1];
    const int*   edge_index = (const int*)  d_in[2];
    const int*   batch      = (const int*)  d_in[3];
    const float* atom_emb   = (const float*)d_in[4];
    const float* bond_emb   = (const float*)d_in[5];
    const float* vn_emb     = (const float*)d_in[6];
    const float* gcn_w      = (const float*)d_in[7];
    const float* gcn_b      = (const float*)d_in[8];
    const float* norm_g     = (const float*)d_in[9];
    const float* norm_b     = (const float*)d_in[10];
    const float* ffn_w      = (const float*)d_in[11];
    const float* ffn_b      = (const float*)d_in[12];
    const float* vn_w1      = (const float*)d_in[13];
    const float* vn_b1      = (const float*)d_in[14];
    const float* vn_g1      = (const float*)d_in[15];
    const float* vn_be1     = (const float*)d_in[16];
    const float* vn_w2      = (const float*)d_in[17];
    const float* vn_b2      = (const float*)d_in[18];
    const float* vn_g2      = (const float*)d_in[19];
    const float* vn_be2     = (const float*)d_in[20];

    float* out       = (float*)d_out;                       // h_graph [N,256]
    float* out_hinit = out + (size_t)N_NODES * D;           // h_init  [N,256]

    float *ph, *ph2, *pagg, *pvn; int* poff;
    cudaGetSymbolAddress((void**)&ph,   g_h);
    cudaGetSymbolAddress((void**)&ph2,  g_h2);
    cudaGetSymbolAddress((void**)&pagg, g_agg);
    cudaGetSymbolAddress((void**)&pvn,  g_vn);
    cudaGetSymbolAddress((void**)&poff, g_off);

    const int GEMM_GRID = (N_NODES + 63) / 64;   // 1563
    const int EDGE_GRID = (N_EDGES + 3) / 4;     // 75000

    node_init_kernel<<<N_NODES, 256>>>(x, atom_emb, vn_emb, ph, pagg, pvn, out_hinit);
    offsets_kernel<<<(NGRAPHS + 1 + 255) / 256, 256>>>(batch, poff);

    // ----- layer 0 -----
    edge_msg_kernel<<<EDGE_GRID, 256>>>((const float4*)ph, edge_index, edge_attr,
                                        (const float4*)bond_emb, pagg);
    gemm_kernel<256><<<GEMM_GRID, 256>>>(ph, pagg, gcn_w, gcn_b, nullptr, ph, N_NODES, D);
    gemm_kernel<64><<<GEMM_GRID, 256>>>(ph, nullptr, ffn_w, ffn_b, nullptr, out, N_NODES, D);

    // ----- layers 1..3 (layers 4..6 are dead code: only out[0..3] reach h_graph) -----
    for (int l = 1; l < 4; l++) {
        int j = l - 1;
        ln_relu_kernel<<<N_NODES, 256>>>(ph, norm_g + (size_t)j * D, norm_b + (size_t)j * D, ph2, pagg);
        vn_mlp_kernel<<<NGRAPHS / 8, 256>>>(ph2, poff,
                                            vn_w1 + (size_t)j * D * D, vn_b1 + (size_t)j * D,
                                            vn_g1 + (size_t)j * D,     vn_be1 + (size_t)j * D,
                                            vn_w2 + (size_t)j * D * D, vn_b2 + (size_t)j * D,
                                            vn_g2 + (size_t)j * D,     vn_be2 + (size_t)j * D,
                                            pvn);
        add_vn_kernel<<<N_NODES, 256>>>(ph2, batch, pvn);
        edge_msg_kernel<<<EDGE_GRID, 256>>>((const float4*)ph2, edge_index, edge_attr,
                                            (const float4*)bond_emb, pagg);
        gemm_kernel<256><<<GEMM_GRID, 256>>>(ph2, pagg, gcn_w + (size_t)l * D * D,
                                             gcn_b + (size_t)l * D, ph, ph, N_NODES, D);
        gemm_kernel<64><<<GEMM_GRID, 256>>>(ph, nullptr, ffn_w + (size_t)l * D * 64,
                                            ffn_b + (size_t)l * 64, nullptr,
                                            out + (size_t)l * 64, N_NODES, D);
    }
}

// round 4
// speedup vs baseline: 1.1214x; 1.1214x over previous
#include <cuda_runtime.h>
#include <stddef.h>
#include <stdint.h>

#define N_NODES 100000
#define N_EDGES 300000
#define NGRAPHS 3000
#define D 256
#define MSG_EPS 1e-7f
#define LN_EPS  1e-5f

// ---------------- scratch (static device allocations; no cudaMalloc) ----------------
__device__ __align__(16) float g_h  [(size_t)N_NODES * D];
__device__ __align__(16) float g_h2 [(size_t)N_NODES * D];
__device__ __align__(16) float g_agg[(size_t)N_NODES * D];
__device__ __align__(16) float g_vn [(size_t)NGRAPHS * D];
__device__ int g_off[NGRAPHS + 1];

__device__ __forceinline__ void cp_async16(uint32_t smem_dst, const void* gsrc) {
    asm volatile("cp.async.cg.shared.global [%0], [%1], 16;\n"
                 :: "r"(smem_dst), "l"(gsrc));
}
__device__ __forceinline__ void cp_commit() {
    asm volatile("cp.async.commit_group;\n" ::);
}
__device__ __forceinline__ void cp_wait0() {
    asm volatile("cp.async.wait_group 0;\n" ::: "memory");
}

// ---------------- node init: atom embedding sum, h_init out, h = h0 + vn_emb ----------------
// also seeds agg = h (GEMM A-operand fusion: agg accumulates messages ON TOP of features)
__global__ void node_init_kernel(const int* __restrict__ x,
                                 const float* __restrict__ atom_emb,
                                 const float* __restrict__ vn_emb,
                                 float* __restrict__ h,
                                 float* __restrict__ agg,
                                 float* __restrict__ vn,
                                 float* __restrict__ out_hinit)
{
    int n = blockIdx.x;
    int d = threadIdx.x;
    __shared__ int xi[9];
    if (d < 9) xi[d] = x[n * 9 + d];
    __syncthreads();
    float s = 0.f;
#pragma unroll
    for (int f = 0; f < 9; f++)
        s += atom_emb[((size_t)f * 64 + xi[f]) * D + d];
    size_t idx = (size_t)n * D + d;
    out_hinit[idx] = s;
    float hv = s + vn_emb[d];
    h[idx]   = hv;
    agg[idx] = hv;                      // pre-seed with features
    if (n < NGRAPHS) vn[(size_t)n * D + d] = vn_emb[d];
}

// ---------------- graph segment offsets via binary search (batch is sorted) ----------------
__global__ void offsets_kernel(const int* __restrict__ batch, int* __restrict__ off)
{
    int g = blockIdx.x * blockDim.x + threadIdx.x;
    if (g > NGRAPHS) return;
    int lo = 0, hi = N_NODES;
    while (lo < hi) {
        int mid = (lo + hi) >> 1;
        if (batch[mid] < g) lo = mid + 1; else hi = mid;
    }
    off[g] = lo;
}

// ---------------- edge messages: msg = relu(h[src]+edge_emb)+eps, scatter-add to agg[dst] ----------------
__global__ void edge_msg_kernel(const float4* __restrict__ hin,
                                const int* __restrict__ ei,
                                const int* __restrict__ ea,
                                const float4* __restrict__ bond,   // [3][8][64] float4
                                float* __restrict__ agg)
{
    int e = blockIdx.x * 4 + (threadIdx.x >> 6);
    if (e >= N_EDGES) return;
    int q = threadIdx.x & 63;
    int src = __ldg(&ei[e]);
    int dst = __ldg(&ei[N_EDGES + e]);
    int a0 = __ldg(&ea[3 * e + 0]);
    int a1 = __ldg(&ea[3 * e + 1]);
    int a2 = __ldg(&ea[3 * e + 2]);
    float4 v  = hin[(size_t)src * 64 + q];
    float4 b0 = bond[(size_t)(0 * 8 + a0) * 64 + q];
    float4 b1 = bond[(size_t)(1 * 8 + a1) * 64 + q];
    float4 b2 = bond[(size_t)(2 * 8 + a2) * 64 + q];
    float mx = fmaxf(v.x + b0.x + b1.x + b2.x, 0.f) + MSG_EPS;
    float my = fmaxf(v.y + b0.y + b1.y + b2.y, 0.f) + MSG_EPS;
    float mz = fmaxf(v.z + b0.z + b1.z + b2.z, 0.f) + MSG_EPS;
    float mw = fmaxf(v.w + b0.w + b1.w + b2.w, 0.f) + MSG_EPS;
    float* base = &agg[(size_t)dst * D + q * 4];
    asm volatile("red.global.add.v4.f32 [%0], {%1, %2, %3, %4};\n"
                 :: "l"(base), "f"(mx), "f"(my), "f"(mz), "f"(mw) : "memory");
}

// ---------------- pipelined GEMM: out = A @ W + bias [+ res] ----------------
// A: [M, 256] fp32 row-major. W: [256, BN] row-major. Double-buffered smem,
// cp.async for W, register-staged transpose for A.
template<int BN>
__global__ __launch_bounds__(256)
void gemm_kernel(const float* __restrict__ A,
                 const float* __restrict__ W, const float* __restrict__ bias,
                 const float* __restrict__ res, float* __restrict__ out,
                 int M, int ldout)
{
    constexpr int BM = 64, BK = 16, K = D;
    constexpr int NG = BN / 64;
    constexpr int NITER = K / BK;
    __shared__ float As[2][BK][BM];
    __shared__ float Bs[2][BK][BN];
    const int tid = threadIdx.x;
    const int tx = tid & 15;        // 16 col-groups
    const int ty = tid >> 4;        // 16 row-groups
    const int m0 = blockIdx.x * BM;

    // A tile load mapping: thread -> (row, 4 consecutive k)
    const int arow = tid & 63;
    const int akc  = (tid >> 6) << 2;         // 0,4,8,12
    const bool valid = (m0 + arow) < M;
    const float* aptr = A + (size_t)(m0 + arow) * K + akc;

    // B tile cp.async mapping
    const int rb0 = (BN == 256) ? (tid >> 6) : (tid >> 4);
    const int cb  = (BN == 256) ? ((tid & 63) << 2) : ((tid & 15) << 2);
    const uint32_t sB0 = (uint32_t)__cvta_generic_to_shared(&Bs[0][0][0]);
    const uint32_t sB1 = (uint32_t)__cvta_generic_to_shared(&Bs[1][0][0]);

    // ---- prologue: stage 0 ----
    float4 areg = make_float4(0.f, 0.f, 0.f, 0.f);
    if (valid) areg = *reinterpret_cast<const float4*>(aptr);
    {
#pragma unroll
        for (int i = 0; i < (BN == 256 ? 4 : 1); i++) {
            int rr = rb0 + i * 4;
            cp_async16(sB0 + (uint32_t)((rr * BN + cb) * 4),
                       W + (size_t)rr * BN + cb);
        }
        cp_commit();
    }
    As[0][akc + 0][arow] = areg.x;
    As[0][akc + 1][arow] = areg.y;
    As[0][akc + 2][arow] = areg.z;
    As[0][akc + 3][arow] = areg.w;
    cp_wait0();
    __syncthreads();

    float acc[4][NG * 4];
#pragma unroll
    for (int i = 0; i < 4; i++)
#pragma unroll
        for (int j = 0; j < NG * 4; j++) acc[i][j] = 0.f;

    int cur = 0;
    for (int k0 = 0; k0 < NITER; k0++) {
        const int nxt = cur ^ 1;
        float4 anext = make_float4(0.f, 0.f, 0.f, 0.f);
        if (k0 + 1 < NITER) {
            if (valid) anext = *reinterpret_cast<const float4*>(aptr + (k0 + 1) * BK);
            const uint32_t sB = nxt ? sB1 : sB0;
#pragma unroll
            for (int i = 0; i < (BN == 256 ? 4 : 1); i++) {
                int rr = rb0 + i * 4;
                cp_async16(sB + (uint32_t)((rr * BN + cb) * 4),
                           W + (size_t)((k0 + 1) * BK + rr) * BN + cb);
            }
            cp_commit();
        }
        // ---- compute on stage [cur] ----
#pragma unroll
        for (int k = 0; k < BK; k++) {
            float4 a4 = *reinterpret_cast<const float4*>(&As[cur][k][ty * 4]);
            float av[4] = {a4.x, a4.y, a4.z, a4.w};
#pragma unroll
            for (int g = 0; g < NG; g++) {
                float4 b4 = *reinterpret_cast<const float4*>(&Bs[cur][k][g * 64 + tx * 4]);
                float bv[4] = {b4.x, b4.y, b4.z, b4.w};
#pragma unroll
                for (int i = 0; i < 4; i++)
#pragma unroll
                    for (int j = 0; j < 4; j++)
                        acc[i][g * 4 + j] = fmaf(av[i], bv[j], acc[i][g * 4 + j]);
            }
        }
        if (k0 + 1 < NITER) {
            As[nxt][akc + 0][arow] = anext.x;
            As[nxt][akc + 1][arow] = anext.y;
            As[nxt][akc + 2][arow] = anext.z;
            As[nxt][akc + 3][arow] = anext.w;
            cp_wait0();
            __syncthreads();
        }
        cur = nxt;
    }
    // ---- epilogue ----
#pragma unroll
    for (int i = 0; i < 4; i++) {
        int m = m0 + ty * 4 + i;
        if (m >= M) continue;
#pragma unroll
        for (int g = 0; g < NG; g++) {
            int c = g * 64 + tx * 4;
            float4 v;
            v.x = acc[i][g * 4 + 0] + bias[c + 0];
            v.y = acc[i][g * 4 + 1] + bias[c + 1];
            v.z = acc[i][g * 4 + 2] + bias[c + 2];
            v.w = acc[i][g * 4 + 3] + bias[c + 3];
            if (res) {
                float4 r4 = *reinterpret_cast<const float4*>(&res[(size_t)m * D + c]);
                v.x += r4.x; v.y += r4.y; v.z += r4.z; v.w += r4.w;
            }
            *reinterpret_cast<float4*>(&out[(size_t)m * ldout + c]) = v;
        }
    }
}

// ---------------- LayerNorm + ReLU per node (also seeds agg = h2 for next conv) ----------------
__global__ void ln_relu_kernel(const float* __restrict__ h,
                               const float* __restrict__ gam,
                               const float* __restrict__ bet,
                               float* __restrict__ h2,
                               float* __restrict__ agg)
{
    int n = blockIdx.x, d = threadIdx.x;
    size_t idx = (size_t)n * D + d;
    float v = h[idx];
    float a = v, b = v * v;
    __shared__ float sa[8], sb[8];
    int lane = d & 31, w = d >> 5;
#pragma unroll
    for (int o = 16; o; o >>= 1) {
        a += __shfl_down_sync(0xffffffffu, a, o);
        b += __shfl_down_sync(0xffffffffu, b, o);
    }
    if (lane == 0) { sa[w] = a; sb[w] = b; }
    __syncthreads();
    if (w == 0) {
        a = (lane < 8) ? sa[lane] : 0.f;
        b = (lane < 8) ? sb[lane] : 0.f;
#pragma unroll
        for (int o = 4; o; o >>= 1) {
            a += __shfl_down_sync(0xffffffffu, a, o);
            b += __shfl_down_sync(0xffffffffu, b, o);
        }
        if (lane == 0) { sa[0] = a; sb[0] = b; }
    }
    __syncthreads();
    float mu  = sa[0] * (1.f / D);
    float var = sb[0] * (1.f / D) - mu * mu;
    float y = (v - mu) * rsqrtf(var + LN_EPS) * gam[d] + bet[d];
    float r = fmaxf(y, 0.f);
    h2[idx]  = r;
    agg[idx] = r;                 // pre-seed with features (messages add on top)
}

// ---------------- virtual-node path: vn = MLP(segment_sum(h2) + vn), 8 graphs/block ----------------
__device__ __forceinline__ void ln_rows8(float (*t)[D], float (*s)[D],
                                         const float* __restrict__ gam,
                                         const float* __restrict__ bet,
                                         float* smu, float* srs)
{
    int lane = threadIdx.x & 31, w = threadIdx.x >> 5;   // warp w handles graph w
    float a = 0.f, b = 0.f;
#pragma unroll
    for (int i = 0; i < 8; i++) {
        float v = t[w][lane + 32 * i];
        a += v; b += v * v;
    }
#pragma unroll
    for (int o = 16; o; o >>= 1) {
        a += __shfl_down_sync(0xffffffffu, a, o);
        b += __shfl_down_sync(0xffffffffu, b, o);
    }
    if (lane == 0) {
        float mu = a * (1.f / D);
        float var = b * (1.f / D) - mu * mu;
        smu[w] = mu;
        srs[w] = rsqrtf(var + LN_EPS);
    }
    __syncthreads();
    int d = threadIdx.x;
    float gd = gam[d], bd = bet[d];
#pragma unroll
    for (int gg = 0; gg < 8; gg++) {
        float v = (t[gg][d] - smu[gg]) * srs[gg] * gd + bd;
        s[gg][d] = fmaxf(v, 0.f);
    }
}

__global__ void vn_mlp_kernel(const float* __restrict__ h2, const int* __restrict__ off,
                              const float* __restrict__ W1, const float* __restrict__ b1,
                              const float* __restrict__ g1, const float* __restrict__ be1,
                              const float* __restrict__ W2, const float* __restrict__ b2,
                              const float* __restrict__ g2, const float* __restrict__ be2,
                              float* __restrict__ vn)
{
    __shared__ float s[8][D];
    __shared__ float t[8][D];
    __shared__ float smu[8], srs[8];
    int d = threadIdx.x;
    int g0 = blockIdx.x * 8;

    // segment sum + current vn
#pragma unroll
    for (int gg = 0; gg < 8; gg++) {
        int g = g0 + gg;
        float acc = vn[(size_t)g * D + d];
        int n1 = off[g + 1];
        for (int n = off[g]; n < n1; n++)
            acc += h2[(size_t)n * D + d];
        s[gg][d] = acc;
    }
    __syncthreads();

    // linear 1
    float y[8];
#pragma unroll
    for (int gg = 0; gg < 8; gg++) y[gg] = b1[d];
    for (int k = 0; k < D; k++) {
        float w = W1[(size_t)k * D + d];
#pragma unroll
        for (int gg = 0; gg < 8; gg++) y[gg] = fmaf(s[gg][k], w, y[gg]);
    }
    __syncthreads();
#pragma unroll
    for (int gg = 0; gg < 8; gg++) t[gg][d] = y[gg];
    __syncthreads();
    ln_rows8(t, s, g1, be1, smu, srs);   // s = relu(LN(t))
    __syncthreads();

    // linear 2
#pragma unroll
    for (int gg = 0; gg < 8; gg++) y[gg] = b2[d];
    for (int k = 0; k < D; k++) {
        float w = W2[(size_t)k * D + d];
#pragma unroll
        for (int gg = 0; gg < 8; gg++) y[gg] = fmaf(s[gg][k], w, y[gg]);
    }
    __syncthreads();
#pragma unroll
    for (int gg = 0; gg < 8; gg++) t[gg][d] = y[gg];
    __syncthreads();
    ln_rows8(t, s, g2, be2, smu, srs);
    __syncthreads();
#pragma unroll
    for (int gg = 0; gg < 8; gg++)
        vn[(size_t)(g0 + gg) * D + d] = s[gg][d];
}

// ---------------- h2 += vn[batch], agg += vn[batch] ----------------
__global__ void add_vn_kernel(float* __restrict__ h2, float* __restrict__ agg,
                              const int* __restrict__ batch,
                              const float* __restrict__ vn)
{
    int n = blockIdx.x, d = threadIdx.x;
    __shared__ int bg;
    if (d == 0) bg = batch[n];
    __syncthreads();
    size_t idx = (size_t)n * D + d;
    float v = vn[(size_t)bg * D + d];
    h2[idx]  += v;
    agg[idx] += v;
}

// ---------------- launcher ----------------
extern "C" void kernel_launch(void* const* d_in, const int* in_sizes, int n_in,
                              void* d_out, int out_size)
{
    const int*   x          = (const int*)  d_in[0];
    const int*   edge_attr  = (const int*)  d_in[1];
    const int*   edge_index = (const int*)  d_in[2];
    const int*   batch      = (const int*)  d_in[3];
    const float* atom_emb   = (const float*)d_in[4];
    const float* bond_emb   = (const float*)d_in[5];
    const float* vn_emb     = (const float*)d_in[6];
    const float* gcn_w      = (const float*)d_in[7];
    const float* gcn_b      = (const float*)d_in[8];
    const float* norm_g     = (const float*)d_in[9];
    const float* norm_b     = (const float*)d_in[10];
    const float* ffn_w      = (const float*)d_in[11];
    const float* ffn_b      = (const float*)d_in[12];
    const float* vn_w1      = (const float*)d_in[13];
    const float* vn_b1      = (const float*)d_in[14];
    const float* vn_g1      = (const float*)d_in[15];
    const float* vn_be1     = (const float*)d_in[16];
    const float* vn_w2      = (const float*)d_in[17];
    const float* vn_b2      = (const float*)d_in[18];
    const float* vn_g2      = (const float*)d_in[19];
    const float* vn_be2     = (const float*)d_in[20];

    float* out       = (float*)d_out;                       // h_graph [N,256]
    float* out_hinit = out + (size_t)N_NODES * D;           // h_init  [N,256]

    float *ph, *ph2, *pagg, *pvn; int* poff;
    cudaGetSymbolAddress((void**)&ph,   g_h);
    cudaGetSymbolAddress((void**)&ph2,  g_h2);
    cudaGetSymbolAddress((void**)&pagg, g_agg);
    cudaGetSymbolAddress((void**)&pvn,  g_vn);
    cudaGetSymbolAddress((void**)&poff, g_off);

    const int GEMM_GRID = (N_NODES + 63) / 64;   // 1563
    const int EDGE_GRID = (N_EDGES + 3) / 4;     // 75000

    node_init_kernel<<<N_NODES, 256>>>(x, atom_emb, vn_emb, ph, pagg, pvn, out_hinit);
    offsets_kernel<<<(NGRAPHS + 1 + 255) / 256, 256>>>(batch, poff);

    // ----- layer 0 -----
    edge_msg_kernel<<<EDGE_GRID, 256>>>((const float4*)ph, edge_index, edge_attr,
                                        (const float4*)bond_emb, pagg);
    gemm_kernel<256><<<GEMM_GRID, 256>>>(pagg, gcn_w, gcn_b, nullptr, ph, N_NODES, D);
    gemm_kernel<64><<<GEMM_GRID, 256>>>(ph, ffn_w, ffn_b, nullptr, out, N_NODES, D);

    // ----- layers 1..3 (layers 4..6 are dead code: only out[0..3] reach h_graph) -----
    for (int l = 1; l < 4; l++) {
        int j = l - 1;
        ln_relu_kernel<<<N_NODES, 256>>>(ph, norm_g + (size_t)j * D, norm_b + (size_t)j * D, ph2, pagg);
        vn_mlp_kernel<<<NGRAPHS / 8, 256>>>(ph2, poff,
                                            vn_w1 + (size_t)j * D * D, vn_b1 + (size_t)j * D,
                                            vn_g1 + (size_t)j * D,     vn_be1 + (size_t)j * D,
                                            vn_w2 + (size_t)j * D * D, vn_b2 + (size_t)j * D,
                                            vn_g2 + (size_t)j * D,     vn_be2 + (size_t)j * D,
                                            pvn);
        add_vn_kernel<<<N_NODES, 256>>>(ph2, pagg, batch, pvn);
        edge_msg_kernel<<<EDGE_GRID, 256>>>((const float4*)ph2, edge_index, edge_attr,
                                            (const float4*)bond_emb, pagg);
        gemm_kernel<256><<<GEMM_GRID, 256>>>(pagg, gcn_w + (size_t)l * D * D,
                                             gcn_b + (size_t)l * D, ph, ph, N_NODES, D);
        gemm_kernel<64><<<GEMM_GRID, 256>>>(ph, ffn_w + (size_t)l * D * 64,
                                            ffn_b + (size_t)l * 64, nullptr,
                                            out + (size_t)l * 64, N_NODES, D);
    }
}

// round 5
// speedup vs baseline: 1.4819x; 1.3215x over previous
#include <cuda_runtime.h>
#include <stddef.h>
#include <stdint.h>

#define N_NODES 100000
#define N_EDGES 300000
#define NGRAPHS 3000
#define D 256
#define MSG_EPS 1e-7f
#define LN_EPS  1e-5f

// ---------------- scratch (static device allocations; no cudaMalloc) ----------------
__device__ __align__(16) float g_h  [(size_t)N_NODES * D];
__device__ __align__(16) float g_h2 [(size_t)N_NODES * D];
__device__ __align__(16) float g_agg[(size_t)N_NODES * D];
__device__ __align__(16) float g_vn [(size_t)NGRAPHS * D];
__device__ int g_off[NGRAPHS + 1];

// ---------------- node init: atom embedding sum, h_init out, h = h0 + vn_emb ----------------
__global__ void node_init_kernel(const int* __restrict__ x,
                                 const float* __restrict__ atom_emb,
                                 const float* __restrict__ vn_emb,
                                 float* __restrict__ h,
                                 float* __restrict__ agg,
                                 float* __restrict__ vn,
                                 float* __restrict__ out_hinit)
{
    int n = blockIdx.x;
    int d = threadIdx.x;
    __shared__ int xi[9];
    if (d < 9) xi[d] = x[n * 9 + d];
    __syncthreads();
    float s = 0.f;
#pragma unroll
    for (int f = 0; f < 9; f++)
        s += atom_emb[((size_t)f * 64 + xi[f]) * D + d];
    size_t idx = (size_t)n * D + d;
    out_hinit[idx] = s;
    float hv = s + vn_emb[d];
    h[idx]   = hv;
    agg[idx] = hv;                      // pre-seed with features
    if (n < NGRAPHS) vn[(size_t)n * D + d] = vn_emb[d];
}

// ---------------- graph segment offsets via binary search (batch is sorted) ----------------
__global__ void offsets_kernel(const int* __restrict__ batch, int* __restrict__ off)
{
    int g = blockIdx.x * blockDim.x + threadIdx.x;
    if (g > NGRAPHS) return;
    int lo = 0, hi = N_NODES;
    while (lo < hi) {
        int mid = (lo + hi) >> 1;
        if (batch[mid] < g) lo = mid + 1; else hi = mid;
    }
    off[g] = lo;
}

// ---------------- edge messages: msg = relu(h[src]+edge_emb)+eps, scatter-add to agg[dst] ----------------
__global__ void edge_msg_kernel(const float4* __restrict__ hin,
                                const int* __restrict__ ei,
                                const int* __restrict__ ea,
                                const float4* __restrict__ bond,   // [3][8][64] float4
                                float* __restrict__ agg)
{
    int e = blockIdx.x * 4 + (threadIdx.x >> 6);
    if (e >= N_EDGES) return;
    int q = threadIdx.x & 63;
    int src = __ldg(&ei[e]);
    int dst = __ldg(&ei[N_EDGES + e]);
    int a0 = __ldg(&ea[3 * e + 0]);
    int a1 = __ldg(&ea[3 * e + 1]);
    int a2 = __ldg(&ea[3 * e + 2]);
    float4 v  = hin[(size_t)src * 64 + q];
    float4 b0 = bond[(size_t)(0 * 8 + a0) * 64 + q];
    float4 b1 = bond[(size_t)(1 * 8 + a1) * 64 + q];
    float4 b2 = bond[(size_t)(2 * 8 + a2) * 64 + q];
    float mx = fmaxf(v.x + b0.x + b1.x + b2.x, 0.f) + MSG_EPS;
    float my = fmaxf(v.y + b0.y + b1.y + b2.y, 0.f) + MSG_EPS;
    float mz = fmaxf(v.z + b0.z + b1.z + b2.z, 0.f) + MSG_EPS;
    float mw = fmaxf(v.w + b0.w + b1.w + b2.w, 0.f) + MSG_EPS;
    float* base = &agg[(size_t)dst * D + q * 4];
    asm volatile("red.global.add.v4.f32 [%0], {%1, %2, %3, %4};\n"
                 :: "l"(base), "f"(mx), "f"(my), "f"(mz), "f"(mw) : "memory");
}

// ---------------- tf32 helpers ----------------
__device__ __forceinline__ float tf32r(float x) {
    uint32_t u;
    asm("cvt.rna.tf32.f32 %0, %1;" : "=r"(u) : "f"(x));
    return __uint_as_float(u);
}
__device__ __forceinline__ void mma_tf32(float* c, const uint32_t* a, const uint32_t* b) {
    asm volatile("mma.sync.aligned.m16n8k8.row.col.f32.tf32.tf32.f32 "
                 "{%0,%1,%2,%3}, {%4,%5,%6,%7}, {%8,%9}, {%0,%1,%2,%3};\n"
                 : "+f"(c[0]), "+f"(c[1]), "+f"(c[2]), "+f"(c[3])
                 : "r"(a[0]), "r"(a[1]), "r"(a[2]), "r"(a[3]),
                   "r"(b[0]), "r"(b[1]));
}

// ---------------- tf32 tensor-core GEMM: out = A @ W + bias [+ res] ----------------
// A: [M, 256] fp32 row-major. W: [256, ldw] row-major (this block uses cols n0..n0+BN).
// BM=128, BK=16, 8 warps in WR x WC grid; warp tile (BM/WR) x (BN/WC); m16n8k8 tiles.
template<int BN, int WR, int WC>
__global__ __launch_bounds__(256)
void gemm_tf32(const float* __restrict__ A,
               const float* __restrict__ W, const float* __restrict__ bias,
               const float* __restrict__ res, float* __restrict__ out,
               int M, int ldout, int ldw)
{
    constexpr int BM = 128, BK = 16, K = D;
    constexpr int NITER = K / BK;              // 16
    constexpr int TM = BM / WR;                // 64 or 32
    constexpr int TN = BN / WC;                // 32
    constexpr int MT = TM / 16;                // 4 or 2
    constexpr int NT = TN / 8;                 // 4
    constexpr int PAD = 8;
    __shared__ float As[2][BK][BM + PAD];
    __shared__ float Bs[2][BK][BN + PAD];

    const int tid  = threadIdx.x;
    const int lane = tid & 31;
    const int wid  = tid >> 5;
    const int wr   = wid / WC;
    const int wc   = wid % WC;
    const int gid  = lane >> 2;
    const int tig  = lane & 3;
    const int m0   = blockIdx.x * BM;
    const int n0   = blockIdx.y * BN;

    // A staging: thread -> (row = tid>>1, 8 consecutive k at (tid&1)*8)
    const int arow = tid >> 1;
    const int akc  = (tid & 1) * 8;
    const bool avalid = (m0 + arow) < M;
    const float* aptr = A + (size_t)(m0 + arow) * K + akc;

    // B staging
    constexpr int BVEC = (BN == 128) ? 2 : 1;          // float4 per thread
    const int bk  = tid >> 4;                          // 0..15
    const int bnc = (tid & 15) * (BVEC * 4);
    const float* bptr = W + (size_t)bk * ldw + n0 + bnc;

    float4 a_st[2];
    float4 b_st[BVEC];

    // ---- prologue: load tile 0 ----
    a_st[0] = make_float4(0.f, 0.f, 0.f, 0.f);
    a_st[1] = a_st[0];
    if (avalid) {
        a_st[0] = *reinterpret_cast<const float4*>(aptr);
        a_st[1] = *reinterpret_cast<const float4*>(aptr + 4);
    }
#pragma unroll
    for (int i = 0; i < BVEC; i++)
        b_st[i] = *reinterpret_cast<const float4*>(bptr + i * 4);

    {
        const float* av = reinterpret_cast<const float*>(a_st);
#pragma unroll
        for (int j = 0; j < 8; j++) As[0][akc + j][arow] = tf32r(av[j]);
        const float* bv = reinterpret_cast<const float*>(b_st);
#pragma unroll
        for (int j = 0; j < BVEC * 4; j++) Bs[0][bk][bnc + j] = tf32r(bv[j]);
    }
    __syncthreads();

    float acc[MT][NT][4];
#pragma unroll
    for (int i = 0; i < MT; i++)
#pragma unroll
        for (int j = 0; j < NT; j++)
#pragma unroll
            for (int q = 0; q < 4; q++) acc[i][j][q] = 0.f;

    for (int k0 = 0; k0 < NITER; k0++) {
        const int cur = k0 & 1;
        if (k0 + 1 < NITER) {
            a_st[0] = make_float4(0.f, 0.f, 0.f, 0.f);
            a_st[1] = a_st[0];
            if (avalid) {
                a_st[0] = *reinterpret_cast<const float4*>(aptr + (k0 + 1) * BK);
                a_st[1] = *reinterpret_cast<const float4*>(aptr + (k0 + 1) * BK + 4);
            }
#pragma unroll
            for (int i = 0; i < BVEC; i++)
                b_st[i] = *reinterpret_cast<const float4*>(bptr + (size_t)(k0 + 1) * BK * ldw + i * 4);
        }
        // ---- compute on stage [cur]: two k8 steps ----
#pragma unroll
        for (int ks = 0; ks < 2; ks++) {
            uint32_t af[MT][4];
            uint32_t bf[NT][2];
#pragma unroll
            for (int mt = 0; mt < MT; mt++) {
                int r = wr * TM + mt * 16 + gid;
                af[mt][0] = __float_as_uint(As[cur][ks * 8 + tig    ][r]);
                af[mt][1] = __float_as_uint(As[cur][ks * 8 + tig    ][r + 8]);
                af[mt][2] = __float_as_uint(As[cur][ks * 8 + tig + 4][r]);
                af[mt][3] = __float_as_uint(As[cur][ks * 8 + tig + 4][r + 8]);
            }
#pragma unroll
            for (int nt = 0; nt < NT; nt++) {
                int c = wc * TN + nt * 8 + gid;
                bf[nt][0] = __float_as_uint(Bs[cur][ks * 8 + tig    ][c]);
                bf[nt][1] = __float_as_uint(Bs[cur][ks * 8 + tig + 4][c]);
            }
#pragma unroll
            for (int mt = 0; mt < MT; mt++)
#pragma unroll
                for (int nt = 0; nt < NT; nt++)
                    mma_tf32(acc[mt][nt], af[mt], bf[nt]);
        }
        if (k0 + 1 < NITER) {
            const int nxt = cur ^ 1;
            const float* av = reinterpret_cast<const float*>(a_st);
#pragma unroll
            for (int j = 0; j < 8; j++) As[nxt][akc + j][arow] = tf32r(av[j]);
            const float* bv = reinterpret_cast<const float*>(b_st);
#pragma unroll
            for (int j = 0; j < BVEC * 4; j++) Bs[nxt][bk][bnc + j] = tf32r(bv[j]);
            __syncthreads();
        }
    }

    // ---- epilogue ----
#pragma unroll
    for (int mt = 0; mt < MT; mt++) {
#pragma unroll
        for (int nt = 0; nt < NT; nt++) {
            int r = m0 + wr * TM + mt * 16 + gid;
            int c = n0 + wc * TN + nt * 8 + 2 * tig;
            float2 bi = *reinterpret_cast<const float2*>(&bias[c]);
            if (r < M) {
                float2 v = make_float2(acc[mt][nt][0] + bi.x, acc[mt][nt][1] + bi.y);
                if (res) {
                    float2 rr = *reinterpret_cast<const float2*>(&res[(size_t)r * D + c]);
                    v.x += rr.x; v.y += rr.y;
                }
                *reinterpret_cast<float2*>(&out[(size_t)r * ldout + c]) = v;
            }
            int r2 = r + 8;
            if (r2 < M) {
                float2 v = make_float2(acc[mt][nt][2] + bi.x, acc[mt][nt][3] + bi.y);
                if (res) {
                    float2 rr = *reinterpret_cast<const float2*>(&res[(size_t)r2 * D + c]);
                    v.x += rr.x; v.y += rr.y;
                }
                *reinterpret_cast<float2*>(&out[(size_t)r2 * ldout + c]) = v;
            }
        }
    }
}

// ---------------- LayerNorm + ReLU per node (also seeds agg = h2 for next conv) ----------------
__global__ void ln_relu_kernel(const float* __restrict__ h,
                               const float* __restrict__ gam,
                               const float* __restrict__ bet,
                               float* __restrict__ h2,
                               float* __restrict__ agg)
{
    int n = blockIdx.x, d = threadIdx.x;
    size_t idx = (size_t)n * D + d;
    float v = h[idx];
    float a = v, b = v * v;
    __shared__ float sa[8], sb[8];
    int lane = d & 31, w = d >> 5;
#pragma unroll
    for (int o = 16; o; o >>= 1) {
        a += __shfl_down_sync(0xffffffffu, a, o);
        b += __shfl_down_sync(0xffffffffu, b, o);
    }
    if (lane == 0) { sa[w] = a; sb[w] = b; }
    __syncthreads();
    if (w == 0) {
        a = (lane < 8) ? sa[lane] : 0.f;
        b = (lane < 8) ? sb[lane] : 0.f;
#pragma unroll
        for (int o = 4; o; o >>= 1) {
            a += __shfl_down_sync(0xffffffffu, a, o);
            b += __shfl_down_sync(0xffffffffu, b, o);
        }
        if (lane == 0) { sa[0] = a; sb[0] = b; }
    }
    __syncthreads();
    float mu  = sa[0] * (1.f / D);
    float var = sb[0] * (1.f / D) - mu * mu;
    float y = (v - mu) * rsqrtf(var + LN_EPS) * gam[d] + bet[d];
    float r = fmaxf(y, 0.f);
    h2[idx]  = r;
    agg[idx] = r;                 // pre-seed with features (messages add on top)
}

// ---------------- virtual-node path: vn = MLP(segment_sum(h2) + vn), 8 graphs/block ----------------
__device__ __forceinline__ void ln_rows8(float (*t)[D], float (*s)[D],
                                         const float* __restrict__ gam,
                                         const float* __restrict__ bet,
                                         float* smu, float* srs)
{
    int lane = threadIdx.x & 31, w = threadIdx.x >> 5;   // warp w handles graph w
    float a = 0.f, b = 0.f;
#pragma unroll
    for (int i = 0; i < 8; i++) {
        float v = t[w][lane + 32 * i];
        a += v; b += v * v;
    }
#pragma unroll
    for (int o = 16; o; o >>= 1) {
        a += __shfl_down_sync(0xffffffffu, a, o);
        b += __shfl_down_sync(0xffffffffu, b, o);
    }
    if (lane == 0) {
        float mu = a * (1.f / D);
        float var = b * (1.f / D) - mu * mu;
        smu[w] = mu;
        srs[w] = rsqrtf(var + LN_EPS);
    }
    __syncthreads();
    int d = threadIdx.x;
    float gd = gam[d], bd = bet[d];
#pragma unroll
    for (int gg = 0; gg < 8; gg++) {
        float v = (t[gg][d] - smu[gg]) * srs[gg] * gd + bd;
        s[gg][d] = fmaxf(v, 0.f);
    }
}

__global__ void vn_mlp_kernel(const float* __restrict__ h2, const int* __restrict__ off,
                              const float* __restrict__ W1, const float* __restrict__ b1,
                              const float* __restrict__ g1, const float* __restrict__ be1,
                              const float* __restrict__ W2, const float* __restrict__ b2,
                              const float* __restrict__ g2, const float* __restrict__ be2,
                              float* __restrict__ vn)
{
    __shared__ float s[8][D];
    __shared__ float t[8][D];
    __shared__ float smu[8], srs[8];
    int d = threadIdx.x;
    int g0 = blockIdx.x * 8;

    // segment sum + current vn
#pragma unroll
    for (int gg = 0; gg < 8; gg++) {
        int g = g0 + gg;
        float acc = vn[(size_t)g * D + d];
        int n1 = off[g + 1];
        for (int n = off[g]; n < n1; n++)
            acc += h2[(size_t)n * D + d];
        s[gg][d] = acc;
    }
    __syncthreads();

    // linear 1
    float y[8];
#pragma unroll
    for (int gg = 0; gg < 8; gg++) y[gg] = b1[d];
    for (int k = 0; k < D; k++) {
        float w = W1[(size_t)k * D + d];
#pragma unroll
        for (int gg = 0; gg < 8; gg++) y[gg] = fmaf(s[gg][k], w, y[gg]);
    }
    __syncthreads();
#pragma unroll
    for (int gg = 0; gg < 8; gg++) t[gg][d] = y[gg];
    __syncthreads();
    ln_rows8(t, s, g1, be1, smu, srs);   // s = relu(LN(t))
    __syncthreads();

    // linear 2
#pragma unroll
    for (int gg = 0; gg < 8; gg++) y[gg] = b2[d];
    for (int k = 0; k < D; k++) {
        float w = W2[(size_t)k * D + d];
#pragma unroll
        for (int gg = 0; gg < 8; gg++) y[gg] = fmaf(s[gg][k], w, y[gg]);
    }
    __syncthreads();
#pragma unroll
    for (int gg = 0; gg < 8; gg++) t[gg][d] = y[gg];
    __syncthreads();
    ln_rows8(t, s, g2, be2, smu, srs);
    __syncthreads();
#pragma unroll
    for (int gg = 0; gg < 8; gg++)
        vn[(size_t)(g0 + gg) * D + d] = s[gg][d];
}

// ---------------- h2 += vn[batch], agg += vn[batch] ----------------
__global__ void add_vn_kernel(float* __restrict__ h2, float* __restrict__ agg,
                              const int* __restrict__ batch,
                              const float* __restrict__ vn)
{
    int n = blockIdx.x, d = threadIdx.x;
    __shared__ int bg;
    if (d == 0) bg = batch[n];
    __syncthreads();
    size_t idx = (size_t)n * D + d;
    float v = vn[(size_t)bg * D + d];
    h2[idx]  += v;
    agg[idx] += v;
}

// ---------------- launcher ----------------
extern "C" void kernel_launch(void* const* d_in, const int* in_sizes, int n_in,
                              void* d_out, int out_size)
{
    const int*   x          = (const int*)  d_in[0];
    const int*   edge_attr  = (const int*)  d_in[1];
    const int*   edge_index = (const int*)  d_in[2];
    const int*   batch      = (const int*)  d_in[3];
    const float* atom_emb   = (const float*)d_in[4];
    const float* bond_emb   = (const float*)d_in[5];
    const float* vn_emb     = (const float*)d_in[6];
    const float* gcn_w      = (const float*)d_in[7];
    const float* gcn_b      = (const float*)d_in[8];
    const float* norm_g     = (const float*)d_in[9];
    const float* norm_b     = (const float*)d_in[10];
    const float* ffn_w      = (const float*)d_in[11];
    const float* ffn_b      = (const float*)d_in[12];
    const float* vn_w1      = (const float*)d_in[13];
    const float* vn_b1      = (const float*)d_in[14];
    const float* vn_g1      = (const float*)d_in[15];
    const float* vn_be1     = (const float*)d_in[16];
    const float* vn_w2      = (const float*)d_in[17];
    const float* vn_b2      = (const float*)d_in[18];
    const float* vn_g2      = (const float*)d_in[19];
    const float* vn_be2     = (const float*)d_in[20];

    float* out       = (float*)d_out;                       // h_graph [N,256]
    float* out_hinit = out + (size_t)N_NODES * D;           // h_init  [N,256]

    float *ph, *ph2, *pagg, *pvn; int* poff;
    cudaGetSymbolAddress((void**)&ph,   g_h);
    cudaGetSymbolAddress((void**)&ph2,  g_h2);
    cudaGetSymbolAddress((void**)&pagg, g_agg);
    cudaGetSymbolAddress((void**)&pvn,  g_vn);
    cudaGetSymbolAddress((void**)&poff, g_off);

    const dim3 G256((N_NODES + 127) / 128, 2);   // 782 x 2
    const dim3 G64 ((N_NODES + 127) / 128, 1);   // 782 x 1
    const int EDGE_GRID = (N_EDGES + 3) / 4;     // 75000

    node_init_kernel<<<N_NODES, 256>>>(x, atom_emb, vn_emb, ph, pagg, pvn, out_hinit);
    offsets_kernel<<<(NGRAPHS + 1 + 255) / 256, 256>>>(batch, poff);

    // ----- layer 0 -----
    edge_msg_kernel<<<EDGE_GRID, 256>>>((const float4*)ph, edge_index, edge_attr,
                                        (const float4*)bond_emb, pagg);
    gemm_tf32<128, 2, 4><<<G256, 256>>>(pagg, gcn_w, gcn_b, nullptr, ph, N_NODES, D, D);
    gemm_tf32<64, 4, 2><<<G64, 256>>>(ph, ffn_w, ffn_b, nullptr, out, N_NODES, D, 64);

    // ----- layers 1..3 (layers 4..6 are dead code: only out[0..3] reach h_graph) -----
    for (int l = 1; l < 4; l++) {
        int j = l - 1;
        ln_relu_kernel<<<N_NODES, 256>>>(ph, norm_g + (size_t)j * D, norm_b + (size_t)j * D, ph2, pagg);
        vn_mlp_kernel<<<NGRAPHS / 8, 256>>>(ph2, poff,
                                            vn_w1 + (size_t)j * D * D, vn_b1 + (size_t)j * D,
                                            vn_g1 + (size_t)j * D,     vn_be1 + (size_t)j * D,
                                            vn_w2 + (size_t)j * D * D, vn_b2 + (size_t)j * D,
                                            vn_g2 + (size_t)j * D,     vn_be2 + (size_t)j * D,
                                            pvn);
        add_vn_kernel<<<N_NODES, 256>>>(ph2, pagg, batch, pvn);
        edge_msg_kernel<<<EDGE_GRID, 256>>>((const float4*)ph2, edge_index, edge_attr,
                                            (const float4*)bond_emb, pagg);
        gemm_tf32<128, 2, 4><<<G256, 256>>>(pagg, gcn_w + (size_t)l * D * D,
                                            gcn_b + (size_t)l * D, ph, ph, N_NODES, D, D);
        gemm_tf32<64, 4, 2><<<G64, 256>>>(ph, ffn_w + (size_t)l * D * 64,
                                          ffn_b + (size_t)l * 64, nullptr,
                                          out + (size_t)l * 64, N_NODES, D, 64);
    }
}

// round 6
// speedup vs baseline: 1.5668x; 1.0573x over previous
#include <cuda_runtime.h>
#include <stddef.h>
#include <stdint.h>

#define N_NODES 100000
#define N_EDGES 300000
#define NGRAPHS 3000
#define D 256
#define MSG_EPS 1e-7f
#define LN_EPS  1e-5f
#define SCAN_B 1024
#define NBLK ((N_NODES + SCAN_B - 1) / SCAN_B)   // 98

// ---------------- scratch (static device allocations; no cudaMalloc) ----------------
__device__ __align__(16) float g_h  [(size_t)N_NODES * D];
__device__ __align__(16) float g_h2 [(size_t)N_NODES * D];
__device__ __align__(16) float g_agg[(size_t)N_NODES * D];
__device__ __align__(16) float g_vn [(size_t)NGRAPHS * D];
__device__ __align__(16) float g_combo[512 * D];          // bond combo table
__device__ int g_off[NGRAPHS + 1];
__device__ int g_deg[N_NODES];
__device__ int g_noff[N_NODES + 1];
__device__ int g_cursor[N_NODES];
__device__ int g_elist[N_EDGES];
__device__ int g_bsum[NBLK];

// ================= CSR build (edge_index constant across layers) =================
__global__ void zero_deg_kernel() {
    int i = blockIdx.x * blockDim.x + threadIdx.x;
    if (i < N_NODES) g_deg[i] = 0;
}
__global__ void hist_kernel(const int* __restrict__ ei) {
    int e = blockIdx.x * blockDim.x + threadIdx.x;
    if (e < N_EDGES) atomicAdd(&g_deg[ei[N_EDGES + e]], 1);
}
__global__ void scan_block_kernel() {
    __shared__ int s[SCAN_B];
    int tid = threadIdx.x;
    int i = blockIdx.x * SCAN_B + tid;
    int v = (i < N_NODES) ? g_deg[i] : 0;
    s[tid] = v;
    __syncthreads();
#pragma unroll
    for (int d = 1; d < SCAN_B; d <<= 1) {
        int t = (tid >= d) ? s[tid - d] : 0;
        __syncthreads();
        s[tid] += t;
        __syncthreads();
    }
    if (i < N_NODES) g_noff[i + 1] = s[tid];
    if (tid == SCAN_B - 1) g_bsum[blockIdx.x] = s[tid];
}
__global__ void scan_sums_kernel() {
    if (threadIdx.x == 0) {
        int acc = 0;
        for (int b = 0; b < NBLK; b++) { int t = g_bsum[b]; g_bsum[b] = acc; acc += t; }
        g_noff[0] = 0;
    }
}
__global__ void add_off_kernel() {
    int i = blockIdx.x * blockDim.x + threadIdx.x;
    if (i < N_NODES) g_noff[i + 1] += g_bsum[i / SCAN_B];
}
__global__ void copy_cursor_kernel() {
    int i = blockIdx.x * blockDim.x + threadIdx.x;
    if (i < N_NODES) g_cursor[i] = g_noff[i];
}
__global__ void fill_kernel(const int* __restrict__ ei, const int* __restrict__ ea) {
    int e = blockIdx.x * blockDim.x + threadIdx.x;
    if (e >= N_EDGES) return;
    int src = ei[e];
    int dst = ei[N_EDGES + e];
    int combo = ea[3 * e + 0] | (ea[3 * e + 1] << 3) | (ea[3 * e + 2] << 6);
    int pos = atomicAdd(&g_cursor[dst], 1);
    g_elist[pos] = src | (combo << 17);
}
__global__ void combo_kernel(const float* __restrict__ bond) {
    int c = blockIdx.x;        // 0..511
    int d = threadIdx.x;
    int a0 = c & 7, a1 = (c >> 3) & 7, a2 = (c >> 6) & 7;
    g_combo[c * D + d] = bond[(size_t)(0 * 8 + a0) * D + d]
                       + bond[(size_t)(1 * 8 + a1) * D + d]
                       + bond[(size_t)(2 * 8 + a2) * D + d];
}

// ---------------- node init: atom embedding sum, h_init out, h = h0 + vn_emb ----------------
__global__ void node_init_kernel(const int* __restrict__ x,
                                 const float* __restrict__ atom_emb,
                                 const float* __restrict__ vn_emb,
                                 float* __restrict__ h,
                                 float* __restrict__ vn,
                                 float* __restrict__ out_hinit)
{
    int n = blockIdx.x;
    int d = threadIdx.x;
    __shared__ int xi[9];
    if (d < 9) xi[d] = x[n * 9 + d];
    __syncthreads();
    float s = 0.f;
#pragma unroll
    for (int f = 0; f < 9; f++)
        s += atom_emb[((size_t)f * 64 + xi[f]) * D + d];
    size_t idx = (size_t)n * D + d;
    out_hinit[idx] = s;
    h[idx] = s + vn_emb[d];
    if (n < NGRAPHS) vn[(size_t)n * D + d] = vn_emb[d];
}

// ---------------- graph segment offsets via binary search (batch is sorted) ----------------
__global__ void offsets_kernel(const int* __restrict__ batch, int* __restrict__ off)
{
    int g = blockIdx.x * blockDim.x + threadIdx.x;
    if (g > NGRAPHS) return;
    int lo = 0, hi = N_NODES;
    while (lo < hi) {
        int mid = (lo + hi) >> 1;
        if (batch[mid] < g) lo = mid + 1; else hi = mid;
    }
    off[g] = lo;
}

// ---------------- CSR gather aggregation: agg[n] = h[n] + sum_in relu(h[src]+combo)+eps ----------
__global__ void aggregate_kernel(const float4* __restrict__ hin,
                                 float4* __restrict__ agg)
{
    int n = blockIdx.x * 4 + (threadIdx.x >> 6);
    if (n >= N_NODES) return;
    int q = threadIdx.x & 63;
    const float4* combo4 = reinterpret_cast<const float4*>(g_combo);
    int i0 = g_noff[n], i1 = g_noff[n + 1];
    float4 self = hin[(size_t)n * 64 + q];
    float ax = self.x, ay = self.y, az = self.z, aw = self.w;
    for (int i = i0; i < i1; i++) {
        int ed = __ldg(&g_elist[i]);
        int src = ed & 0x1FFFF;
        int combo = ed >> 17;
        float4 v = hin[(size_t)src * 64 + q];
        float4 b = combo4[(size_t)combo * 64 + q];
        ax += fmaxf(v.x + b.x, 0.f) + MSG_EPS;
        ay += fmaxf(v.y + b.y, 0.f) + MSG_EPS;
        az += fmaxf(v.z + b.z, 0.f) + MSG_EPS;
        aw += fmaxf(v.w + b.w, 0.f) + MSG_EPS;
    }
    agg[(size_t)n * 64 + q] = make_float4(ax, ay, az, aw);
}

// ---------------- tf32 helpers ----------------
__device__ __forceinline__ float tf32r(float x) {
    uint32_t u;
    asm("cvt.rna.tf32.f32 %0, %1;" : "=r"(u) : "f"(x));
    return __uint_as_float(u);
}
__device__ __forceinline__ void mma_tf32(float* c, const uint32_t* a, const uint32_t* b) {
    asm volatile("mma.sync.aligned.m16n8k8.row.col.f32.tf32.tf32.f32 "
                 "{%0,%1,%2,%3}, {%4,%5,%6,%7}, {%8,%9}, {%0,%1,%2,%3};\n"
                 : "+f"(c[0]), "+f"(c[1]), "+f"(c[2]), "+f"(c[3])
                 : "r"(a[0]), "r"(a[1]), "r"(a[2]), "r"(a[3]),
                   "r"(b[0]), "r"(b[1]));
}

// ---------------- tf32 tensor-core GEMM: out = A @ W + bias [+ res] ----------------
template<int BN, int WR, int WC>
__global__ __launch_bounds__(256)
void gemm_tf32(const float* __restrict__ A,
               const float* __restrict__ W, const float* __restrict__ bias,
               const float* __restrict__ res, float* __restrict__ out,
               int M, int ldout, int ldw)
{
    constexpr int BM = 128, BK = 16, K = D;
    constexpr int NITER = K / BK;              // 16
    constexpr int TM = BM / WR;
    constexpr int TN = BN / WC;
    constexpr int MT = TM / 16;
    constexpr int NT = TN / 8;
    constexpr int PAD = 8;
    __shared__ float As[2][BK][BM + PAD];
    __shared__ float Bs[2][BK][BN + PAD];

    const int tid  = threadIdx.x;
    const int lane = tid & 31;
    const int wid  = tid >> 5;
    const int wr   = wid / WC;
    const int wc   = wid % WC;
    const int gid  = lane >> 2;
    const int tig  = lane & 3;
    const int m0   = blockIdx.x * BM;
    const int n0   = blockIdx.y * BN;

    // A staging: row = tid&127 (conflict-free transpose STS), 8 k at (tid>>7)*8
    const int arow = tid & 127;
    const int akc  = (tid >> 7) << 3;
    const bool avalid = (m0 + arow) < M;
    const float* aptr = A + (size_t)(m0 + arow) * K + akc;

    // B staging
    constexpr int BVEC = (BN == 128) ? 2 : 1;
    const int bk  = tid >> 4;
    const int bnc = (tid & 15) * (BVEC * 4);
    const float* bptr = W + (size_t)bk * ldw + n0 + bnc;

    float4 a_st[2];
    float4 b_st[BVEC];

    a_st[0] = make_float4(0.f, 0.f, 0.f, 0.f);
    a_st[1] = a_st[0];
    if (avalid) {
        a_st[0] = *reinterpret_cast<const float4*>(aptr);
        a_st[1] = *reinterpret_cast<const float4*>(aptr + 4);
    }
#pragma unroll
    for (int i = 0; i < BVEC; i++)
        b_st[i] = *reinterpret_cast<const float4*>(bptr + i * 4);

    {
        const float* av = reinterpret_cast<const float*>(a_st);
#pragma unroll
        for (int j = 0; j < 8; j++) As[0][akc + j][arow] = tf32r(av[j]);
        const float* bv = reinterpret_cast<const float*>(b_st);
#pragma unroll
        for (int j = 0; j < BVEC * 4; j++) Bs[0][bk][bnc + j] = tf32r(bv[j]);
    }
    __syncthreads();

    float acc[MT][NT][4];
#pragma unroll
    for (int i = 0; i < MT; i++)
#pragma unroll
        for (int j = 0; j < NT; j++)
#pragma unroll
            for (int q = 0; q < 4; q++) acc[i][j][q] = 0.f;

    for (int k0 = 0; k0 < NITER; k0++) {
        const int cur = k0 & 1;
        if (k0 + 1 < NITER) {
            a_st[0] = make_float4(0.f, 0.f, 0.f, 0.f);
            a_st[1] = a_st[0];
            if (avalid) {
                a_st[0] = *reinterpret_cast<const float4*>(aptr + (k0 + 1) * BK);
                a_st[1] = *reinterpret_cast<const float4*>(aptr + (k0 + 1) * BK + 4);
            }
#pragma unroll
            for (int i = 0; i < BVEC; i++)
                b_st[i] = *reinterpret_cast<const float4*>(bptr + (size_t)(k0 + 1) * BK * ldw + i * 4);
        }
#pragma unroll
        for (int ks = 0; ks < 2; ks++) {
            uint32_t af[MT][4];
            uint32_t bf[NT][2];
#pragma unroll
            for (int mt = 0; mt < MT; mt++) {
                int r = wr * TM + mt * 16 + gid;
                af[mt][0] = __float_as_uint(As[cur][ks * 8 + tig    ][r]);
                af[mt][1] = __float_as_uint(As[cur][ks * 8 + tig    ][r + 8]);
                af[mt][2] = __float_as_uint(As[cur][ks * 8 + tig + 4][r]);
                af[mt][3] = __float_as_uint(As[cur][ks * 8 + tig + 4][r + 8]);
            }
#pragma unroll
            for (int nt = 0; nt < NT; nt++) {
                int c = wc * TN + nt * 8 + gid;
                bf[nt][0] = __float_as_uint(Bs[cur][ks * 8 + tig    ][c]);
                bf[nt][1] = __float_as_uint(Bs[cur][ks * 8 + tig + 4][c]);
            }
#pragma unroll
            for (int mt = 0; mt < MT; mt++)
#pragma unroll
                for (int nt = 0; nt < NT; nt++)
                    mma_tf32(acc[mt][nt], af[mt], bf[nt]);
        }
        if (k0 + 1 < NITER) {
            const int nxt = cur ^ 1;
            const float* av = reinterpret_cast<const float*>(a_st);
#pragma unroll
            for (int j = 0; j < 8; j++) As[nxt][akc + j][arow] = tf32r(av[j]);
            const float* bv = reinterpret_cast<const float*>(b_st);
#pragma unroll
            for (int j = 0; j < BVEC * 4; j++) Bs[nxt][bk][bnc + j] = tf32r(bv[j]);
            __syncthreads();
        }
    }

#pragma unroll
    for (int mt = 0; mt < MT; mt++) {
#pragma unroll
        for (int nt = 0; nt < NT; nt++) {
            int r = m0 + wr * TM + mt * 16 + gid;
            int c = n0 + wc * TN + nt * 8 + 2 * tig;
            float2 bi = *reinterpret_cast<const float2*>(&bias[c]);
            if (r < M) {
                float2 v = make_float2(acc[mt][nt][0] + bi.x, acc[mt][nt][1] + bi.y);
                if (res) {
                    float2 rr = *reinterpret_cast<const float2*>(&res[(size_t)r * D + c]);
                    v.x += rr.x; v.y += rr.y;
                }
                *reinterpret_cast<float2*>(&out[(size_t)r * ldout + c]) = v;
            }
            int r2 = r + 8;
            if (r2 < M) {
                float2 v = make_float2(acc[mt][nt][2] + bi.x, acc[mt][nt][3] + bi.y);
                if (res) {
                    float2 rr = *reinterpret_cast<const float2*>(&res[(size_t)r2 * D + c]);
                    v.x += rr.x; v.y += rr.y;
                }
                *reinterpret_cast<float2*>(&out[(size_t)r2 * ldout + c]) = v;
            }
        }
    }
}

// ---------------- LayerNorm + ReLU per node ----------------
__global__ void ln_relu_kernel(const float* __restrict__ h,
                               const float* __restrict__ gam,
                               const float* __restrict__ bet,
                               float* __restrict__ h2)
{
    int n = blockIdx.x, d = threadIdx.x;
    size_t idx = (size_t)n * D + d;
    float v = h[idx];
    float a = v, b = v * v;
    __shared__ float sa[8], sb[8];
    int lane = d & 31, w = d >> 5;
#pragma unroll
    for (int o = 16; o; o >>= 1) {
        a += __shfl_down_sync(0xffffffffu, a, o);
        b += __shfl_down_sync(0xffffffffu, b, o);
    }
    if (lane == 0) { sa[w] = a; sb[w] = b; }
    __syncthreads();
    if (w == 0) {
        a = (lane < 8) ? sa[lane] : 0.f;
        b = (lane < 8) ? sb[lane] : 0.f;
#pragma unroll
        for (int o = 4; o; o >>= 1) {
            a += __shfl_down_sync(0xffffffffu, a, o);
            b += __shfl_down_sync(0xffffffffu, b, o);
        }
        if (lane == 0) { sa[0] = a; sb[0] = b; }
    }
    __syncthreads();
    float mu  = sa[0] * (1.f / D);
    float var = sb[0] * (1.f / D) - mu * mu;
    float y = (v - mu) * rsqrtf(var + LN_EPS) * gam[d] + bet[d];
    h2[idx] = fmaxf(y, 0.f);
}

// ---------------- virtual-node path ----------------
__device__ __forceinline__ void ln_rows8(float (*t)[D], float (*s)[D],
                                         const float* __restrict__ gam,
                                         const float* __restrict__ bet,
                                         float* smu, float* srs)
{
    int lane = threadIdx.x & 31, w = threadIdx.x >> 5;
    float a = 0.f, b = 0.f;
#pragma unroll
    for (int i = 0; i < 8; i++) {
        float v = t[w][lane + 32 * i];
        a += v; b += v * v;
    }
#pragma unroll
    for (int o = 16; o; o >>= 1) {
        a += __shfl_down_sync(0xffffffffu, a, o);
        b += __shfl_down_sync(0xffffffffu, b, o);
    }
    if (lane == 0) {
        float mu = a * (1.f / D);
        float var = b * (1.f / D) - mu * mu;
        smu[w] = mu;
        srs[w] = rsqrtf(var + LN_EPS);
    }
    __syncthreads();
    int d = threadIdx.x;
    float gd = gam[d], bd = bet[d];
#pragma unroll
    for (int gg = 0; gg < 8; gg++) {
        float v = (t[gg][d] - smu[gg]) * srs[gg] * gd + bd;
        s[gg][d] = fmaxf(v, 0.f);
    }
}

__global__ void vn_mlp_kernel(const float* __restrict__ h2, const int* __restrict__ off,
                              const float* __restrict__ W1, const float* __restrict__ b1,
                              const float* __restrict__ g1, const float* __restrict__ be1,
                              const float* __restrict__ W2, const float* __restrict__ b2,
                              const float* __restrict__ g2, const float* __restrict__ be2,
                              float* __restrict__ vn)
{
    __shared__ float s[8][D];
    __shared__ float t[8][D];
    __shared__ float smu[8], srs[8];
    int d = threadIdx.x;
    int g0 = blockIdx.x * 8;

#pragma unroll
    for (int gg = 0; gg < 8; gg++) {
        int g = g0 + gg;
        float acc = vn[(size_t)g * D + d];
        int n1 = off[g + 1];
        for (int n = off[g]; n < n1; n++)
            acc += h2[(size_t)n * D + d];
        s[gg][d] = acc;
    }
    __syncthreads();

    float y[8];
#pragma unroll
    for (int gg = 0; gg < 8; gg++) y[gg] = b1[d];
    for (int k = 0; k < D; k++) {
        float w = W1[(size_t)k * D + d];
#pragma unroll
        for (int gg = 0; gg < 8; gg++) y[gg] = fmaf(s[gg][k], w, y[gg]);
    }
    __syncthreads();
#pragma unroll
    for (int gg = 0; gg < 8; gg++) t[gg][d] = y[gg];
    __syncthreads();
    ln_rows8(t, s, g1, be1, smu, srs);
    __syncthreads();

#pragma unroll
    for (int gg = 0; gg < 8; gg++) y[gg] = b2[d];
    for (int k = 0; k < D; k++) {
        float w = W2[(size_t)k * D + d];
#pragma unroll
        for (int gg = 0; gg < 8; gg++) y[gg] = fmaf(s[gg][k], w, y[gg]);
    }
    __syncthreads();
#pragma unroll
    for (int gg = 0; gg < 8; gg++) t[gg][d] = y[gg];
    __syncthreads();
    ln_rows8(t, s, g2, be2, smu, srs);
    __syncthreads();
#pragma unroll
    for (int gg = 0; gg < 8; gg++)
        vn[(size_t)(g0 + gg) * D + d] = s[gg][d];
}

// ---------------- h2 += vn[batch] ----------------
__global__ void add_vn_kernel(float* __restrict__ h2,
                              const int* __restrict__ batch,
                              const float* __restrict__ vn)
{
    int n = blockIdx.x, d = threadIdx.x;
    __shared__ int bg;
    if (d == 0) bg = batch[n];
    __syncthreads();
    h2[(size_t)n * D + d] += vn[(size_t)bg * D + d];
}

// ---------------- launcher ----------------
extern "C" void kernel_launch(void* const* d_in, const int* in_sizes, int n_in,
                              void* d_out, int out_size)
{
    const int*   x          = (const int*)  d_in[0];
    const int*   edge_attr  = (const int*)  d_in[1];
    const int*   edge_index = (const int*)  d_in[2];
    const int*   batch      = (const int*)  d_in[3];
    const float* atom_emb   = (const float*)d_in[4];
    const float* bond_emb   = (const float*)d_in[5];
    const float* vn_emb     = (const float*)d_in[6];
    const float* gcn_w      = (const float*)d_in[7];
    const float* gcn_b      = (const float*)d_in[8];
    const float* norm_g     = (const float*)d_in[9];
    const float* norm_b     = (const float*)d_in[10];
    const float* ffn_w      = (const float*)d_in[11];
    const float* ffn_b      = (const float*)d_in[12];
    const float* vn_w1      = (const float*)d_in[13];
    const float* vn_b1      = (const float*)d_in[14];
    const float* vn_g1      = (const float*)d_in[15];
    const float* vn_be1     = (const float*)d_in[16];
    const float* vn_w2      = (const float*)d_in[17];
    const float* vn_b2      = (const float*)d_in[18];
    const float* vn_g2      = (const float*)d_in[19];
    const float* vn_be2     = (const float*)d_in[20];

    float* out       = (float*)d_out;                       // h_graph [N,256]
    float* out_hinit = out + (size_t)N_NODES * D;           // h_init  [N,256]

    float *ph, *ph2, *pagg, *pvn; int* poff;
    cudaGetSymbolAddress((void**)&ph,   g_h);
    cudaGetSymbolAddress((void**)&ph2,  g_h2);
    cudaGetSymbolAddress((void**)&pagg, g_agg);
    cudaGetSymbolAddress((void**)&pvn,  g_vn);
    cudaGetSymbolAddress((void**)&poff, g_off);

    const dim3 G256((N_NODES + 127) / 128, 2);
    const dim3 G64 ((N_NODES + 127) / 128, 1);
    const int AGG_GRID = (N_NODES + 3) / 4;

    // ---- CSR build (edge structure reused for all 4 layers) ----
    zero_deg_kernel<<<(N_NODES + 255) / 256, 256>>>();
    hist_kernel<<<(N_EDGES + 255) / 256, 256>>>(edge_index);
    scan_block_kernel<<<NBLK, SCAN_B>>>();
    scan_sums_kernel<<<1, 32>>>();
    add_off_kernel<<<(N_NODES + 255) / 256, 256>>>();
    copy_cursor_kernel<<<(N_NODES + 255) / 256, 256>>>();
    fill_kernel<<<(N_EDGES + 255) / 256, 256>>>(edge_index, edge_attr);
    combo_kernel<<<512, 256>>>(bond_emb);

    node_init_kernel<<<N_NODES, 256>>>(x, atom_emb, vn_emb, ph, pvn, out_hinit);
    offsets_kernel<<<(NGRAPHS + 1 + 255) / 256, 256>>>(batch, poff);

    // ----- layer 0 -----
    aggregate_kernel<<<AGG_GRID, 256>>>((const float4*)ph, (float4*)pagg);
    gemm_tf32<128, 2, 4><<<G256, 256>>>(pagg, gcn_w, gcn_b, nullptr, ph, N_NODES, D, D);
    gemm_tf32<64, 4, 2><<<G64, 256>>>(ph, ffn_w, ffn_b, nullptr, out, N_NODES, D, 64);

    // ----- layers 1..3 (layers 4..6 are dead code: only out[0..3] reach h_graph) -----
    for (int l = 1; l < 4; l++) {
        int j = l - 1;
        ln_relu_kernel<<<N_NODES, 256>>>(ph, norm_g + (size_t)j * D, norm_b + (size_t)j * D, ph2);
        vn_mlp_kernel<<<NGRAPHS / 8, 256>>>(ph2, poff,
                                            vn_w1 + (size_t)j * D * D, vn_b1 + (size_t)j * D,
                                            vn_g1 + (size_t)j * D,     vn_be1 + (size_t)j * D,
                                            vn_w2 + (size_t)j * D * D, vn_b2 + (size_t)j * D,
                                            vn_g2 + (size_t)j * D,     vn_be2 + (size_t)j * D,
                                            pvn);
        add_vn_kernel<<<N_NODES, 256>>>(ph2, batch, pvn);
        aggregate_kernel<<<AGG_GRID, 256>>>((const float4*)ph2, (float4*)pagg);
        gemm_tf32<128, 2, 4><<<G256, 256>>>(pagg, gcn_w + (size_t)l * D * D,
                                            gcn_b + (size_t)l * D, ph, ph, N_NODES, D, D);
        gemm_tf32<64, 4, 2><<<G64, 256>>>(ph, ffn_w + (size_t)l * D * 64,
                                          ffn_b + (size_t)l * 64, nullptr,
                                          out + (size_t)l * 64, N_NODES, D, 64);
    }
}

// round 7
// speedup vs baseline: 1.8050x; 1.1520x over previous
#include <cuda_runtime.h>
#include <stddef.h>
#include <stdint.h>

#define N_NODES 100000
#define N_EDGES 300000
#define NGRAPHS 3000
#define D 256
#define MSG_EPS 1e-7f
#define LN_EPS  1e-5f
#define SCAN_B 1024
#define NBLK ((N_NODES + SCAN_B - 1) / SCAN_B)   // 98

// ---------------- scratch (static device allocations; no cudaMalloc) ----------------
__device__ __align__(16) float g_h  [(size_t)N_NODES * D];
__device__ __align__(16) float g_h2 [(size_t)N_NODES * D];
__device__ __align__(16) float g_agg[(size_t)N_NODES * D];
__device__ __align__(16) float g_vn [(size_t)NGRAPHS * D];
__device__ __align__(16) float g_combo[512 * D];          // bond combo table
__device__ int g_off[NGRAPHS + 1];
__device__ int g_deg[N_NODES];
__device__ int g_noff[N_NODES + 1];
__device__ int g_cursor[N_NODES];
__device__ int g_elist[N_EDGES];
__device__ int g_bsum[NBLK];

// ================= CSR build (edge_index constant across layers) =================
__global__ void zero_deg_kernel() {
    int i = blockIdx.x * blockDim.x + threadIdx.x;
    if (i < N_NODES) g_deg[i] = 0;
}
__global__ void hist_kernel(const int* __restrict__ ei) {
    int e = blockIdx.x * blockDim.x + threadIdx.x;
    if (e < N_EDGES) atomicAdd(&g_deg[ei[N_EDGES + e]], 1);
}
__global__ void scan_block_kernel() {
    __shared__ int s[SCAN_B];
    int tid = threadIdx.x;
    int i = blockIdx.x * SCAN_B + tid;
    int v = (i < N_NODES) ? g_deg[i] : 0;
    s[tid] = v;
    __syncthreads();
#pragma unroll
    for (int d = 1; d < SCAN_B; d <<= 1) {
        int t = (tid >= d) ? s[tid - d] : 0;
        __syncthreads();
        s[tid] += t;
        __syncthreads();
    }
    if (i < N_NODES) g_noff[i + 1] = s[tid];
    if (tid == SCAN_B - 1) g_bsum[blockIdx.x] = s[tid];
}
__global__ void scan_sums_kernel() {
    // parallel scan of NBLK (98) block sums with one 128-thread block
    __shared__ int s[128];
    int tid = threadIdx.x;
    int v = (tid < NBLK) ? g_bsum[tid] : 0;
    s[tid] = v;
    __syncthreads();
#pragma unroll
    for (int d = 1; d < 128; d <<= 1) {
        int t = (tid >= d) ? s[tid - d] : 0;
        __syncthreads();
        s[tid] += t;
        __syncthreads();
    }
    if (tid < NBLK) g_bsum[tid] = s[tid] - v;   // exclusive
    if (tid == 0) g_noff[0] = 0;
}
__global__ void add_off_kernel() {
    int i = blockIdx.x * blockDim.x + threadIdx.x;
    if (i < N_NODES) g_noff[i + 1] += g_bsum[i / SCAN_B];
}
__global__ void copy_cursor_kernel() {
    int i = blockIdx.x * blockDim.x + threadIdx.x;
    if (i < N_NODES) g_cursor[i] = g_noff[i];
}
__global__ void fill_kernel(const int* __restrict__ ei, const int* __restrict__ ea) {
    int e = blockIdx.x * blockDim.x + threadIdx.x;
    if (e >= N_EDGES) return;
    int src = ei[e];
    int dst = ei[N_EDGES + e];
    int combo = ea[3 * e + 0] | (ea[3 * e + 1] << 3) | (ea[3 * e + 2] << 6);
    int pos = atomicAdd(&g_cursor[dst], 1);
    g_elist[pos] = src | (combo << 17);
}
__global__ void combo_kernel(const float* __restrict__ bond) {
    int c = blockIdx.x;        // 0..511
    int d = threadIdx.x;
    int a0 = c & 7, a1 = (c >> 3) & 7, a2 = (c >> 6) & 7;
    g_combo[c * D + d] = bond[(size_t)(0 * 8 + a0) * D + d]
                       + bond[(size_t)(1 * 8 + a1) * D + d]
                       + bond[(size_t)(2 * 8 + a2) * D + d];
}

// ---------------- node init: atom embedding sum, h_init out, h = h0 + vn_emb ----------------
__global__ void node_init_kernel(const int* __restrict__ x,
                                 const float* __restrict__ atom_emb,
                                 const float* __restrict__ vn_emb,
                                 float* __restrict__ h,
                                 float* __restrict__ vn,
                                 float* __restrict__ out_hinit)
{
    int n = blockIdx.x;
    int d = threadIdx.x;
    __shared__ int xi[9];
    if (d < 9) xi[d] = x[n * 9 + d];
    __syncthreads();
    float s = 0.f;
#pragma unroll
    for (int f = 0; f < 9; f++)
        s += atom_emb[((size_t)f * 64 + xi[f]) * D + d];
    size_t idx = (size_t)n * D + d;
    out_hinit[idx] = s;
    h[idx] = s + vn_emb[d];
    if (n < NGRAPHS) vn[(size_t)n * D + d] = vn_emb[d];
}

// ---------------- graph segment offsets via binary search (batch is sorted) ----------------
__global__ void offsets_kernel(const int* __restrict__ batch, int* __restrict__ off)
{
    int g = blockIdx.x * blockDim.x + threadIdx.x;
    if (g > NGRAPHS) return;
    int lo = 0, hi = N_NODES;
    while (lo < hi) {
        int mid = (lo + hi) >> 1;
        if (batch[mid] < g) lo = mid + 1; else hi = mid;
    }
    off[g] = lo;
}

// ---------------- CSR gather aggregation ----------------
// WITHVN=false: agg[n] = h[n] + sum_in relu(h[src]+combo)+eps            (vn already inside h)
// WITHVN=true : agg[n] = h2[n]+vn[b[n]] + sum_in relu(h2[src]+vn[b[src]]+combo)+eps
template<bool WITHVN>
__global__ void aggregate_kernel(const float4* __restrict__ hin,
                                 const float4* __restrict__ vn,
                                 const int* __restrict__ batch,
                                 float4* __restrict__ agg)
{
    int n = blockIdx.x * 4 + (threadIdx.x >> 6);
    if (n >= N_NODES) return;
    int q = threadIdx.x & 63;
    const float4* combo4 = reinterpret_cast<const float4*>(g_combo);
    int i0 = g_noff[n], i1 = g_noff[n + 1];
    float4 self = hin[(size_t)n * 64 + q];
    float ax = self.x, ay = self.y, az = self.z, aw = self.w;
    if (WITHVN) {
        int bg = __ldg(&batch[n]);
        float4 vv = vn[(size_t)bg * 64 + q];
        ax += vv.x; ay += vv.y; az += vv.z; aw += vv.w;
    }
    int i = i0;
    for (; i + 1 < i1; i += 2) {
        int ed0 = __ldg(&g_elist[i]);
        int ed1 = __ldg(&g_elist[i + 1]);
        int s0 = ed0 & 0x1FFFF, c0 = ed0 >> 17;
        int s1 = ed1 & 0x1FFFF, c1 = ed1 >> 17;
        float4 v0 = hin[(size_t)s0 * 64 + q];
        float4 v1 = hin[(size_t)s1 * 64 + q];
        float4 b0 = combo4[(size_t)c0 * 64 + q];
        float4 b1 = combo4[(size_t)c1 * 64 + q];
        if (WITHVN) {
            int bg0 = __ldg(&batch[s0]);
            int bg1 = __ldg(&batch[s1]);
            float4 w0 = vn[(size_t)bg0 * 64 + q];
            float4 w1 = vn[(size_t)bg1 * 64 + q];
            v0.x += w0.x; v0.y += w0.y; v0.z += w0.z; v0.w += w0.w;
            v1.x += w1.x; v1.y += w1.y; v1.z += w1.z; v1.w += w1.w;
        }
        ax += fmaxf(v0.x + b0.x, 0.f) + MSG_EPS + fmaxf(v1.x + b1.x, 0.f) + MSG_EPS;
        ay += fmaxf(v0.y + b0.y, 0.f) + MSG_EPS + fmaxf(v1.y + b1.y, 0.f) + MSG_EPS;
        az += fmaxf(v0.z + b0.z, 0.f) + MSG_EPS + fmaxf(v1.z + b1.z, 0.f) + MSG_EPS;
        aw += fmaxf(v0.w + b0.w, 0.f) + MSG_EPS + fmaxf(v1.w + b1.w, 0.f) + MSG_EPS;
    }
    if (i < i1) {
        int ed = __ldg(&g_elist[i]);
        int s0 = ed & 0x1FFFF, c0 = ed >> 17;
        float4 v = hin[(size_t)s0 * 64 + q];
        float4 b = combo4[(size_t)c0 * 64 + q];
        if (WITHVN) {
            int bg0 = __ldg(&batch[s0]);
            float4 w = vn[(size_t)bg0 * 64 + q];
            v.x += w.x; v.y += w.y; v.z += w.z; v.w += w.w;
        }
        ax += fmaxf(v.x + b.x, 0.f) + MSG_EPS;
        ay += fmaxf(v.y + b.y, 0.f) + MSG_EPS;
        az += fmaxf(v.z + b.z, 0.f) + MSG_EPS;
        aw += fmaxf(v.w + b.w, 0.f) + MSG_EPS;
    }
    agg[(size_t)n * 64 + q] = make_float4(ax, ay, az, aw);
}

// ---------------- tf32 helpers ----------------
__device__ __forceinline__ float tf32r(float x) {
    uint32_t u;
    asm("cvt.rna.tf32.f32 %0, %1;" : "=r"(u) : "f"(x));
    return __uint_as_float(u);
}
__device__ __forceinline__ void mma_tf32(float* c, const uint32_t* a, const uint32_t* b) {
    asm volatile("mma.sync.aligned.m16n8k8.row.col.f32.tf32.tf32.f32 "
                 "{%0,%1,%2,%3}, {%4,%5,%6,%7}, {%8,%9}, {%0,%1,%2,%3};\n"
                 : "+f"(c[0]), "+f"(c[1]), "+f"(c[2]), "+f"(c[3])
                 : "r"(a[0]), "r"(a[1]), "r"(a[2]), "r"(a[3]),
                   "r"(b[0]), "r"(b[1]));
}

// ---------------- tf32 tensor-core GEMM: out = A @ W + bias [+ res] ----------------
template<int BN, int WR, int WC>
__global__ __launch_bounds__(256)
void gemm_tf32(const float* __restrict__ A,
               const float* __restrict__ W, const float* __restrict__ bias,
               const float* __restrict__ res, float* __restrict__ out,
               int M, int ldout, int ldw)
{
    constexpr int BM = 128, BK = 16, K = D;
    constexpr int NITER = K / BK;              // 16
    constexpr int TM = BM / WR;
    constexpr int TN = BN / WC;
    constexpr int MT = TM / 16;
    constexpr int NT = TN / 8;
    constexpr int PAD = 8;
    __shared__ float As[2][BK][BM + PAD];
    __shared__ float Bs[2][BK][BN + PAD];

    const int tid  = threadIdx.x;
    const int lane = tid & 31;
    const int wid  = tid >> 5;
    const int wr   = wid / WC;
    const int wc   = wid % WC;
    const int gid  = lane >> 2;
    const int tig  = lane & 3;
    const int m0   = blockIdx.x * BM;
    const int n0   = blockIdx.y * BN;

    const int arow = tid & 127;
    const int akc  = (tid >> 7) << 3;
    const bool avalid = (m0 + arow) < M;
    const float* aptr = A + (size_t)(m0 + arow) * K + akc;

    constexpr int BVEC = (BN == 128) ? 2 : 1;
    const int bk  = tid >> 4;
    const int bnc = (tid & 15) * (BVEC * 4);
    const float* bptr = W + (size_t)bk * ldw + n0 + bnc;

    float4 a_st[2];
    float4 b_st[BVEC];

    a_st[0] = make_float4(0.f, 0.f, 0.f, 0.f);
    a_st[1] = a_st[0];
    if (avalid) {
        a_st[0] = *reinterpret_cast<const float4*>(aptr);
        a_st[1] = *reinterpret_cast<const float4*>(aptr + 4);
    }
#pragma unroll
    for (int i = 0; i < BVEC; i++)
        b_st[i] = *reinterpret_cast<const float4*>(bptr + i * 4);

    {
        const float* av = reinterpret_cast<const float*>(a_st);
#pragma unroll
        for (int j = 0; j < 8; j++) As[0][akc + j][arow] = tf32r(av[j]);
        const float* bv = reinterpret_cast<const float*>(b_st);
#pragma unroll
        for (int j = 0; j < BVEC * 4; j++) Bs[0][bk][bnc + j] = tf32r(bv[j]);
    }
    __syncthreads();

    float acc[MT][NT][4];
#pragma unroll
    for (int i = 0; i < MT; i++)
#pragma unroll
        for (int j = 0; j < NT; j++)
#pragma unroll
            for (int q = 0; q < 4; q++) acc[i][j][q] = 0.f;

    for (int k0 = 0; k0 < NITER; k0++) {
        const int cur = k0 & 1;
        if (k0 + 1 < NITER) {
            a_st[0] = make_float4(0.f, 0.f, 0.f, 0.f);
            a_st[1] = a_st[0];
            if (avalid) {
                a_st[0] = *reinterpret_cast<const float4*>(aptr + (k0 + 1) * BK);
                a_st[1] = *reinterpret_cast<const float4*>(aptr + (k0 + 1) * BK + 4);
            }
#pragma unroll
            for (int i = 0; i < BVEC; i++)
                b_st[i] = *reinterpret_cast<const float4*>(bptr + (size_t)(k0 + 1) * BK * ldw + i * 4);
        }
#pragma unroll
        for (int ks = 0; ks < 2; ks++) {
            uint32_t af[MT][4];
            uint32_t bf[NT][2];
#pragma unroll
            for (int mt = 0; mt < MT; mt++) {
                int r = wr * TM + mt * 16 + gid;
                af[mt][0] = __float_as_uint(As[cur][ks * 8 + tig    ][r]);
                af[mt][1] = __float_as_uint(As[cur][ks * 8 + tig    ][r + 8]);
                af[mt][2] = __float_as_uint(As[cur][ks * 8 + tig + 4][r]);
                af[mt][3] = __float_as_uint(As[cur][ks * 8 + tig + 4][r + 8]);
            }
#pragma unroll
            for (int nt = 0; nt < NT; nt++) {
                int c = wc * TN + nt * 8 + gid;
                bf[nt][0] = __float_as_uint(Bs[cur][ks * 8 + tig    ][c]);
                bf[nt][1] = __float_as_uint(Bs[cur][ks * 8 + tig + 4][c]);
            }
#pragma unroll
            for (int mt = 0; mt < MT; mt++)
#pragma unroll
                for (int nt = 0; nt < NT; nt++)
                    mma_tf32(acc[mt][nt], af[mt], bf[nt]);
        }
        if (k0 + 1 < NITER) {
            const int nxt = cur ^ 1;
            const float* av = reinterpret_cast<const float*>(a_st);
#pragma unroll
            for (int j = 0; j < 8; j++) As[nxt][akc + j][arow] = tf32r(av[j]);
            const float* bv = reinterpret_cast<const float*>(b_st);
#pragma unroll
            for (int j = 0; j < BVEC * 4; j++) Bs[nxt][bk][bnc + j] = tf32r(bv[j]);
            __syncthreads();
        }
    }

#pragma unroll
    for (int mt = 0; mt < MT; mt++) {
#pragma unroll
        for (int nt = 0; nt < NT; nt++) {
            int r = m0 + wr * TM + mt * 16 + gid;
            int c = n0 + wc * TN + nt * 8 + 2 * tig;
            float2 bi = *reinterpret_cast<const float2*>(&bias[c]);
            if (r < M) {
                float2 v = make_float2(acc[mt][nt][0] + bi.x, acc[mt][nt][1] + bi.y);
                if (res) {
                    float2 rr = *reinterpret_cast<const float2*>(&res[(size_t)r * D + c]);
                    v.x += rr.x; v.y += rr.y;
                }
                *reinterpret_cast<float2*>(&out[(size_t)r * ldout + c]) = v;
            }
            int r2 = r + 8;
            if (r2 < M) {
                float2 v = make_float2(acc[mt][nt][2] + bi.x, acc[mt][nt][3] + bi.y);
                if (res) {
                    float2 rr = *reinterpret_cast<const float2*>(&res[(size_t)r2 * D + c]);
                    v.x += rr.x; v.y += rr.y;
                }
                *reinterpret_cast<float2*>(&out[(size_t)r2 * ldout + c]) = v;
            }
        }
    }
}

// ---------------- LayerNorm + ReLU per node ----------------
__global__ void ln_relu_kernel(const float* __restrict__ h,
                               const float* __restrict__ gam,
                               const float* __restrict__ bet,
                               float* __restrict__ h2)
{
    int n = blockIdx.x, d = threadIdx.x;
    size_t idx = (size_t)n * D + d;
    float v = h[idx];
    float a = v, b = v * v;
    __shared__ float sa[8], sb[8];
    int lane = d & 31, w = d >> 5;
#pragma unroll
    for (int o = 16; o; o >>= 1) {
        a += __shfl_down_sync(0xffffffffu, a, o);
        b += __shfl_down_sync(0xffffffffu, b, o);
    }
    if (lane == 0) { sa[w] = a; sb[w] = b; }
    __syncthreads();
    if (w == 0) {
        a = (lane < 8) ? sa[lane] : 0.f;
        b = (lane < 8) ? sb[lane] : 0.f;
#pragma unroll
        for (int o = 4; o; o >>= 1) {
            a += __shfl_down_sync(0xffffffffu, a, o);
            b += __shfl_down_sync(0xffffffffu, b, o);
        }
        if (lane == 0) { sa[0] = a; sb[0] = b; }
    }
    __syncthreads();
    float mu  = sa[0] * (1.f / D);
    float var = sb[0] * (1.f / D) - mu * mu;
    float y = (v - mu) * rsqrtf(var + LN_EPS) * gam[d] + bet[d];
    h2[idx] = fmaxf(y, 0.f);
}

// ---------------- virtual-node path ----------------
__device__ __forceinline__ void ln_rows8(float (*t)[D], float (*s)[D],
                                         const float* __restrict__ gam,
                                         const float* __restrict__ bet,
                                         float* smu, float* srs)
{
    int lane = threadIdx.x & 31, w = threadIdx.x >> 5;
    float a = 0.f, b = 0.f;
#pragma unroll
    for (int i = 0; i < 8; i++) {
        float v = t[w][lane + 32 * i];
        a += v; b += v * v;
    }
#pragma unroll
    for (int o = 16; o; o >>= 1) {
        a += __shfl_down_sync(0xffffffffu, a, o);
        b += __shfl_down_sync(0xffffffffu, b, o);
    }
    if (lane == 0) {
        float mu = a * (1.f / D);
        float var = b * (1.f / D) - mu * mu;
        smu[w] = mu;
        srs[w] = rsqrtf(var + LN_EPS);
    }
    __syncthreads();
    int d = threadIdx.x;
    float gd = gam[d], bd = bet[d];
#pragma unroll
    for (int gg = 0; gg < 8; gg++) {
        float v = (t[gg][d] - smu[gg]) * srs[gg] * gd + bd;
        s[gg][d] = fmaxf(v, 0.f);
    }
}

__global__ void vn_mlp_kernel(const float* __restrict__ h2, const int* __restrict__ off,
                              const float* __restrict__ W1, const float* __restrict__ b1,
                              const float* __restrict__ g1, const float* __restrict__ be1,
                              const float* __restrict__ W2, const float* __restrict__ b2,
                              const float* __restrict__ g2, const float* __restrict__ be2,
                              float* __restrict__ vn)
{
    __shared__ float s[8][D];
    __shared__ float t[8][D];
    __shared__ float smu[8], srs[8];
    int d = threadIdx.x;
    int g0 = blockIdx.x * 8;

#pragma unroll
    for (int gg = 0; gg < 8; gg++) {
        int g = g0 + gg;
        float acc = vn[(size_t)g * D + d];
        int n1 = off[g + 1];
        for (int n = off[g]; n < n1; n++)
            acc += h2[(size_t)n * D + d];
        s[gg][d] = acc;
    }
    __syncthreads();

    float y[8];
#pragma unroll
    for (int gg = 0; gg < 8; gg++) y[gg] = b1[d];
    for (int k = 0; k < D; k++) {
        float w = W1[(size_t)k * D + d];
#pragma unroll
        for (int gg = 0; gg < 8; gg++) y[gg] = fmaf(s[gg][k], w, y[gg]);
    }
    __syncthreads();
#pragma unroll
    for (int gg = 0; gg < 8; gg++) t[gg][d] = y[gg];
    __syncthreads();
    ln_rows8(t, s, g1, be1, smu, srs);
    __syncthreads();

#pragma unroll
    for (int gg = 0; gg < 8; gg++) y[gg] = b2[d];
    for (int k = 0; k < D; k++) {
        float w = W2[(size_t)k * D + d];
#pragma unroll
        for (int gg = 0; gg < 8; gg++) y[gg] = fmaf(s[gg][k], w, y[gg]);
    }
    __syncthreads();
#pragma unroll
    for (int gg = 0; gg < 8; gg++) t[gg][d] = y[gg];
    __syncthreads();
    ln_rows8(t, s, g2, be2, smu, srs);
    __syncthreads();
#pragma unroll
    for (int gg = 0; gg < 8; gg++)
        vn[(size_t)(g0 + gg) * D + d] = s[gg][d];
}

// ---------------- launcher ----------------
extern "C" void kernel_launch(void* const* d_in, const int* in_sizes, int n_in,
                              void* d_out, int out_size)
{
    const int*   x          = (const int*)  d_in[0];
    const int*   edge_attr  = (const int*)  d_in[1];
    const int*   edge_index = (const int*)  d_in[2];
    const int*   batch      = (const int*)  d_in[3];
    const float* atom_emb   = (const float*)d_in[4];
    const float* bond_emb   = (const float*)d_in[5];
    const float* vn_emb     = (const float*)d_in[6];
    const float* gcn_w      = (const float*)d_in[7];
    const float* gcn_b      = (const float*)d_in[8];
    const float* norm_g     = (const float*)d_in[9];
    const float* norm_b     = (const float*)d_in[10];
    const float* ffn_w      = (const float*)d_in[11];
    const float* ffn_b      = (const float*)d_in[12];
    const float* vn_w1      = (const float*)d_in[13];
    const float* vn_b1      = (const float*)d_in[14];
    const float* vn_g1      = (const float*)d_in[15];
    const float* vn_be1     = (const float*)d_in[16];
    const float* vn_w2      = (const float*)d_in[17];
    const float* vn_b2      = (const float*)d_in[18];
    const float* vn_g2      = (const float*)d_in[19];
    const float* vn_be2     = (const float*)d_in[20];

    float* out       = (float*)d_out;                       // h_graph [N,256]
    float* out_hinit = out + (size_t)N_NODES * D;           // h_init  [N,256]

    float *ph, *ph2, *pagg, *pvn; int* poff;
    cudaGetSymbolAddress((void**)&ph,   g_h);
    cudaGetSymbolAddress((void**)&ph2,  g_h2);
    cudaGetSymbolAddress((void**)&pagg, g_agg);
    cudaGetSymbolAddress((void**)&pvn,  g_vn);
    cudaGetSymbolAddress((void**)&poff, g_off);

    const dim3 G256((N_NODES + 127) / 128, 2);
    const dim3 G64 ((N_NODES + 127) / 128, 1);
    const int AGG_GRID = (N_NODES + 3) / 4;

    // ---- CSR build (edge structure reused for all 4 layers) ----
    zero_deg_kernel<<<(N_NODES + 255) / 256, 256>>>();
    hist_kernel<<<(N_EDGES + 255) / 256, 256>>>(edge_index);
    scan_block_kernel<<<NBLK, SCAN_B>>>();
    scan_sums_kernel<<<1, 128>>>();
    add_off_kernel<<<(N_NODES + 255) / 256, 256>>>();
    copy_cursor_kernel<<<(N_NODES + 255) / 256, 256>>>();
    fill_kernel<<<(N_EDGES + 255) / 256, 256>>>(edge_index, edge_attr);
    combo_kernel<<<512, 256>>>(bond_emb);

    node_init_kernel<<<N_NODES, 256>>>(x, atom_emb, vn_emb, ph, pvn, out_hinit);
    offsets_kernel<<<(NGRAPHS + 1 + 255) / 256, 256>>>(batch, poff);

    // ----- layer 0 (vn already folded into h by node_init) -----
    aggregate_kernel<false><<<AGG_GRID, 256>>>((const float4*)ph, nullptr, nullptr, (float4*)pagg);
    gemm_tf32<128, 2, 4><<<G256, 256>>>(pagg, gcn_w, gcn_b, nullptr, ph, N_NODES, D, D);
    gemm_tf32<64, 4, 2><<<G64, 256>>>(ph, ffn_w, ffn_b, nullptr, out, N_NODES, D, 64);

    // ----- layers 1..3 (layers 4..6 are dead code: only out[0..3] reach h_graph) -----
    for (int l = 1; l < 4; l++) {
        int j = l - 1;
        ln_relu_kernel<<<N_NODES, 256>>>(ph, norm_g + (size_t)j * D, norm_b + (size_t)j * D, ph2);
        vn_mlp_kernel<<<NGRAPHS / 8, 256>>>(ph2, poff,
                                            vn_w1 + (size_t)j * D * D, vn_b1 + (size_t)j * D,
                                            vn_g1 + (size_t)j * D,     vn_be1 + (size_t)j * D,
                                            vn_w2 + (size_t)j * D * D, vn_b2 + (size_t)j * D,
                                            vn_g2 + (size_t)j * D,     vn_be2 + (size_t)j * D,
                                            pvn);
        aggregate_kernel<true><<<AGG_GRID, 256>>>((const float4*)ph2, (const float4*)pvn,
                                                  batch, (float4*)pagg);
        gemm_tf32<128, 2, 4><<<G256, 256>>>(pagg, gcn_w + (size_t)l * D * D,
                                            gcn_b + (size_t)l * D, ph, ph, N_NODES, D, D);
        gemm_tf32<64, 4, 2><<<G64, 256>>>(ph, ffn_w + (size_t)l * D * 64,
                                          ffn_b + (size_t)l * 64, nullptr,
                                          out + (size_t)l * 64, N_NODES, D, 64);
    }
}

// round 8
// speedup vs baseline: 1.9945x; 1.1050x over previous
#include <cuda_runtime.h>
#include <stddef.h>
#include <stdint.h>

#define N_NODES 100000
#define N_EDGES 300000
#define NGRAPHS 3000
#define D 256
#define MSG_EPS 1e-7f
#define LN_EPS  1e-5f
#define SCAN_B 1024
#define NBLK ((N_NODES + SCAN_B - 1) / SCAN_B)   // 98

// ---------------- scratch (static device allocations; no cudaMalloc) ----------------
__device__ __align__(16) float g_h  [(size_t)N_NODES * D];
__device__ __align__(16) float g_h2 [(size_t)N_NODES * D];
__device__ __align__(16) float g_agg[(size_t)N_NODES * D];
__device__ __align__(16) float g_vn [(size_t)NGRAPHS * D];
__device__ __align__(16) float g_combo[512 * D];          // bond combo table
__device__ int g_off[NGRAPHS + 1];
__device__ int g_deg[N_NODES];
__device__ int g_noff[N_NODES + 1];
__device__ int g_cursor[N_NODES];
__device__ int g_elist[N_EDGES];
__device__ int g_bsum[NBLK];

__device__ __forceinline__ void cp_async16(uint32_t smem_dst, const void* gsrc) {
    asm volatile("cp.async.cg.shared.global [%0], [%1], 16;\n"
                 :: "r"(smem_dst), "l"(gsrc));
}
__device__ __forceinline__ void cp_commit() {
    asm volatile("cp.async.commit_group;\n" ::);
}
__device__ __forceinline__ void cp_wait0() {
    asm volatile("cp.async.wait_group 0;\n" ::: "memory");
}

// ================= CSR build (edge_index constant across layers) =================
__global__ void zero_deg_kernel() {
    int i = blockIdx.x * blockDim.x + threadIdx.x;
    if (i < N_NODES) g_deg[i] = 0;
}
__global__ void hist_kernel(const int* __restrict__ ei) {
    int e = blockIdx.x * blockDim.x + threadIdx.x;
    if (e < N_EDGES) atomicAdd(&g_deg[ei[N_EDGES + e]], 1);
}
__global__ void scan_block_kernel() {
    __shared__ int s[SCAN_B];
    int tid = threadIdx.x;
    int i = blockIdx.x * SCAN_B + tid;
    int v = (i < N_NODES) ? g_deg[i] : 0;
    s[tid] = v;
    __syncthreads();
#pragma unroll
    for (int d = 1; d < SCAN_B; d <<= 1) {
        int t = (tid >= d) ? s[tid - d] : 0;
        __syncthreads();
        s[tid] += t;
        __syncthreads();
    }
    if (i < N_NODES) g_noff[i + 1] = s[tid];
    if (tid == SCAN_B - 1) g_bsum[blockIdx.x] = s[tid];
}
__global__ void scan_sums_kernel() {
    __shared__ int s[128];
    int tid = threadIdx.x;
    int v = (tid < NBLK) ? g_bsum[tid] : 0;
    s[tid] = v;
    __syncthreads();
#pragma unroll
    for (int d = 1; d < 128; d <<= 1) {
        int t = (tid >= d) ? s[tid - d] : 0;
        __syncthreads();
        s[tid] += t;
        __syncthreads();
    }
    if (tid < NBLK) g_bsum[tid] = s[tid] - v;   // exclusive
    if (tid == 0) g_noff[0] = 0;
}
__global__ void add_off_kernel() {
    int i = blockIdx.x * blockDim.x + threadIdx.x;
    if (i < N_NODES) g_noff[i + 1] += g_bsum[i / SCAN_B];
}
__global__ void copy_cursor_kernel() {
    int i = blockIdx.x * blockDim.x + threadIdx.x;
    if (i < N_NODES) g_cursor[i] = g_noff[i];
}
__global__ void fill_kernel(const int* __restrict__ ei, const int* __restrict__ ea) {
    int e = blockIdx.x * blockDim.x + threadIdx.x;
    if (e >= N_EDGES) return;
    int src = ei[e];
    int dst = ei[N_EDGES + e];
    int combo = ea[3 * e + 0] | (ea[3 * e + 1] << 3) | (ea[3 * e + 2] << 6);
    int pos = atomicAdd(&g_cursor[dst], 1);
    g_elist[pos] = src | (combo << 17);
}
__global__ void combo_kernel(const float* __restrict__ bond) {
    int c = blockIdx.x;        // 0..511
    int d = threadIdx.x;
    int a0 = c & 7, a1 = (c >> 3) & 7, a2 = (c >> 6) & 7;
    g_combo[c * D + d] = bond[(size_t)(0 * 8 + a0) * D + d]
                       + bond[(size_t)(1 * 8 + a1) * D + d]
                       + bond[(size_t)(2 * 8 + a2) * D + d];
}

// ---------------- node init ----------------
__global__ void node_init_kernel(const int* __restrict__ x,
                                 const float* __restrict__ atom_emb,
                                 const float* __restrict__ vn_emb,
                                 float* __restrict__ h,
                                 float* __restrict__ vn,
                                 float* __restrict__ out_hinit)
{
    int n = blockIdx.x;
    int d = threadIdx.x;
    __shared__ int xi[9];
    if (d < 9) xi[d] = x[n * 9 + d];
    __syncthreads();
    float s = 0.f;
#pragma unroll
    for (int f = 0; f < 9; f++)
        s += atom_emb[((size_t)f * 64 + xi[f]) * D + d];
    size_t idx = (size_t)n * D + d;
    out_hinit[idx] = s;
    h[idx] = s + vn_emb[d];
    if (n < NGRAPHS) vn[(size_t)n * D + d] = vn_emb[d];
}

// ---------------- graph segment offsets ----------------
__global__ void offsets_kernel(const int* __restrict__ batch, int* __restrict__ off)
{
    int g = blockIdx.x * blockDim.x + threadIdx.x;
    if (g > NGRAPHS) return;
    int lo = 0, hi = N_NODES;
    while (lo < hi) {
        int mid = (lo + hi) >> 1;
        if (batch[mid] < g) lo = mid + 1; else hi = mid;
    }
    off[g] = lo;
}

// ---------------- CSR gather aggregation ----------------
template<bool WITHVN>
__global__ void aggregate_kernel(const float4* __restrict__ hin,
                                 const float4* __restrict__ vn,
                                 const int* __restrict__ batch,
                                 float4* __restrict__ agg)
{
    int n = blockIdx.x * 4 + (threadIdx.x >> 6);
    if (n >= N_NODES) return;
    int q = threadIdx.x & 63;
    const float4* combo4 = reinterpret_cast<const float4*>(g_combo);
    int i0 = g_noff[n], i1 = g_noff[n + 1];
    float4 self = hin[(size_t)n * 64 + q];
    float ax = self.x, ay = self.y, az = self.z, aw = self.w;
    if (WITHVN) {
        int bg = __ldg(&batch[n]);
        float4 vv = vn[(size_t)bg * 64 + q];
        ax += vv.x; ay += vv.y; az += vv.z; aw += vv.w;
    }
    int i = i0;
    for (; i + 1 < i1; i += 2) {
        int ed0 = __ldg(&g_elist[i]);
        int ed1 = __ldg(&g_elist[i + 1]);
        int s0 = ed0 & 0x1FFFF, c0 = ed0 >> 17;
        int s1 = ed1 & 0x1FFFF, c1 = ed1 >> 17;
        float4 v0 = hin[(size_t)s0 * 64 + q];
        float4 v1 = hin[(size_t)s1 * 64 + q];
        float4 b0 = combo4[(size_t)c0 * 64 + q];
        float4 b1 = combo4[(size_t)c1 * 64 + q];
        if (WITHVN) {
            int bg0 = __ldg(&batch[s0]);
            int bg1 = __ldg(&batch[s1]);
            float4 w0 = vn[(size_t)bg0 * 64 + q];
            float4 w1 = vn[(size_t)bg1 * 64 + q];
            v0.x += w0.x; v0.y += w0.y; v0.z += w0.z; v0.w += w0.w;
            v1.x += w1.x; v1.y += w1.y; v1.z += w1.z; v1.w += w1.w;
        }
        ax += fmaxf(v0.x + b0.x, 0.f) + MSG_EPS + fmaxf(v1.x + b1.x, 0.f) + MSG_EPS;
        ay += fmaxf(v0.y + b0.y, 0.f) + MSG_EPS + fmaxf(v1.y + b1.y, 0.f) + MSG_EPS;
        az += fmaxf(v0.z + b0.z, 0.f) + MSG_EPS + fmaxf(v1.z + b1.z, 0.f) + MSG_EPS;
        aw += fmaxf(v0.w + b0.w, 0.f) + MSG_EPS + fmaxf(v1.w + b1.w, 0.f) + MSG_EPS;
    }
    if (i < i1) {
        int ed = __ldg(&g_elist[i]);
        int s0 = ed & 0x1FFFF, c0 = ed >> 17;
        float4 v = hin[(size_t)s0 * 64 + q];
        float4 b = combo4[(size_t)c0 * 64 + q];
        if (WITHVN) {
            int bg0 = __ldg(&batch[s0]);
            float4 w = vn[(size_t)bg0 * 64 + q];
            v.x += w.x; v.y += w.y; v.z += w.z; v.w += w.w;
        }
        ax += fmaxf(v.x + b.x, 0.f) + MSG_EPS;
        ay += fmaxf(v.y + b.y, 0.f) + MSG_EPS;
        az += fmaxf(v.z + b.z, 0.f) + MSG_EPS;
        aw += fmaxf(v.w + b.w, 0.f) + MSG_EPS;
    }
    agg[(size_t)n * 64 + q] = make_float4(ax, ay, az, aw);
}

// ---------------- tf32 helpers ----------------
__device__ __forceinline__ float tf32r(float x) {
    uint32_t u;
    asm("cvt.rna.tf32.f32 %0, %1;" : "=r"(u) : "f"(x));
    return __uint_as_float(u);
}
__device__ __forceinline__ uint32_t tf32u(float x) {
    uint32_t u;
    asm("cvt.rna.tf32.f32 %0, %1;" : "=r"(u) : "f"(x));
    return u;
}
__device__ __forceinline__ void mma_tf32(float* c, const uint32_t* a, const uint32_t* b) {
    asm volatile("mma.sync.aligned.m16n8k8.row.col.f32.tf32.tf32.f32 "
                 "{%0,%1,%2,%3}, {%4,%5,%6,%7}, {%8,%9}, {%0,%1,%2,%3};\n"
                 : "+f"(c[0]), "+f"(c[1]), "+f"(c[2]), "+f"(c[3])
                 : "r"(a[0]), "r"(a[1]), "r"(a[2]), "r"(a[3]),
                   "r"(b[0]), "r"(b[1]));
}

// ==================== fused GCN GEMM + residual + LayerNorm/ReLU ====================
// outh  = A @ W + bias (+res)              [M, 256]
// outh2 = relu(LN(outh, gam, bet))  if gam [M, 256]
// BM=64, BN=256 (whole rows per block -> LN in epilogue), cp.async B, 2 CTAs/SM.
__global__ __launch_bounds__(256, 2)
void gemm_fused(const float* __restrict__ A,
                const float* __restrict__ W, const float* __restrict__ bias,
                const float* __restrict__ res,
                const float* __restrict__ gam, const float* __restrict__ bet,
                float* __restrict__ outh, float* __restrict__ outh2, int M)
{
    constexpr int BM = 64, BN = 256, BK = 16, K = D;
    constexpr int NITER = K / BK;              // 16
    constexpr int MT = 2, NT = 8;              // warp tile 32x64 (WR=2, WC=4)
    constexpr int PADA = 8, PADB = 8;
    __shared__ float As[2][BK][BM + PADA];     // tf32-converted
    __shared__ float Bs[2][BK][BN + PADB];     // raw fp32 via cp.async
    __shared__ float ssA[BM][5], ssB[BM][5];
    __shared__ float smu[BM], srs[BM];

    const int tid  = threadIdx.x;
    const int lane = tid & 31;
    const int wid  = tid >> 5;
    const int wr   = wid >> 2;          // 0..1
    const int wc   = wid & 3;           // 0..3
    const int gid  = lane >> 2;
    const int tig  = lane & 3;
    const int m0   = blockIdx.x * BM;

    const int arow = tid & 63;
    const int akc  = (tid >> 6) << 2;
    const bool avalid = (m0 + arow) < M;
    const float* aptr = A + (size_t)(m0 + arow) * K + akc;

    const int bk  = tid >> 4;
    const int bnc = (tid & 15) << 4;
    const float* bptr = W + (size_t)bk * BN + bnc;
    const uint32_t sB0 = (uint32_t)__cvta_generic_to_shared(&Bs[0][bk][bnc]);
    const uint32_t sB1 = (uint32_t)__cvta_generic_to_shared(&Bs[1][bk][bnc]);

    // ---- prologue ----
#pragma unroll
    for (int j = 0; j < 4; j++)
        cp_async16(sB0 + j * 16, bptr + j * 4);
    cp_commit();
    float4 a0 = make_float4(0.f, 0.f, 0.f, 0.f);
    if (avalid) a0 = *reinterpret_cast<const float4*>(aptr);
    As[0][akc + 0][arow] = tf32r(a0.x);
    As[0][akc + 1][arow] = tf32r(a0.y);
    As[0][akc + 2][arow] = tf32r(a0.z);
    As[0][akc + 3][arow] = tf32r(a0.w);
    cp_wait0();
    __syncthreads();

    float acc[MT][NT][4];
#pragma unroll
    for (int i = 0; i < MT; i++)
#pragma unroll
        for (int j = 0; j < NT; j++)
#pragma unroll
            for (int q = 0; q < 4; q++) acc[i][j][q] = 0.f;

    for (int k0 = 0; k0 < NITER; k0++) {
        const int cur = k0 & 1;
        float4 an = make_float4(0.f, 0.f, 0.f, 0.f);
        if (k0 + 1 < NITER) {
            const uint32_t sB = (cur ? sB0 : sB1);
            const float* bp = bptr + (size_t)(k0 + 1) * BK * BN;
#pragma unroll
            for (int j = 0; j < 4; j++)
                cp_async16(sB + j * 16, bp + j * 4);
            cp_commit();
            if (avalid) an = *reinterpret_cast<const float4*>(aptr + (k0 + 1) * BK);
        }
#pragma unroll
        for (int ks = 0; ks < 2; ks++) {
            uint32_t af[MT][4];
            uint32_t bf[NT][2];
#pragma unroll
            for (int mt = 0; mt < MT; mt++) {
                int r = wr * 32 + mt * 16 + gid;
                af[mt][0] = __float_as_uint(As[cur][ks * 8 + tig    ][r]);
                af[mt][1] = __float_as_uint(As[cur][ks * 8 + tig    ][r + 8]);
                af[mt][2] = __float_as_uint(As[cur][ks * 8 + tig + 4][r]);
                af[mt][3] = __float_as_uint(As[cur][ks * 8 + tig + 4][r + 8]);
            }
#pragma unroll
            for (int nt = 0; nt < NT; nt++) {
                int c = wc * 64 + nt * 8 + gid;
                bf[nt][0] = tf32u(Bs[cur][ks * 8 + tig    ][c]);
                bf[nt][1] = tf32u(Bs[cur][ks * 8 + tig + 4][c]);
            }
#pragma unroll
            for (int mt = 0; mt < MT; mt++)
#pragma unroll
                for (int nt = 0; nt < NT; nt++)
                    mma_tf32(acc[mt][nt], af[mt], bf[nt]);
        }
        if (k0 + 1 < NITER) {
            const int nxt = cur ^ 1;
            As[nxt][akc + 0][arow] = tf32r(an.x);
            As[nxt][akc + 1][arow] = tf32r(an.y);
            As[nxt][akc + 2][arow] = tf32r(an.z);
            As[nxt][akc + 3][arow] = tf32r(an.w);
            cp_wait0();
            __syncthreads();
        }
    }

    // ---- epilogue: v = acc + bias (+res); write h ----
#pragma unroll
    for (int mt = 0; mt < MT; mt++) {
        int r  = m0 + wr * 32 + mt * 16 + gid;
        int r2 = r + 8;
#pragma unroll
        for (int nt = 0; nt < NT; nt++) {
            int c = wc * 64 + nt * 8 + 2 * tig;
            float2 bi = *reinterpret_cast<const float2*>(&bias[c]);
            float v0 = acc[mt][nt][0] + bi.x;
            float v1 = acc[mt][nt][1] + bi.y;
            float v2 = acc[mt][nt][2] + bi.x;
            float v3 = acc[mt][nt][3] + bi.y;
            if (res) {
                if (r < M) {
                    float2 rr = *reinterpret_cast<const float2*>(&res[(size_t)r * D + c]);
                    v0 += rr.x; v1 += rr.y;
                }
                if (r2 < M) {
                    float2 rr = *reinterpret_cast<const float2*>(&res[(size_t)r2 * D + c]);
                    v2 += rr.x; v3 += rr.y;
                }
            }
            acc[mt][nt][0] = v0; acc[mt][nt][1] = v1;
            acc[mt][nt][2] = v2; acc[mt][nt][3] = v3;
            if (r < M)
                *reinterpret_cast<float2*>(&outh[(size_t)r * D + c]) = make_float2(v0, v1);
            if (r2 < M)
                *reinterpret_cast<float2*>(&outh[(size_t)r2 * D + c]) = make_float2(v2, v3);
        }
    }

    if (!gam) return;

    // ---- LayerNorm + ReLU -> outh2 ----
#pragma unroll
    for (int mt = 0; mt < MT; mt++) {
#pragma unroll
        for (int hh = 0; hh < 2; hh++) {
            float s = 0.f, q = 0.f;
#pragma unroll
            for (int nt = 0; nt < NT; nt++) {
                float u0 = acc[mt][nt][2 * hh];
                float u1 = acc[mt][nt][2 * hh + 1];
                s += u0 + u1;
                q += u0 * u0 + u1 * u1;
            }
            s += __shfl_xor_sync(0xffffffffu, s, 1);
            q += __shfl_xor_sync(0xffffffffu, q, 1);
            s += __shfl_xor_sync(0xffffffffu, s, 2);
            q += __shfl_xor_sync(0xffffffffu, q, 2);
            if (tig == 0) {
                int lr = wr * 32 + mt * 16 + hh * 8 + gid;
                ssA[lr][wc] = s;
                ssB[lr][wc] = q;
            }
        }
    }
    __syncthreads();
    if (tid < BM) {
        float s = ssA[tid][0] + ssA[tid][1] + ssA[tid][2] + ssA[tid][3];
        float q = ssB[tid][0] + ssB[tid][1] + ssB[tid][2] + ssB[tid][3];
        float mu  = s * (1.f / D);
        float var = q * (1.f / D) - mu * mu;
        smu[tid] = mu;
        srs[tid] = rsqrtf(var + LN_EPS);
    }
    __syncthreads();

#pragma unroll
    for (int mt = 0; mt < MT; mt++) {
        int lr  = wr * 32 + mt * 16 + gid;
        int lr2 = lr + 8;
        int r   = m0 + lr;
        int r2  = m0 + lr2;
        float mu0 = smu[lr],  rs0 = srs[lr];
        float mu1 = smu[lr2], rs1 = srs[lr2];
#pragma unroll
        for (int nt = 0; nt < NT; nt++) {
            int c = wc * 64 + nt * 8 + 2 * tig;
            float2 gg = *reinterpret_cast<const float2*>(&gam[c]);
            float2 bb = *reinterpret_cast<const float2*>(&bet[c]);
            if (r < M) {
                float y0 = (acc[mt][nt][0] - mu0) * rs0 * gg.x + bb.x;
                float y1 = (acc[mt][nt][1] - mu0) * rs0 * gg.y + bb.y;
                *reinterpret_cast<float2*>(&outh2[(size_t)r * D + c]) =
                    make_float2(fmaxf(y0, 0.f), fmaxf(y1, 0.f));
            }
            if (r2 < M) {
                float y2 = (acc[mt][nt][2] - mu1) * rs1 * gg.x + bb.x;
                float y3 = (acc[mt][nt][3] - mu1) * rs1 * gg.y + bb.y;
                *reinterpret_cast<float2*>(&outh2[(size_t)r2 * D + c]) =
                    make_float2(fmaxf(y2, 0.f), fmaxf(y3, 0.f));
            }
        }
    }
}

// ---------------- tf32 GEMM (FFN) ----------------
template<int BN, int WR, int WC>
__global__ __launch_bounds__(256)
void gemm_tf32(const float* __restrict__ A,
               const float* __restrict__ W, const float* __restrict__ bias,
               const float* __restrict__ res, float* __restrict__ out,
               int M, int ldout, int ldw)
{
    constexpr int BM = 128, BK = 16, K = D;
    constexpr int NITER = K / BK;
    constexpr int TM = BM / WR;
    constexpr int TN = BN / WC;
    constexpr int MT = TM / 16;
    constexpr int NT = TN / 8;
    constexpr int PAD = 8;
    __shared__ float As[2][BK][BM + PAD];
    __shared__ float Bs[2][BK][BN + PAD];

    const int tid  = threadIdx.x;
    const int lane = tid & 31;
    const int wid  = tid >> 5;
    const int wr   = wid / WC;
    const int wc   = wid % WC;
    const int gid  = lane >> 2;
    const int tig  = lane & 3;
    const int m0   = blockIdx.x * BM;
    const int n0   = blockIdx.y * BN;

    const int arow = tid & 127;
    const int akc  = (tid >> 7) << 3;
    const bool avalid = (m0 + arow) < M;
    const float* aptr = A + (size_t)(m0 + arow) * K + akc;

    constexpr int BVEC = (BN == 128) ? 2 : 1;
    const int bk  = tid >> 4;
    const int bnc = (tid & 15) * (BVEC * 4);
    const float* bptr = W + (size_t)bk * ldw + n0 + bnc;

    float4 a_st[2];
    float4 b_st[BVEC];

    a_st[0] = make_float4(0.f, 0.f, 0.f, 0.f);
    a_st[1] = a_st[0];
    if (avalid) {
        a_st[0] = *reinterpret_cast<const float4*>(aptr);
        a_st[1] = *reinterpret_cast<const float4*>(aptr + 4);
    }
#pragma unroll
    for (int i = 0; i < BVEC; i++)
        b_st[i] = *reinterpret_cast<const float4*>(bptr + i * 4);

    {
        const float* av = reinterpret_cast<const float*>(a_st);
#pragma unroll
        for (int j = 0; j < 8; j++) As[0][akc + j][arow] = tf32r(av[j]);
        const float* bv = reinterpret_cast<const float*>(b_st);
#pragma unroll
        for (int j = 0; j < BVEC * 4; j++) Bs[0][bk][bnc + j] = tf32r(bv[j]);
    }
    __syncthreads();

    float acc[MT][NT][4];
#pragma unroll
    for (int i = 0; i < MT; i++)
#pragma unroll
        for (int j = 0; j < NT; j++)
#pragma unroll
            for (int q = 0; q < 4; q++) acc[i][j][q] = 0.f;

    for (int k0 = 0; k0 < NITER; k0++) {
        const int cur = k0 & 1;
        if (k0 + 1 < NITER) {
            a_st[0] = make_float4(0.f, 0.f, 0.f, 0.f);
            a_st[1] = a_st[0];
            if (avalid) {
                a_st[0] = *reinterpret_cast<const float4*>(aptr + (k0 + 1) * BK);
                a_st[1] = *reinterpret_cast<const float4*>(aptr + (k0 + 1) * BK + 4);
            }
#pragma unroll
            for (int i = 0; i < BVEC; i++)
                b_st[i] = *reinterpret_cast<const float4*>(bptr + (size_t)(k0 + 1) * BK * ldw + i * 4);
        }
#pragma unroll
        for (int ks = 0; ks < 2; ks++) {
            uint32_t af[MT][4];
            uint32_t bf[NT][2];
#pragma unroll
            for (int mt = 0; mt < MT; mt++) {
                int r = wr * TM + mt * 16 + gid;
                af[mt][0] = __float_as_uint(As[cur][ks * 8 + tig    ][r]);
                af[mt][1] = __float_as_uint(As[cur][ks * 8 + tig    ][r + 8]);
                af[mt][2] = __float_as_uint(As[cur][ks * 8 + tig + 4][r]);
                af[mt][3] = __float_as_uint(As[cur][ks * 8 + tig + 4][r + 8]);
            }
#pragma unroll
            for (int nt = 0; nt < NT; nt++) {
                int c = wc * TN + nt * 8 + gid;
                bf[nt][0] = __float_as_uint(Bs[cur][ks * 8 + tig    ][c]);
                bf[nt][1] = __float_as_uint(Bs[cur][ks * 8 + tig + 4][c]);
            }
#pragma unroll
            for (int mt = 0; mt < MT; mt++)
#pragma unroll
                for (int nt = 0; nt < NT; nt++)
                    mma_tf32(acc[mt][nt], af[mt], bf[nt]);
        }
        if (k0 + 1 < NITER) {
            const int nxt = cur ^ 1;
            const float* av = reinterpret_cast<const float*>(a_st);
#pragma unroll
            for (int j = 0; j < 8; j++) As[nxt][akc + j][arow] = tf32r(av[j]);
            const float* bv = reinterpret_cast<const float*>(b_st);
#pragma unroll
            for (int j = 0; j < BVEC * 4; j++) Bs[nxt][bk][bnc + j] = tf32r(bv[j]);
            __syncthreads();
        }
    }

#pragma unroll
    for (int mt = 0; mt < MT; mt++) {
#pragma unroll
        for (int nt = 0; nt < NT; nt++) {
            int r = m0 + wr * TM + mt * 16 + gid;
            int c = n0 + wc * TN + nt * 8 + 2 * tig;
            float2 bi = *reinterpret_cast<const float2*>(&bias[c]);
            if (r < M) {
                float2 v = make_float2(acc[mt][nt][0] + bi.x, acc[mt][nt][1] + bi.y);
                if (res) {
                    float2 rr = *reinterpret_cast<const float2*>(&res[(size_t)r * D + c]);
                    v.x += rr.x; v.y += rr.y;
                }
                *reinterpret_cast<float2*>(&out[(size_t)r * ldout + c]) = v;
            }
            int r2 = r + 8;
            if (r2 < M) {
                float2 v = make_float2(acc[mt][nt][2] + bi.x, acc[mt][nt][3] + bi.y);
                if (res) {
                    float2 rr = *reinterpret_cast<const float2*>(&res[(size_t)r2 * D + c]);
                    v.x += rr.x; v.y += rr.y;
                }
                *reinterpret_cast<float2*>(&out[(size_t)r2 * ldout + c]) = v;
            }
        }
    }
}

// ---------------- virtual-node path ----------------
__device__ __forceinline__ void ln_rows8(float (*t)[D], float (*s)[D],
                                         const float* __restrict__ gam,
                                         const float* __restrict__ bet,
                                         float* smu, float* srs)
{
    int lane = threadIdx.x & 31, w = threadIdx.x >> 5;
    float a = 0.f, b = 0.f;
#pragma unroll
    for (int i = 0; i < 8; i++) {
        float v = t[w][lane + 32 * i];
        a += v; b += v * v;
    }
#pragma unroll
    for (int o = 16; o; o >>= 1) {
        a += __shfl_down_sync(0xffffffffu, a, o);
        b += __shfl_down_sync(0xffffffffu, b, o);
    }
    if (lane == 0) {
        float mu = a * (1.f / D);
        float var = b * (1.f / D) - mu * mu;
        smu[w] = mu;
        srs[w] = rsqrtf(var + LN_EPS);
    }
    __syncthreads();
    int d = threadIdx.x;
    float gd = gam[d], bd = bet[d];
#pragma unroll
    for (int gg = 0; gg < 8; gg++) {
        float v = (t[gg][d] - smu[gg]) * srs[gg] * gd + bd;
        s[gg][d] = fmaxf(v, 0.f);
    }
}

__global__ void vn_mlp_kernel(const float* __restrict__ h2, const int* __restrict__ off,
                              const float* __restrict__ W1, const float* __restrict__ b1,
                              const float* __restrict__ g1, const float* __restrict__ be1,
                              const float* __restrict__ W2, const float* __restrict__ b2,
                              const float* __restrict__ g2, const float* __restrict__ be2,
                              float* __restrict__ vn)
{
    __shared__ float s[8][D];
    __shared__ float t[8][D];
    __shared__ float smu[8], srs[8];
    int d = threadIdx.x;
    int g0 = blockIdx.x * 8;

#pragma unroll
    for (int gg = 0; gg < 8; gg++) {
        int g = g0 + gg;
        float acc = vn[(size_t)g * D + d];
        int n1 = off[g + 1];
        for (int n = off[g]; n < n1; n++)
            acc += h2[(size_t)n * D + d];
        s[gg][d] = acc;
    }
    __syncthreads();

    float y[8];
#pragma unroll
    for (int gg = 0; gg < 8; gg++) y[gg] = b1[d];
    for (int k = 0; k < D; k++) {
        float w = W1[(size_t)k * D + d];
#pragma unroll
        for (int gg = 0; gg < 8; gg++) y[gg] = fmaf(s[gg][k], w, y[gg]);
    }
    __syncthreads();
#pragma unroll
    for (int gg = 0; gg < 8; gg++) t[gg][d] = y[gg];
    __syncthreads();
    ln_rows8(t, s, g1, be1, smu, srs);
    __syncthreads();

#pragma unroll
    for (int gg = 0; gg < 8; gg++) y[gg] = b2[d];
    for (int k = 0; k < D; k++) {
        float w = W2[(size_t)k * D + d];
#pragma unroll
        for (int gg = 0; gg < 8; gg++) y[gg] = fmaf(s[gg][k], w, y[gg]);
    }
    __syncthreads();
#pragma unroll
    for (int gg = 0; gg < 8; gg++) t[gg][d] = y[gg];
    __syncthreads();
    ln_rows8(t, s, g2, be2, smu, srs);
    __syncthreads();
#pragma unroll
    for (int gg = 0; gg < 8; gg++)
        vn[(size_t)(g0 + gg) * D + d] = s[gg][d];
}

// ---------------- launcher ----------------
extern "C" void kernel_launch(void* const* d_in, const int* in_sizes, int n_in,
                              void* d_out, int out_size)
{
    const int*   x          = (const int*)  d_in[0];
    const int*   edge_attr  = (const int*)  d_in[1];
    const int*   edge_index = (const int*)  d_in[2];
    const int*   batch      = (const int*)  d_in[3];
    const float* atom_emb   = (const float*)d_in[4];
    const float* bond_emb   = (const float*)d_in[5];
    const float* vn_emb     = (const float*)d_in[6];
    const float* gcn_w      = (const float*)d_in[7];
    const float* gcn_b      = (const float*)d_in[8];
    const float* norm_g     = (const float*)d_in[9];
    const float* norm_b     = (const float*)d_in[10];
    const float* ffn_w      = (const float*)d_in[11];
    const float* ffn_b      = (const float*)d_in[12];
    const float* vn_w1      = (const float*)d_in[13];
    const float* vn_b1      = (const float*)d_in[14];
    const float* vn_g1      = (const float*)d_in[15];
    const float* vn_be1     = (const float*)d_in[16];
    const float* vn_w2      = (const float*)d_in[17];
    const float* vn_b2      = (const float*)d_in[18];
    const float* vn_g2      = (const float*)d_in[19];
    const float* vn_be2     = (const float*)d_in[20];

    float* out       = (float*)d_out;                       // h_graph [N,256]
    float* out_hinit = out + (size_t)N_NODES * D;           // h_init  [N,256]

    float *ph, *ph2, *pagg, *pvn; int* poff;
    cudaGetSymbolAddress((void**)&ph,   g_h);
    cudaGetSymbolAddress((void**)&ph2,  g_h2);
    cudaGetSymbolAddress((void**)&pagg, g_agg);
    cudaGetSymbolAddress((void**)&pvn,  g_vn);
    cudaGetSymbolAddress((void**)&poff, g_off);

    const int FUSED_GRID = (N_NODES + 63) / 64;   // 1563
    const dim3 G64((N_NODES + 127) / 128, 1);
    const int AGG_GRID = (N_NODES + 3) / 4;

    // ---- CSR build (edge structure reused for all 4 layers) ----
    zero_deg_kernel<<<(N_NODES + 255) / 256, 256>>>();
    hist_kernel<<<(N_EDGES + 255) / 256, 256>>>(edge_index);
    scan_block_kernel<<<NBLK, SCAN_B>>>();
    scan_sums_kernel<<<1, 128>>>();
    add_off_kernel<<<(N_NODES + 255) / 256, 256>>>();
    copy_cursor_kernel<<<(N_NODES + 255) / 256, 256>>>();
    fill_kernel<<<(N_EDGES + 255) / 256, 256>>>(edge_index, edge_attr);
    combo_kernel<<<512, 256>>>(bond_emb);

    node_init_kernel<<<N_NODES, 256>>>(x, atom_emb, vn_emb, ph, pvn, out_hinit);
    offsets_kernel<<<(NGRAPHS + 1 + 255) / 256, 256>>>(batch, poff);

    // ----- layer 0 (LN for next layer fused into GEMM epilogue) -----
    aggregate_kernel<false><<<AGG_GRID, 256>>>((const float4*)ph, nullptr, nullptr, (float4*)pagg);
    gemm_fused<<<FUSED_GRID, 256>>>(pagg, gcn_w, gcn_b, nullptr,
                                    norm_g, norm_b, ph, ph2, N_NODES);
    gemm_tf32<64, 4, 2><<<G64, 256>>>(ph, ffn_w, ffn_b, nullptr, out, N_NODES, D, 64);

    // ----- layers 1..3 (layers 4..6 dead: only out[0..3] reach h_graph) -----
    for (int l = 1; l < 4; l++) {
        int j = l - 1;
        vn_mlp_kernel<<<NGRAPHS / 8, 256>>>(ph2, poff,
                                            vn_w1 + (size_t)j * D * D, vn_b1 + (size_t)j * D,
                                            vn_g1 + (size_t)j * D,     vn_be1 + (size_t)j * D,
                                            vn_w2 + (size_t)j * D * D, vn_b2 + (size_t)j * D,
                                            vn_g2 + (size_t)j * D,     vn_be2 + (size_t)j * D,
                                            pvn);
        aggregate_kernel<true><<<AGG_GRID, 256>>>((const float4*)ph2, (const float4*)pvn,
                                                  batch, (float4*)pagg);
        const float* gl = (l < 3) ? (norm_g + (size_t)l * D) : nullptr;
        const float* bl = (l < 3) ? (norm_b + (size_t)l * D) : nullptr;
        gemm_fused<<<FUSED_GRID, 256>>>(pagg, gcn_w + (size_t)l * D * D,
                                        gcn_b + (size_t)l * D, ph,
                                        gl, bl, ph, ph2, N_NODES);
        gemm_tf32<64, 4, 2><<<G64, 256>>>(ph, ffn_w + (size_t)l * D * 64,
                                          ffn_b + (size_t)l * 64, nullptr,
                                          out + (size_t)l * 64, N_NODES, D, 64);
    }
}

// round 9
// speedup vs baseline: 2.1207x; 1.0633x over previous
#include <cuda_runtime.h>
#include <stddef.h>
#include <stdint.h>

#define N_NODES 100000
#define N_EDGES 300000
#define NGRAPHS 3000
#define D 256
#define MSG_EPS 1e-7f
#define LN_EPS  1e-5f
#define SCAN_B 1024
#define NBLK ((N_NODES + SCAN_B - 1) / SCAN_B)   // 98

// ---------------- scratch (static device allocations; no cudaMalloc) ----------------
__device__ __align__(16) float g_h  [(size_t)N_NODES * D];
__device__ __align__(16) float g_h2 [(size_t)N_NODES * D];
__device__ __align__(16) float g_agg[(size_t)N_NODES * D];
__device__ __align__(16) float g_vn [(size_t)NGRAPHS * D];
__device__ __align__(16) float g_combo[512 * D];          // bond combo table
__device__ int g_off[NGRAPHS + 1];
__device__ int g_deg[N_NODES];
__device__ int g_noff[N_NODES + 1];
__device__ int g_cursor[N_NODES];
__device__ int g_elist[N_EDGES];
__device__ int g_bsum[NBLK];

__device__ __forceinline__ void cp_async16(uint32_t smem_dst, const void* gsrc) {
    asm volatile("cp.async.cg.shared.global [%0], [%1], 16;\n"
                 :: "r"(smem_dst), "l"(gsrc));
}
__device__ __forceinline__ void cp_commit() {
    asm volatile("cp.async.commit_group;\n" ::);
}
__device__ __forceinline__ void cp_wait0() {
    asm volatile("cp.async.wait_group 0;\n" ::: "memory");
}

// ================= CSR build (edge_index constant across layers) =================
__global__ void zero_deg_kernel() {
    int i = blockIdx.x * blockDim.x + threadIdx.x;
    if (i < N_NODES) g_deg[i] = 0;
}
__global__ void hist_kernel(const int* __restrict__ ei) {
    int e = blockIdx.x * blockDim.x + threadIdx.x;
    if (e < N_EDGES) atomicAdd(&g_deg[ei[N_EDGES + e]], 1);
}
__global__ void scan_block_kernel() {
    __shared__ int s[SCAN_B];
    int tid = threadIdx.x;
    int i = blockIdx.x * SCAN_B + tid;
    int v = (i < N_NODES) ? g_deg[i] : 0;
    s[tid] = v;
    __syncthreads();
#pragma unroll
    for (int d = 1; d < SCAN_B; d <<= 1) {
        int t = (tid >= d) ? s[tid - d] : 0;
        __syncthreads();
        s[tid] += t;
        __syncthreads();
    }
    if (i < N_NODES) g_noff[i + 1] = s[tid];
    if (tid == SCAN_B - 1) g_bsum[blockIdx.x] = s[tid];
}
__global__ void scan_sums_kernel() {
    __shared__ int s[128];
    int tid = threadIdx.x;
    int v = (tid < NBLK) ? g_bsum[tid] : 0;
    s[tid] = v;
    __syncthreads();
#pragma unroll
    for (int d = 1; d < 128; d <<= 1) {
        int t = (tid >= d) ? s[tid - d] : 0;
        __syncthreads();
        s[tid] += t;
        __syncthreads();
    }
    if (tid < NBLK) g_bsum[tid] = s[tid] - v;   // exclusive
    if (tid == 0) g_noff[0] = 0;
}
__global__ void add_off_kernel() {
    int i = blockIdx.x * blockDim.x + threadIdx.x;
    if (i < N_NODES) g_noff[i + 1] += g_bsum[i / SCAN_B];
}
__global__ void copy_cursor_kernel() {
    int i = blockIdx.x * blockDim.x + threadIdx.x;
    if (i < N_NODES) g_cursor[i] = g_noff[i];
}
__global__ void fill_kernel(const int* __restrict__ ei, const int* __restrict__ ea) {
    int e = blockIdx.x * blockDim.x + threadIdx.x;
    if (e >= N_EDGES) return;
    int src = ei[e];
    int dst = ei[N_EDGES + e];
    int combo = ea[3 * e + 0] | (ea[3 * e + 1] << 3) | (ea[3 * e + 2] << 6);
    int pos = atomicAdd(&g_cursor[dst], 1);
    g_elist[pos] = src | (combo << 17);
}
__global__ void combo_kernel(const float* __restrict__ bond) {
    int c = blockIdx.x;        // 0..511
    int d = threadIdx.x;
    int a0 = c & 7, a1 = (c >> 3) & 7, a2 = (c >> 6) & 7;
    g_combo[c * D + d] = bond[(size_t)(0 * 8 + a0) * D + d]
                       + bond[(size_t)(1 * 8 + a1) * D + d]
                       + bond[(size_t)(2 * 8 + a2) * D + d];
}

// ---------------- node init ----------------
__global__ void node_init_kernel(const int* __restrict__ x,
                                 const float* __restrict__ atom_emb,
                                 const float* __restrict__ vn_emb,
                                 float* __restrict__ h,
                                 float* __restrict__ vn,
                                 float* __restrict__ out_hinit)
{
    int n = blockIdx.x;
    int d = threadIdx.x;
    __shared__ int xi[9];
    if (d < 9) xi[d] = x[n * 9 + d];
    __syncthreads();
    float s = 0.f;
#pragma unroll
    for (int f = 0; f < 9; f++)
        s += atom_emb[((size_t)f * 64 + xi[f]) * D + d];
    size_t idx = (size_t)n * D + d;
    out_hinit[idx] = s;
    h[idx] = s + vn_emb[d];
    if (n < NGRAPHS) vn[(size_t)n * D + d] = vn_emb[d];
}

// ---------------- graph segment offsets ----------------
__global__ void offsets_kernel(const int* __restrict__ batch, int* __restrict__ off)
{
    int g = blockIdx.x * blockDim.x + threadIdx.x;
    if (g > NGRAPHS) return;
    int lo = 0, hi = N_NODES;
    while (lo < hi) {
        int mid = (lo + hi) >> 1;
        if (batch[mid] < g) lo = mid + 1; else hi = mid;
    }
    off[g] = lo;
}

// ---------------- CSR gather aggregation ----------------
template<bool WITHVN>
__global__ void aggregate_kernel(const float4* __restrict__ hin,
                                 const float4* __restrict__ vn,
                                 const int* __restrict__ batch,
                                 float4* __restrict__ agg)
{
    int n = blockIdx.x * 4 + (threadIdx.x >> 6);
    if (n >= N_NODES) return;
    int q = threadIdx.x & 63;
    const float4* combo4 = reinterpret_cast<const float4*>(g_combo);
    int i0 = g_noff[n], i1 = g_noff[n + 1];
    float4 self = hin[(size_t)n * 64 + q];
    float ax = self.x, ay = self.y, az = self.z, aw = self.w;
    if (WITHVN) {
        int bg = __ldg(&batch[n]);
        float4 vv = vn[(size_t)bg * 64 + q];
        ax += vv.x; ay += vv.y; az += vv.z; aw += vv.w;
    }
    int i = i0;
    for (; i + 1 < i1; i += 2) {
        int ed0 = __ldg(&g_elist[i]);
        int ed1 = __ldg(&g_elist[i + 1]);
        int s0 = ed0 & 0x1FFFF, c0 = ed0 >> 17;
        int s1 = ed1 & 0x1FFFF, c1 = ed1 >> 17;
        float4 v0 = hin[(size_t)s0 * 64 + q];
        float4 v1 = hin[(size_t)s1 * 64 + q];
        float4 b0 = combo4[(size_t)c0 * 64 + q];
        float4 b1 = combo4[(size_t)c1 * 64 + q];
        if (WITHVN) {
            int bg0 = __ldg(&batch[s0]);
            int bg1 = __ldg(&batch[s1]);
            float4 w0 = vn[(size_t)bg0 * 64 + q];
            float4 w1 = vn[(size_t)bg1 * 64 + q];
            v0.x += w0.x; v0.y += w0.y; v0.z += w0.z; v0.w += w0.w;
            v1.x += w1.x; v1.y += w1.y; v1.z += w1.z; v1.w += w1.w;
        }
        ax += fmaxf(v0.x + b0.x, 0.f) + MSG_EPS + fmaxf(v1.x + b1.x, 0.f) + MSG_EPS;
        ay += fmaxf(v0.y + b0.y, 0.f) + MSG_EPS + fmaxf(v1.y + b1.y, 0.f) + MSG_EPS;
        az += fmaxf(v0.z + b0.z, 0.f) + MSG_EPS + fmaxf(v1.z + b1.z, 0.f) + MSG_EPS;
        aw += fmaxf(v0.w + b0.w, 0.f) + MSG_EPS + fmaxf(v1.w + b1.w, 0.f) + MSG_EPS;
    }
    if (i < i1) {
        int ed = __ldg(&g_elist[i]);
        int s0 = ed & 0x1FFFF, c0 = ed >> 17;
        float4 v = hin[(size_t)s0 * 64 + q];
        float4 b = combo4[(size_t)c0 * 64 + q];
        if (WITHVN) {
            int bg0 = __ldg(&batch[s0]);
            float4 w = vn[(size_t)bg0 * 64 + q];
            v.x += w.x; v.y += w.y; v.z += w.z; v.w += w.w;
        }
        ax += fmaxf(v.x + b.x, 0.f) + MSG_EPS;
        ay += fmaxf(v.y + b.y, 0.f) + MSG_EPS;
        az += fmaxf(v.z + b.z, 0.f) + MSG_EPS;
        aw += fmaxf(v.w + b.w, 0.f) + MSG_EPS;
    }
    agg[(size_t)n * 64 + q] = make_float4(ax, ay, az, aw);
}

// ---------------- tf32 helpers ----------------
__device__ __forceinline__ float tf32r(float x) {
    uint32_t u;
    asm("cvt.rna.tf32.f32 %0, %1;" : "=r"(u) : "f"(x));
    return __uint_as_float(u);
}
__device__ __forceinline__ uint32_t tf32u(float x) {
    uint32_t u;
    asm("cvt.rna.tf32.f32 %0, %1;" : "=r"(u) : "f"(x));
    return u;
}
__device__ __forceinline__ void mma_tf32(float* c, const uint32_t* a, const uint32_t* b) {
    asm volatile("mma.sync.aligned.m16n8k8.row.col.f32.tf32.tf32.f32 "
                 "{%0,%1,%2,%3}, {%4,%5,%6,%7}, {%8,%9}, {%0,%1,%2,%3};\n"
                 : "+f"(c[0]), "+f"(c[1]), "+f"(c[2]), "+f"(c[3])
                 : "r"(a[0]), "r"(a[1]), "r"(a[2]), "r"(a[3]),
                   "r"(b[0]), "r"(b[1]));
}

// ==================== fused GCN GEMM + residual + LN/ReLU + FFN ====================
// outh  = A @ W + bias (+res)                [M, 256]
// outh2 = relu(LN(outh, gam, bet))  if gam   [M, 256]
// outf[:, 0..63] = outh @ ffnW + ffnB        (outf row stride 256)
// Dynamic smem layout (78848 B):
//   [0, 66560)       h_tile float[64][260]   (FFN phase; aliases As/Bs of mainloop)
//     [0, 9216)      As[2][16][72]           (mainloop only)
//     [9216, 43008)  Bs[2][16][264]          (mainloop only)
//   [66560, 75776)   Wf[2][16][72]           (FFN W stages)
//   [75776, 78848)   ssA[64][5], ssB[64][5], smu[64], srs[64]
#define HT_STRIDE 260
#define SM_AS   0
#define SM_BS   9216
#define SM_WF   66560
#define SM_SSA  75776
#define SM_SSB  77056
#define SM_MU   78336
#define SM_RS   78592
#define SM_TOTAL 78848

__global__ __launch_bounds__(256)
void gemm_fused(const float* __restrict__ A,
                const float* __restrict__ W, const float* __restrict__ bias,
                const float* __restrict__ res,
                const float* __restrict__ gam, const float* __restrict__ bet,
                const float* __restrict__ ffnW, const float* __restrict__ ffnB,
                float* __restrict__ outh, float* __restrict__ outh2,
                float* __restrict__ outf, int M)
{
    constexpr int BM = 64, BN = 256, BK = 16, K = D;
    constexpr int NITER = K / BK;              // 16
    constexpr int MT = 2, NT = 8;              // mainloop warp tile 32x64 (WR=2, WC=4)
    extern __shared__ char smraw[];
    float* As = reinterpret_cast<float*>(smraw + SM_AS);   // [buf*16+k][72]
    float* Bs = reinterpret_cast<float*>(smraw + SM_BS);   // [buf*16+k][264]
    float* HT = reinterpret_cast<float*>(smraw);           // [64][HT_STRIDE]
    float* Wf = reinterpret_cast<float*>(smraw + SM_WF);   // [buf*16+k][72]
    float* ssA = reinterpret_cast<float*>(smraw + SM_SSA); // [64][5]
    float* ssB = reinterpret_cast<float*>(smraw + SM_SSB);
    float* smu = reinterpret_cast<float*>(smraw + SM_MU);
    float* srs = reinterpret_cast<float*>(smraw + SM_RS);
    const uint32_t smbase = (uint32_t)__cvta_generic_to_shared(smraw);

    const int tid  = threadIdx.x;
    const int lane = tid & 31;
    const int wid  = tid >> 5;
    const int wr   = wid >> 2;          // 0..1
    const int wc   = wid & 3;           // 0..3
    const int gid  = lane >> 2;
    const int tig  = lane & 3;
    const int m0   = blockIdx.x * BM;

    const int arow = tid & 63;
    const int akc  = (tid >> 6) << 2;
    const bool avalid = (m0 + arow) < M;
    const float* aptr = A + (size_t)(m0 + arow) * K + akc;

    const int bk  = tid >> 4;
    const int bnc = (tid & 15) << 4;
    const float* bptr = W + (size_t)bk * BN + bnc;

    // ---- prologue: stage 0 ----
    {
        uint32_t dst = smbase + SM_BS + (uint32_t)((bk * 264 + bnc) * 4);
#pragma unroll
        for (int j = 0; j < 4; j++)
            cp_async16(dst + j * 16, bptr + j * 4);
        cp_commit();
    }
    float4 a0 = make_float4(0.f, 0.f, 0.f, 0.f);
    if (avalid) a0 = *reinterpret_cast<const float4*>(aptr);
    As[(akc + 0) * 72 + arow] = tf32r(a0.x);
    As[(akc + 1) * 72 + arow] = tf32r(a0.y);
    As[(akc + 2) * 72 + arow] = tf32r(a0.z);
    As[(akc + 3) * 72 + arow] = tf32r(a0.w);
    cp_wait0();
    __syncthreads();

    float acc[MT][NT][4];
#pragma unroll
    for (int i = 0; i < MT; i++)
#pragma unroll
        for (int j = 0; j < NT; j++)
#pragma unroll
            for (int q = 0; q < 4; q++) acc[i][j][q] = 0.f;

    for (int k0 = 0; k0 < NITER; k0++) {
        const int cur = k0 & 1;
        float4 an = make_float4(0.f, 0.f, 0.f, 0.f);
        if (k0 + 1 < NITER) {
            const int nxt = cur ^ 1;
            uint32_t dst = smbase + SM_BS + (uint32_t)(((nxt * 16 + bk) * 264 + bnc) * 4);
            const float* bp = bptr + (size_t)(k0 + 1) * BK * BN;
#pragma unroll
            for (int j = 0; j < 4; j++)
                cp_async16(dst + j * 16, bp + j * 4);
            cp_commit();
            if (avalid) an = *reinterpret_cast<const float4*>(aptr + (k0 + 1) * BK);
        }
#pragma unroll
        for (int ks = 0; ks < 2; ks++) {
            uint32_t af[MT][4];
            uint32_t bf[NT][2];
#pragma unroll
            for (int mt = 0; mt < MT; mt++) {
                int r = wr * 32 + mt * 16 + gid;
                af[mt][0] = __float_as_uint(As[(cur * 16 + ks * 8 + tig) * 72 + r]);
                af[mt][1] = __float_as_uint(As[(cur * 16 + ks * 8 + tig) * 72 + r + 8]);
                af[mt][2] = __float_as_uint(As[(cur * 16 + ks * 8 + tig + 4) * 72 + r]);
                af[mt][3] = __float_as_uint(As[(cur * 16 + ks * 8 + tig + 4) * 72 + r + 8]);
            }
#pragma unroll
            for (int nt = 0; nt < NT; nt++) {
                int c = wc * 64 + nt * 8 + gid;
                bf[nt][0] = tf32u(Bs[(cur * 16 + ks * 8 + tig) * 264 + c]);
                bf[nt][1] = tf32u(Bs[(cur * 16 + ks * 8 + tig + 4) * 264 + c]);
            }
#pragma unroll
            for (int mt = 0; mt < MT; mt++)
#pragma unroll
                for (int nt = 0; nt < NT; nt++)
                    mma_tf32(acc[mt][nt], af[mt], bf[nt]);
        }
        if (k0 + 1 < NITER) {
            const int nxt = cur ^ 1;
            As[(nxt * 16 + akc + 0) * 72 + arow] = tf32r(an.x);
            As[(nxt * 16 + akc + 1) * 72 + arow] = tf32r(an.y);
            As[(nxt * 16 + akc + 2) * 72 + arow] = tf32r(an.z);
            As[(nxt * 16 + akc + 3) * 72 + arow] = tf32r(an.w);
            cp_wait0();
            __syncthreads();
        }
    }

    // ---- prefetch FFN W chunk 0 (region disjoint from As/Bs) ----
    {
        int kr = tid >> 4;
        int wcol = (tid & 15) << 2;
        uint32_t dst = smbase + SM_WF + (uint32_t)(((kr) * 72 + wcol) * 4);
        cp_async16(dst, ffnW + (size_t)kr * 64 + wcol);
        cp_commit();
    }

    // ---- epilogue: v = acc + bias (+res); write h global ----
#pragma unroll
    for (int mt = 0; mt < MT; mt++) {
        int r  = m0 + wr * 32 + mt * 16 + gid;
        int r2 = r + 8;
#pragma unroll
        for (int nt = 0; nt < NT; nt++) {
            int c = wc * 64 + nt * 8 + 2 * tig;
            float2 bi = *reinterpret_cast<const float2*>(&bias[c]);
            float v0 = acc[mt][nt][0] + bi.x;
            float v1 = acc[mt][nt][1] + bi.y;
            float v2 = acc[mt][nt][2] + bi.x;
            float v3 = acc[mt][nt][3] + bi.y;
            if (res) {
                if (r < M) {
                    float2 rr = *reinterpret_cast<const float2*>(&res[(size_t)r * D + c]);
                    v0 += rr.x; v1 += rr.y;
                }
                if (r2 < M) {
                    float2 rr = *reinterpret_cast<const float2*>(&res[(size_t)r2 * D + c]);
                    v2 += rr.x; v3 += rr.y;
                }
            }
            acc[mt][nt][0] = v0; acc[mt][nt][1] = v1;
            acc[mt][nt][2] = v2; acc[mt][nt][3] = v3;
            if (r < M)
                *reinterpret_cast<float2*>(&outh[(size_t)r * D + c]) = make_float2(v0, v1);
            if (r2 < M)
                *reinterpret_cast<float2*>(&outh[(size_t)r2 * D + c]) = make_float2(v2, v3);
        }
    }

    // ---- wait for all mainloop smem reads, then overwrite with h_tile (tf32) ----
    __syncthreads();
#pragma unroll
    for (int mt = 0; mt < MT; mt++) {
        int lr  = wr * 32 + mt * 16 + gid;
        int lr2 = lr + 8;
#pragma unroll
        for (int nt = 0; nt < NT; nt++) {
            int c = wc * 64 + nt * 8 + 2 * tig;
            HT[lr  * HT_STRIDE + c    ] = tf32r(acc[mt][nt][0]);
            HT[lr  * HT_STRIDE + c + 1] = tf32r(acc[mt][nt][1]);
            HT[lr2 * HT_STRIDE + c    ] = tf32r(acc[mt][nt][2]);
            HT[lr2 * HT_STRIDE + c + 1] = tf32r(acc[mt][nt][3]);
        }
    }

    // ---- LayerNorm + ReLU -> outh2 (overlaps with Wf prefetch in flight) ----
    if (gam) {
#pragma unroll
        for (int mt = 0; mt < MT; mt++) {
#pragma unroll
            for (int hh = 0; hh < 2; hh++) {
                float s = 0.f, q = 0.f;
#pragma unroll
                for (int nt = 0; nt < NT; nt++) {
                    float u0 = acc[mt][nt][2 * hh];
                    float u1 = acc[mt][nt][2 * hh + 1];
                    s += u0 + u1;
                    q += u0 * u0 + u1 * u1;
                }
                s += __shfl_xor_sync(0xffffffffu, s, 1);
                q += __shfl_xor_sync(0xffffffffu, q, 1);
                s += __shfl_xor_sync(0xffffffffu, s, 2);
                q += __shfl_xor_sync(0xffffffffu, q, 2);
                if (tig == 0) {
                    int lr = wr * 32 + mt * 16 + hh * 8 + gid;
                    ssA[lr * 5 + wc] = s;
                    ssB[lr * 5 + wc] = q;
                }
            }
        }
        __syncthreads();
        if (tid < BM) {
            float s = ssA[tid * 5 + 0] + ssA[tid * 5 + 1] + ssA[tid * 5 + 2] + ssA[tid * 5 + 3];
            float q = ssB[tid * 5 + 0] + ssB[tid * 5 + 1] + ssB[tid * 5 + 2] + ssB[tid * 5 + 3];
            float mu  = s * (1.f / D);
            float var = q * (1.f / D) - mu * mu;
            smu[tid] = mu;
            srs[tid] = rsqrtf(var + LN_EPS);
        }
        __syncthreads();
#pragma unroll
        for (int mt = 0; mt < MT; mt++) {
            int lr  = wr * 32 + mt * 16 + gid;
            int lr2 = lr + 8;
            int r   = m0 + lr;
            int r2  = m0 + lr2;
            float mu0 = smu[lr],  rs0 = srs[lr];
            float mu1 = smu[lr2], rs1 = srs[lr2];
#pragma unroll
            for (int nt = 0; nt < NT; nt++) {
                int c = wc * 64 + nt * 8 + 2 * tig;
                float2 gg = *reinterpret_cast<const float2*>(&gam[c]);
                float2 bb = *reinterpret_cast<const float2*>(&bet[c]);
                if (r < M) {
                    float y0 = (acc[mt][nt][0] - mu0) * rs0 * gg.x + bb.x;
                    float y1 = (acc[mt][nt][1] - mu0) * rs0 * gg.y + bb.y;
                    *reinterpret_cast<float2*>(&outh2[(size_t)r * D + c]) =
                        make_float2(fmaxf(y0, 0.f), fmaxf(y1, 0.f));
                }
                if (r2 < M) {
                    float y2 = (acc[mt][nt][2] - mu1) * rs1 * gg.x + bb.x;
                    float y3 = (acc[mt][nt][3] - mu1) * rs1 * gg.y + bb.y;
                    *reinterpret_cast<float2*>(&outh2[(size_t)r2 * D + c]) =
                        make_float2(fmaxf(y2, 0.f), fmaxf(y3, 0.f));
                }
            }
        }
    }

    // ---- FFN phase: outf = h_tile @ ffnW + ffnB, 64x64x256 ----
    // warps: wrf = wid>>1 (4 row tiles of 16), wcf = wid&1 (2 col tiles of 32)
    const int wrf = wid >> 1;
    const int wcf = wid & 1;
    const int fkr = tid >> 4;
    const int fwc = (tid & 15) << 2;
    cp_wait0();
    __syncthreads();          // Wf chunk 0 ready; h_tile fully written

    float fac[4][4];
#pragma unroll
    for (int i = 0; i < 4; i++)
#pragma unroll
        for (int j = 0; j < 4; j++) fac[i][j] = 0.f;

    constexpr int FCH = 16;   // 16 chunks of 16 k
    for (int ch = 0; ch < FCH; ch++) {
        const int cur = ch & 1;
        if (ch + 1 < FCH) {
            const int nxt = cur ^ 1;
            uint32_t dst = smbase + SM_WF + (uint32_t)(((nxt * 16 + fkr) * 72 + fwc) * 4);
            cp_async16(dst, ffnW + (size_t)((ch + 1) * 16 + fkr) * 64 + fwc);
            cp_commit();
        }
#pragma unroll
        for (int ks = 0; ks < 2; ks++) {
            int kb = ch * 16 + ks * 8;
            uint32_t af[4];
            {
                int r = wrf * 16 + gid;
                af[0] = __float_as_uint(HT[r * HT_STRIDE + kb + tig]);
                af[1] = __float_as_uint(HT[(r + 8) * HT_STRIDE + kb + tig]);
                af[2] = __float_as_uint(HT[r * HT_STRIDE + kb + tig + 4]);
                af[3] = __float_as_uint(HT[(r + 8) * HT_STRIDE + kb + tig + 4]);
            }
#pragma unroll
            for (int nt = 0; nt < 4; nt++) {
                int c = wcf * 32 + nt * 8 + gid;
                uint32_t bf[2];
                bf[0] = tf32u(Wf[(cur * 16 + ks * 8 + tig) * 72 + c]);
                bf[1] = tf32u(Wf[(cur * 16 + ks * 8 + tig + 4) * 72 + c]);
                mma_tf32(fac[nt], af, bf);
            }
        }
        if (ch + 1 < FCH) {
            cp_wait0();
            __syncthreads();
        }
    }

    // FFN epilogue
    {
        int r  = m0 + wrf * 16 + gid;
        int r2 = r + 8;
#pragma unroll
        for (int nt = 0; nt < 4; nt++) {
            int c = wcf * 32 + nt * 8 + 2 * tig;
            float2 bi = *reinterpret_cast<const float2*>(&ffnB[c]);
            if (r < M)
                *reinterpret_cast<float2*>(&outf[(size_t)r * 256 + c]) =
                    make_float2(fac[nt][0] + bi.x, fac[nt][1] + bi.y);
            if (r2 < M)
                *reinterpret_cast<float2*>(&outf[(size_t)r2 * 256 + c]) =
                    make_float2(fac[nt][2] + bi.x, fac[nt][3] + bi.y);
        }
    }
}

// ---------------- virtual-node path ----------------
__device__ __forceinline__ void ln_rows8(float (*t)[D], float (*s)[D],
                                         const float* __restrict__ gam,
                                         const float* __restrict__ bet,
                                         float* smu, float* srs)
{
    int lane = threadIdx.x & 31, w = threadIdx.x >> 5;
    float a = 0.f, b = 0.f;
#pragma unroll
    for (int i = 0; i < 8; i++) {
        float v = t[w][lane + 32 * i];
        a += v; b += v * v;
    }
#pragma unroll
    for (int o = 16; o; o >>= 1) {
        a += __shfl_down_sync(0xffffffffu, a, o);
        b += __shfl_down_sync(0xffffffffu, b, o);
    }
    if (lane == 0) {
        float mu = a * (1.f / D);
        float var = b * (1.f / D) - mu * mu;
        smu[w] = mu;
        srs[w] = rsqrtf(var + LN_EPS);
    }
    __syncthreads();
    int d = threadIdx.x;
    float gd = gam[d], bd = bet[d];
#pragma unroll
    for (int gg = 0; gg < 8; gg++) {
        float v = (t[gg][d] - smu[gg]) * srs[gg] * gd + bd;
        s[gg][d] = fmaxf(v, 0.f);
    }
}

__global__ void vn_mlp_kernel(const float* __restrict__ h2, const int* __restrict__ off,
                              const float* __restrict__ W1, const float* __restrict__ b1,
                              const float* __restrict__ g1, const float* __restrict__ be1,
                              const float* __restrict__ W2, const float* __restrict__ b2,
                              const float* __restrict__ g2, const float* __restrict__ be2,
                              float* __restrict__ vn)
{
    __shared__ float s[8][D];
    __shared__ float t[8][D];
    __shared__ float smu[8], srs[8];
    int d = threadIdx.x;
    int g0 = blockIdx.x * 8;

#pragma unroll
    for (int gg = 0; gg < 8; gg++) {
        int g = g0 + gg;
        float acc = vn[(size_t)g * D + d];
        int n1 = off[g + 1];
        for (int n = off[g]; n < n1; n++)
            acc += h2[(size_t)n * D + d];
        s[gg][d] = acc;
    }
    __syncthreads();

    float y[8];
#pragma unroll
    for (int gg = 0; gg < 8; gg++) y[gg] = b1[d];
    for (int k = 0; k < D; k++) {
        float w = W1[(size_t)k * D + d];
#pragma unroll
        for (int gg = 0; gg < 8; gg++) y[gg] = fmaf(s[gg][k], w, y[gg]);
    }
    __syncthreads();
#pragma unroll
    for (int gg = 0; gg < 8; gg++) t[gg][d] = y[gg];
    __syncthreads();
    ln_rows8(t, s, g1, be1, smu, srs);
    __syncthreads();

#pragma unroll
    for (int gg = 0; gg < 8; gg++) y[gg] = b2[d];
    for (int k = 0; k < D; k++) {
        float w = W2[(size_t)k * D + d];
#pragma unroll
        for (int gg = 0; gg < 8; gg++) y[gg] = fmaf(s[gg][k], w, y[gg]);
    }
    __syncthreads();
#pragma unroll
    for (int gg = 0; gg < 8; gg++) t[gg][d] = y[gg];
    __syncthreads();
    ln_rows8(t, s, g2, be2, smu, srs);
    __syncthreads();
#pragma unroll
    for (int gg = 0; gg < 8; gg++)
        vn[(size_t)(g0 + gg) * D + d] = s[gg][d];
}

// ---------------- launcher ----------------
extern "C" void kernel_launch(void* const* d_in, const int* in_sizes, int n_in,
                              void* d_out, int out_size)
{
    const int*   x          = (const int*)  d_in[0];
    const int*   edge_attr  = (const int*)  d_in[1];
    const int*   edge_index = (const int*)  d_in[2];
    const int*   batch      = (const int*)  d_in[3];
    const float* atom_emb   = (const float*)d_in[4];
    const float* bond_emb   = (const float*)d_in[5];
    const float* vn_emb     = (const float*)d_in[6];
    const float* gcn_w      = (const float*)d_in[7];
    const float* gcn_b      = (const float*)d_in[8];
    const float* norm_g     = (const float*)d_in[9];
    const float* norm_b     = (const float*)d_in[10];
    const float* ffn_w      = (const float*)d_in[11];
    const float* ffn_b      = (const float*)d_in[12];
    const float* vn_w1      = (const float*)d_in[13];
    const float* vn_b1      = (const float*)d_in[14];
    const float* vn_g1      = (const float*)d_in[15];
    const float* vn_be1     = (const float*)d_in[16];
    const float* vn_w2      = (const float*)d_in[17];
    const float* vn_b2      = (const float*)d_in[18];
    const float* vn_g2      = (const float*)d_in[19];
    const float* vn_be2     = (const float*)d_in[20];

    float* out       = (float*)d_out;                       // h_graph [N,256]
    float* out_hinit = out + (size_t)N_NODES * D;           // h_init  [N,256]

    float *ph, *ph2, *pagg, *pvn; int* poff;
    cudaGetSymbolAddress((void**)&ph,   g_h);
    cudaGetSymbolAddress((void**)&ph2,  g_h2);
    cudaGetSymbolAddress((void**)&pagg, g_agg);
    cudaGetSymbolAddress((void**)&pvn,  g_vn);
    cudaGetSymbolAddress((void**)&poff, g_off);

    static int smem_set = 0;
    if (!smem_set) {
        cudaFuncSetAttribute(gemm_fused, cudaFuncAttributeMaxDynamicSharedMemorySize, SM_TOTAL);
        smem_set = 1;
    }

    const int FUSED_GRID = (N_NODES + 63) / 64;   // 1563
    const int AGG_GRID = (N_NODES + 3) / 4;

    // ---- CSR build (edge structure reused for all 4 layers) ----
    zero_deg_kernel<<<(N_NODES + 255) / 256, 256>>>();
    hist_kernel<<<(N_EDGES + 255) / 256, 256>>>(edge_index);
    scan_block_kernel<<<NBLK, SCAN_B>>>();
    scan_sums_kernel<<<1, 128>>>();
    add_off_kernel<<<(N_NODES + 255) / 256, 256>>>();
    copy_cursor_kernel<<<(N_NODES + 255) / 256, 256>>>();
    fill_kernel<<<(N_EDGES + 255) / 256, 256>>>(edge_index, edge_attr);
    combo_kernel<<<512, 256>>>(bond_emb);

    node_init_kernel<<<N_NODES, 256>>>(x, atom_emb, vn_emb, ph, pvn, out_hinit);
    offsets_kernel<<<(NGRAPHS + 1 + 255) / 256, 256>>>(batch, poff);

    // ----- layer 0 (LN + FFN fused into GEMM) -----
    aggregate_kernel<false><<<AGG_GRID, 256>>>((const float4*)ph, nullptr, nullptr, (float4*)pagg);
    gemm_fused<<<FUSED_GRID, 256, SM_TOTAL>>>(pagg, gcn_w, gcn_b, nullptr,
                                              norm_g, norm_b, ffn_w, ffn_b,
                                              ph, ph2, out, N_NODES);

    // ----- layers 1..3 (layers 4..6 dead: only out[0..3] reach h_graph) -----
    for (int l = 1; l < 4; l++) {
        int j = l - 1;
        vn_mlp_kernel<<<NGRAPHS / 8, 256>>>(ph2, poff,
                                            vn_w1 + (size_t)j * D * D, vn_b1 + (size_t)j * D,
                                            vn_g1 + (size_t)j * D,     vn_be1 + (size_t)j * D,
                                            vn_w2 + (size_t)j * D * D, vn_b2 + (size_t)j * D,
                                            vn_g2 + (size_t)j * D,     vn_be2 + (size_t)j * D,
                                            pvn);
        aggregate_kernel<true><<<AGG_GRID, 256>>>((const float4*)ph2, (const float4*)pvn,
                                                  batch, (float4*)pagg);
        const float* gl = (l < 3) ? (norm_g + (size_t)l * D) : nullptr;
        const float* bl = (l < 3) ? (norm_b + (size_t)l * D) : nullptr;
        gemm_fused<<<FUSED_GRID, 256, SM_TOTAL>>>(pagg, gcn_w + (size_t)l * D * D,
                                                  gcn_b + (size_t)l * D, ph,
                                                  gl, bl,
                                                  ffn_w + (size_t)l * D * 64,
                                                  ffn_b + (size_t)l * 64,
                                                  ph, ph2, out + (size_t)l * 64, N_NODES);
    }
}

// round 10
// speedup vs baseline: 2.1263x; 1.0026x over previous
#include <cuda_runtime.h>
#include <stddef.h>
#include <stdint.h>

#define N_NODES 100000
#define N_EDGES 300000
#define NGRAPHS 3000
#define D 256
#define MSG_EPS 1e-7f
#define LN_EPS  1e-5f
#define SCAN_B 1024
#define NBLK ((N_NODES + SCAN_B - 1) / SCAN_B)   // 98

// ---------------- scratch (static device allocations; no cudaMalloc) ----------------
__device__ __align__(16) float g_h  [(size_t)N_NODES * D];
__device__ __align__(16) float g_h2 [(size_t)N_NODES * D];
__device__ __align__(16) float g_agg[(size_t)N_NODES * D];
__device__ __align__(16) float g_vn [(size_t)NGRAPHS * D];
__device__ __align__(16) float g_combo[512 * D];          // bond combo table
__device__ int g_off[NGRAPHS + 1];
__device__ int g_deg[N_NODES];
__device__ int g_noff[N_NODES + 1];
__device__ int g_cursor[N_NODES];
__device__ int g_elist[N_EDGES];
__device__ int g_bsum[NBLK];

__device__ __forceinline__ void cp_async16(uint32_t smem_dst, const void* gsrc) {
    asm volatile("cp.async.cg.shared.global [%0], [%1], 16;\n"
                 :: "r"(smem_dst), "l"(gsrc));
}
__device__ __forceinline__ void cp_commit() {
    asm volatile("cp.async.commit_group;\n" ::);
}
__device__ __forceinline__ void cp_wait0() {
    asm volatile("cp.async.wait_group 0;\n" ::: "memory");
}

// ================= CSR build (edge_index constant across layers) =================
__global__ void zero_deg_kernel() {
    int i = blockIdx.x * blockDim.x + threadIdx.x;
    if (i < N_NODES) g_deg[i] = 0;
}
__global__ void hist_kernel(const int* __restrict__ ei) {
    int e = blockIdx.x * blockDim.x + threadIdx.x;
    if (e < N_EDGES) atomicAdd(&g_deg[ei[N_EDGES + e]], 1);
}
__global__ void scan_block_kernel() {
    __shared__ int s[SCAN_B];
    int tid = threadIdx.x;
    int i = blockIdx.x * SCAN_B + tid;
    int v = (i < N_NODES) ? g_deg[i] : 0;
    s[tid] = v;
    __syncthreads();
#pragma unroll
    for (int d = 1; d < SCAN_B; d <<= 1) {
        int t = (tid >= d) ? s[tid - d] : 0;
        __syncthreads();
        s[tid] += t;
        __syncthreads();
    }
    if (i < N_NODES) g_noff[i + 1] = s[tid];
    if (tid == SCAN_B - 1) g_bsum[blockIdx.x] = s[tid];
}
__global__ void scan_sums_kernel() {
    __shared__ int s[128];
    int tid = threadIdx.x;
    int v = (tid < NBLK) ? g_bsum[tid] : 0;
    s[tid] = v;
    __syncthreads();
#pragma unroll
    for (int d = 1; d < 128; d <<= 1) {
        int t = (tid >= d) ? s[tid - d] : 0;
        __syncthreads();
        s[tid] += t;
        __syncthreads();
    }
    if (tid < NBLK) g_bsum[tid] = s[tid] - v;   // exclusive
    if (tid == 0) g_noff[0] = 0;
}
__global__ void add_off_kernel() {       // also seeds cursor (cursor[i] = noff[i])
    int i = blockIdx.x * blockDim.x + threadIdx.x;
    if (i < N_NODES) {
        int v = g_noff[i + 1] + g_bsum[i / SCAN_B];
        g_noff[i + 1] = v;
        if (i + 1 < N_NODES) g_cursor[i + 1] = v;
        if (i == 0) g_cursor[0] = 0;
    }
}
__global__ void fill_kernel(const int* __restrict__ ei, const int* __restrict__ ea) {
    int e = blockIdx.x * blockDim.x + threadIdx.x;
    if (e >= N_EDGES) return;
    int src = ei[e];
    int dst = ei[N_EDGES + e];
    int combo = ea[3 * e + 0] | (ea[3 * e + 1] << 3) | (ea[3 * e + 2] << 6);
    int pos = atomicAdd(&g_cursor[dst], 1);
    g_elist[pos] = src | (combo << 17);
}
__global__ void combo_kernel(const float* __restrict__ bond) {
    int c = blockIdx.x;        // 0..511
    int d = threadIdx.x;
    int a0 = c & 7, a1 = (c >> 3) & 7, a2 = (c >> 6) & 7;
    g_combo[c * D + d] = bond[(size_t)(0 * 8 + a0) * D + d]
                       + bond[(size_t)(1 * 8 + a1) * D + d]
                       + bond[(size_t)(2 * 8 + a2) * D + d];
}

// ---------------- node init (4 nodes/block, float4) ----------------
__global__ void node_init_kernel(const int* __restrict__ x,
                                 const float4* __restrict__ atom_emb,
                                 const float4* __restrict__ vn_emb,
                                 float4* __restrict__ h,
                                 float4* __restrict__ vn,
                                 float4* __restrict__ out_hinit)
{
    int n = blockIdx.x * 4 + (threadIdx.x >> 6);
    if (n >= N_NODES) return;
    int q = threadIdx.x & 63;
    float4 s = make_float4(0.f, 0.f, 0.f, 0.f);
#pragma unroll
    for (int f = 0; f < 9; f++) {
        int xi = __ldg(&x[n * 9 + f]);
        float4 v = atom_emb[((size_t)f * 64 + xi) * 64 + q];
        s.x += v.x; s.y += v.y; s.z += v.z; s.w += v.w;
    }
    size_t idx = (size_t)n * 64 + q;
    out_hinit[idx] = s;
    float4 vv = vn_emb[q];
    h[idx] = make_float4(s.x + vv.x, s.y + vv.y, s.z + vv.z, s.w + vv.w);
    if (n < NGRAPHS) vn[(size_t)n * 64 + q] = vv;
}

// ---------------- graph segment offsets ----------------
__global__ void offsets_kernel(const int* __restrict__ batch, int* __restrict__ off)
{
    int g = blockIdx.x * blockDim.x + threadIdx.x;
    if (g > NGRAPHS) return;
    int lo = 0, hi = N_NODES;
    while (lo < hi) {
        int mid = (lo + hi) >> 1;
        if (batch[mid] < g) lo = mid + 1; else hi = mid;
    }
    off[g] = lo;
}

// ---------------- CSR gather aggregation ----------------
template<bool WITHVN>
__global__ void aggregate_kernel(const float4* __restrict__ hin,
                                 const float4* __restrict__ vn,
                                 const int* __restrict__ batch,
                                 float4* __restrict__ agg)
{
    int n = blockIdx.x * 4 + (threadIdx.x >> 6);
    if (n >= N_NODES) return;
    int q = threadIdx.x & 63;
    const float4* combo4 = reinterpret_cast<const float4*>(g_combo);
    int i0 = g_noff[n], i1 = g_noff[n + 1];
    float4 self = hin[(size_t)n * 64 + q];
    float ax = self.x, ay = self.y, az = self.z, aw = self.w;
    if (WITHVN) {
        int bg = __ldg(&batch[n]);
        float4 vv = vn[(size_t)bg * 64 + q];
        ax += vv.x; ay += vv.y; az += vv.z; aw += vv.w;
    }
    int i = i0;
    for (; i + 1 < i1; i += 2) {
        int ed0 = __ldg(&g_elist[i]);
        int ed1 = __ldg(&g_elist[i + 1]);
        int s0 = ed0 & 0x1FFFF, c0 = ed0 >> 17;
        int s1 = ed1 & 0x1FFFF, c1 = ed1 >> 17;
        float4 v0 = hin[(size_t)s0 * 64 + q];
        float4 v1 = hin[(size_t)s1 * 64 + q];
        float4 b0 = combo4[(size_t)c0 * 64 + q];
        float4 b1 = combo4[(size_t)c1 * 64 + q];
        if (WITHVN) {
            int bg0 = __ldg(&batch[s0]);
            int bg1 = __ldg(&batch[s1]);
            float4 w0 = vn[(size_t)bg0 * 64 + q];
            float4 w1 = vn[(size_t)bg1 * 64 + q];
            v0.x += w0.x; v0.y += w0.y; v0.z += w0.z; v0.w += w0.w;
            v1.x += w1.x; v1.y += w1.y; v1.z += w1.z; v1.w += w1.w;
        }
        ax += fmaxf(v0.x + b0.x, 0.f) + MSG_EPS + fmaxf(v1.x + b1.x, 0.f) + MSG_EPS;
        ay += fmaxf(v0.y + b0.y, 0.f) + MSG_EPS + fmaxf(v1.y + b1.y, 0.f) + MSG_EPS;
        az += fmaxf(v0.z + b0.z, 0.f) + MSG_EPS + fmaxf(v1.z + b1.z, 0.f) + MSG_EPS;
        aw += fmaxf(v0.w + b0.w, 0.f) + MSG_EPS + fmaxf(v1.w + b1.w, 0.f) + MSG_EPS;
    }
    if (i < i1) {
        int ed = __ldg(&g_elist[i]);
        int s0 = ed & 0x1FFFF, c0 = ed >> 17;
        float4 v = hin[(size_t)s0 * 64 + q];
        float4 b = combo4[(size_t)c0 * 64 + q];
        if (WITHVN) {
            int bg0 = __ldg(&batch[s0]);
            float4 w = vn[(size_t)bg0 * 64 + q];
            v.x += w.x; v.y += w.y; v.z += w.z; v.w += w.w;
        }
        ax += fmaxf(v.x + b.x, 0.f) + MSG_EPS;
        ay += fmaxf(v.y + b.y, 0.f) + MSG_EPS;
        az += fmaxf(v.z + b.z, 0.f) + MSG_EPS;
        aw += fmaxf(v.w + b.w, 0.f) + MSG_EPS;
    }
    agg[(size_t)n * 64 + q] = make_float4(ax, ay, az, aw);
}

// ---------------- tf32 helpers ----------------
__device__ __forceinline__ float tf32r(float x) {
    uint32_t u;
    asm("cvt.rna.tf32.f32 %0, %1;" : "=r"(u) : "f"(x));
    return __uint_as_float(u);
}
__device__ __forceinline__ uint32_t tf32u(float x) {
    uint32_t u;
    asm("cvt.rna.tf32.f32 %0, %1;" : "=r"(u) : "f"(x));
    return u;
}
__device__ __forceinline__ void mma_tf32(float* c, const uint32_t* a, const uint32_t* b) {
    asm volatile("mma.sync.aligned.m16n8k8.row.col.f32.tf32.tf32.f32 "
                 "{%0,%1,%2,%3}, {%4,%5,%6,%7}, {%8,%9}, {%0,%1,%2,%3};\n"
                 : "+f"(c[0]), "+f"(c[1]), "+f"(c[2]), "+f"(c[3])
                 : "r"(a[0]), "r"(a[1]), "r"(a[2]), "r"(a[3]),
                   "r"(b[0]), "r"(b[1]));
}

// ==================== fused GCN GEMM + residual + LN/ReLU + FFN ====================
// BM=128, BN=256: warp tile 64x64 (MT=4, NT=8) — fragment reuse 1.0 word/MMA vs 1.5.
// Dynamic smem (148480 B):
//   [0, 133120)       HT float[128][260]  (FFN phase; aliases As/Bs of mainloop)
//     [0, 17408)      As[2][16][136]
//     [17408, 51200)  Bs[2][16][264]
//   [133120, 142336)  Wf[2][16][72]
//   [142336, 148480)  ssA[128][5], ssB[128][5], smu[128], srs[128]
#define AS_STRIDE 136
#define BS_STRIDE 264
#define HT_STRIDE 260
#define SM_AS    0
#define SM_BS    17408
#define SM_WF    133120
#define SM_SSA   142336
#define SM_SSB   144896
#define SM_MU    147456
#define SM_RS    147968
#define SM_TOTAL 148480

__global__ __launch_bounds__(256, 1)
void gemm_fused(const float* __restrict__ A,
                const float* __restrict__ W, const float* __restrict__ bias,
                const float* __restrict__ res,
                const float* __restrict__ gam, const float* __restrict__ bet,
                const float* __restrict__ ffnW, const float* __restrict__ ffnB,
                float* __restrict__ outh, float* __restrict__ outh2,
                float* __restrict__ outf, int M)
{
    constexpr int BM = 128, BN = 256, BK = 16, K = D;
    constexpr int NITER = K / BK;              // 16
    constexpr int MT = 4, NT = 8;              // warp tile 64x64 (WR=2, WC=4)
    extern __shared__ char smraw[];
    float* As = reinterpret_cast<float*>(smraw + SM_AS);
    float* Bs = reinterpret_cast<float*>(smraw + SM_BS);
    float* HT = reinterpret_cast<float*>(smraw);
    float* Wf = reinterpret_cast<float*>(smraw + SM_WF);
    float* ssA = reinterpret_cast<float*>(smraw + SM_SSA);
    float* ssB = reinterpret_cast<float*>(smraw + SM_SSB);
    float* smu = reinterpret_cast<float*>(smraw + SM_MU);
    float* srs = reinterpret_cast<float*>(smraw + SM_RS);
    const uint32_t smbase = (uint32_t)__cvta_generic_to_shared(smraw);

    const int tid  = threadIdx.x;
    const int lane = tid & 31;
    const int wid  = tid >> 5;
    const int wr   = wid >> 2;          // 0..1 (64 rows each)
    const int wc   = wid & 3;           // 0..3 (64 cols each)
    const int gid  = lane >> 2;
    const int tig  = lane & 3;
    const int m0   = blockIdx.x * BM;

    // A staging: row = tid&127, 8 consecutive k at (tid>>7)*8
    const int arow = tid & 127;
    const int akc  = (tid >> 7) << 3;
    const bool avalid = (m0 + arow) < M;
    const float* aptr = A + (size_t)(m0 + arow) * K + akc;

    // B staging via cp.async: 16 floats/thread/stage
    const int bk  = tid >> 4;
    const int bnc = (tid & 15) << 4;
    const float* bptr = W + (size_t)bk * BN + bnc;

    // ---- prologue: stage 0 ----
    {
        uint32_t dst = smbase + SM_BS + (uint32_t)((bk * BS_STRIDE + bnc) * 4);
#pragma unroll
        for (int j = 0; j < 4; j++)
            cp_async16(dst + j * 16, bptr + j * 4);
        cp_commit();
    }
    {
        float4 a0 = make_float4(0.f, 0.f, 0.f, 0.f);
        float4 a1 = a0;
        if (avalid) {
            a0 = *reinterpret_cast<const float4*>(aptr);
            a1 = *reinterpret_cast<const float4*>(aptr + 4);
        }
        As[(akc + 0) * AS_STRIDE + arow] = tf32r(a0.x);
        As[(akc + 1) * AS_STRIDE + arow] = tf32r(a0.y);
        As[(akc + 2) * AS_STRIDE + arow] = tf32r(a0.z);
        As[(akc + 3) * AS_STRIDE + arow] = tf32r(a0.w);
        As[(akc + 4) * AS_STRIDE + arow] = tf32r(a1.x);
        As[(akc + 5) * AS_STRIDE + arow] = tf32r(a1.y);
        As[(akc + 6) * AS_STRIDE + arow] = tf32r(a1.z);
        As[(akc + 7) * AS_STRIDE + arow] = tf32r(a1.w);
    }
    cp_wait0();
    __syncthreads();

    float acc[MT][NT][4];
#pragma unroll
    for (int i = 0; i < MT; i++)
#pragma unroll
        for (int j = 0; j < NT; j++)
#pragma unroll
            for (int q = 0; q < 4; q++) acc[i][j][q] = 0.f;

    for (int k0 = 0; k0 < NITER; k0++) {
        const int cur = k0 & 1;
        float4 an0 = make_float4(0.f, 0.f, 0.f, 0.f);
        float4 an1 = an0;
        if (k0 + 1 < NITER) {
            const int nxt = cur ^ 1;
            uint32_t dst = smbase + SM_BS + (uint32_t)(((nxt * 16 + bk) * BS_STRIDE + bnc) * 4);
            const float* bp = bptr + (size_t)(k0 + 1) * BK * BN;
#pragma unroll
            for (int j = 0; j < 4; j++)
                cp_async16(dst + j * 16, bp + j * 4);
            cp_commit();
            if (avalid) {
                an0 = *reinterpret_cast<const float4*>(aptr + (k0 + 1) * BK);
                an1 = *reinterpret_cast<const float4*>(aptr + (k0 + 1) * BK + 4);
            }
        }
#pragma unroll
        for (int ks = 0; ks < 2; ks++) {
            uint32_t af[MT][4];
            uint32_t bf[NT][2];
#pragma unroll
            for (int mt = 0; mt < MT; mt++) {
                int r = wr * 64 + mt * 16 + gid;
                af[mt][0] = __float_as_uint(As[(cur * 16 + ks * 8 + tig) * AS_STRIDE + r]);
                af[mt][1] = __float_as_uint(As[(cur * 16 + ks * 8 + tig) * AS_STRIDE + r + 8]);
                af[mt][2] = __float_as_uint(As[(cur * 16 + ks * 8 + tig + 4) * AS_STRIDE + r]);
                af[mt][3] = __float_as_uint(As[(cur * 16 + ks * 8 + tig + 4) * AS_STRIDE + r + 8]);
            }
#pragma unroll
            for (int nt = 0; nt < NT; nt++) {
                int c = wc * 64 + nt * 8 + gid;
                bf[nt][0] = tf32u(Bs[(cur * 16 + ks * 8 + tig) * BS_STRIDE + c]);
                bf[nt][1] = tf32u(Bs[(cur * 16 + ks * 8 + tig + 4) * BS_STRIDE + c]);
            }
#pragma unroll
            for (int mt = 0; mt < MT; mt++)
#pragma unroll
                for (int nt = 0; nt < NT; nt++)
                    mma_tf32(acc[mt][nt], af[mt], bf[nt]);
        }
        if (k0 + 1 < NITER) {
            const int nxt = cur ^ 1;
            As[(nxt * 16 + akc + 0) * AS_STRIDE + arow] = tf32r(an0.x);
            As[(nxt * 16 + akc + 1) * AS_STRIDE + arow] = tf32r(an0.y);
            As[(nxt * 16 + akc + 2) * AS_STRIDE + arow] = tf32r(an0.z);
            As[(nxt * 16 + akc + 3) * AS_STRIDE + arow] = tf32r(an0.w);
            As[(nxt * 16 + akc + 4) * AS_STRIDE + arow] = tf32r(an1.x);
            As[(nxt * 16 + akc + 5) * AS_STRIDE + arow] = tf32r(an1.y);
            As[(nxt * 16 + akc + 6) * AS_STRIDE + arow] = tf32r(an1.z);
            As[(nxt * 16 + akc + 7) * AS_STRIDE + arow] = tf32r(an1.w);
            cp_wait0();
            __syncthreads();
        }
    }

    // ---- prefetch FFN W chunk 0 (disjoint from As/Bs/HT mainloop region) ----
    {
        int kr = tid >> 4;
        int wcol = (tid & 15) << 2;
        uint32_t dst = smbase + SM_WF + (uint32_t)((kr * 72 + wcol) * 4);
        cp_async16(dst, ffnW + (size_t)kr * 64 + wcol);
        cp_commit();
    }

    // ---- epilogue: v = acc + bias (+res); write h ----
#pragma unroll
    for (int mt = 0; mt < MT; mt++) {
        int r  = m0 + wr * 64 + mt * 16 + gid;
        int r2 = r + 8;
#pragma unroll
        for (int nt = 0; nt < NT; nt++) {
            int c = wc * 64 + nt * 8 + 2 * tig;
            float2 bi = *reinterpret_cast<const float2*>(&bias[c]);
            float v0 = acc[mt][nt][0] + bi.x;
            float v1 = acc[mt][nt][1] + bi.y;
            float v2 = acc[mt][nt][2] + bi.x;
            float v3 = acc[mt][nt][3] + bi.y;
            if (res) {
                if (r < M) {
                    float2 rr = *reinterpret_cast<const float2*>(&res[(size_t)r * D + c]);
                    v0 += rr.x; v1 += rr.y;
                }
                if (r2 < M) {
                    float2 rr = *reinterpret_cast<const float2*>(&res[(size_t)r2 * D + c]);
                    v2 += rr.x; v3 += rr.y;
                }
            }
            acc[mt][nt][0] = v0; acc[mt][nt][1] = v1;
            acc[mt][nt][2] = v2; acc[mt][nt][3] = v3;
            if (r < M)
                *reinterpret_cast<float2*>(&outh[(size_t)r * D + c]) = make_float2(v0, v1);
            if (r2 < M)
                *reinterpret_cast<float2*>(&outh[(size_t)r2 * D + c]) = make_float2(v2, v3);
        }
    }

    // ---- all mainloop smem reads done -> overwrite with h_tile (tf32) ----
    __syncthreads();
#pragma unroll
    for (int mt = 0; mt < MT; mt++) {
        int lr  = wr * 64 + mt * 16 + gid;
        int lr2 = lr + 8;
#pragma unroll
        for (int nt = 0; nt < NT; nt++) {
            int c = wc * 64 + nt * 8 + 2 * tig;
            HT[lr  * HT_STRIDE + c    ] = tf32r(acc[mt][nt][0]);
            HT[lr  * HT_STRIDE + c + 1] = tf32r(acc[mt][nt][1]);
            HT[lr2 * HT_STRIDE + c    ] = tf32r(acc[mt][nt][2]);
            HT[lr2 * HT_STRIDE + c + 1] = tf32r(acc[mt][nt][3]);
        }
    }

    // ---- LayerNorm + ReLU -> outh2 ----
    if (gam) {
#pragma unroll
        for (int mt = 0; mt < MT; mt++) {
#pragma unroll
            for (int hh = 0; hh < 2; hh++) {
                float s = 0.f, q = 0.f;
#pragma unroll
                for (int nt = 0; nt < NT; nt++) {
                    float u0 = acc[mt][nt][2 * hh];
                    float u1 = acc[mt][nt][2 * hh + 1];
                    s += u0 + u1;
                    q += u0 * u0 + u1 * u1;
                }
                s += __shfl_xor_sync(0xffffffffu, s, 1);
                q += __shfl_xor_sync(0xffffffffu, q, 1);
                s += __shfl_xor_sync(0xffffffffu, s, 2);
                q += __shfl_xor_sync(0xffffffffu, q, 2);
                if (tig == 0) {
                    int lr = wr * 64 + mt * 16 + hh * 8 + gid;
                    ssA[lr * 5 + wc] = s;
                    ssB[lr * 5 + wc] = q;
                }
            }
        }
        __syncthreads();
        if (tid < BM) {
            float s = ssA[tid * 5 + 0] + ssA[tid * 5 + 1] + ssA[tid * 5 + 2] + ssA[tid * 5 + 3];
            float q = ssB[tid * 5 + 0] + ssB[tid * 5 + 1] + ssB[tid * 5 + 2] + ssB[tid * 5 + 3];
            float mu  = s * (1.f / D);
            float var = q * (1.f / D) - mu * mu;
            smu[tid] = mu;
            srs[tid] = rsqrtf(var + LN_EPS);
        }
        __syncthreads();
#pragma unroll
        for (int mt = 0; mt < MT; mt++) {
            int lr  = wr * 64 + mt * 16 + gid;
            int lr2 = lr + 8;
            int r   = m0 + lr;
            int r2  = m0 + lr2;
            float mu0 = smu[lr],  rs0 = srs[lr];
            float mu1 = smu[lr2], rs1 = srs[lr2];
#pragma unroll
            for (int nt = 0; nt < NT; nt++) {
                int c = wc * 64 + nt * 8 + 2 * tig;
                float2 gg = *reinterpret_cast<const float2*>(&gam[c]);
                float2 bb = *reinterpret_cast<const float2*>(&bet[c]);
                if (r < M) {
                    float y0 = (acc[mt][nt][0] - mu0) * rs0 * gg.x + bb.x;
                    float y1 = (acc[mt][nt][1] - mu0) * rs0 * gg.y + bb.y;
                    *reinterpret_cast<float2*>(&outh2[(size_t)r * D + c]) =
                        make_float2(fmaxf(y0, 0.f), fmaxf(y1, 0.f));
                }
                if (r2 < M) {
                    float y2 = (acc[mt][nt][2] - mu1) * rs1 * gg.x + bb.x;
                    float y3 = (acc[mt][nt][3] - mu1) * rs1 * gg.y + bb.y;
                    *reinterpret_cast<float2*>(&outh2[(size_t)r2 * D + c]) =
                        make_float2(fmaxf(y2, 0.f), fmaxf(y3, 0.f));
                }
            }
        }
    }

    // ---- FFN phase: outf = h_tile @ ffnW + ffnB, 128x64x256 ----
    // warps: wrf = wid>>1 (4 row groups of 32), wcf = wid&1 (2 col groups of 32)
    const int wrf = wid >> 1;
    const int wcf = wid & 1;
    const int fkr = tid >> 4;
    const int fwc = (tid & 15) << 2;
    cp_wait0();
    __syncthreads();          // Wf chunk 0 ready; h_tile fully written

    float fac[2][4][4];
#pragma unroll
    for (int m = 0; m < 2; m++)
#pragma unroll
        for (int i = 0; i < 4; i++)
#pragma unroll
            for (int j = 0; j < 4; j++) fac[m][i][j] = 0.f;

    constexpr int FCH = 16;   // 16 chunks of 16 k
    for (int ch = 0; ch < FCH; ch++) {
        const int cur = ch & 1;
        if (ch + 1 < FCH) {
            const int nxt = cur ^ 1;
            uint32_t dst = smbase + SM_WF + (uint32_t)(((nxt * 16 + fkr) * 72 + fwc) * 4);
            cp_async16(dst, ffnW + (size_t)((ch + 1) * 16 + fkr) * 64 + fwc);
            cp_commit();
        }
#pragma unroll
        for (int ks = 0; ks < 2; ks++) {
            int kb = ch * 16 + ks * 8;
            uint32_t bf[4][2];
#pragma unroll
            for (int nt = 0; nt < 4; nt++) {
                int c = wcf * 32 + nt * 8 + gid;
                bf[nt][0] = tf32u(Wf[(cur * 16 + ks * 8 + tig) * 72 + c]);
                bf[nt][1] = tf32u(Wf[(cur * 16 + ks * 8 + tig + 4) * 72 + c]);
            }
#pragma unroll
            for (int mtf = 0; mtf < 2; mtf++) {
                int r = wrf * 32 + mtf * 16 + gid;
                uint32_t af[4];
                af[0] = __float_as_uint(HT[r * HT_STRIDE + kb + tig]);
                af[1] = __float_as_uint(HT[(r + 8) * HT_STRIDE + kb + tig]);
                af[2] = __float_as_uint(HT[r * HT_STRIDE + kb + tig + 4]);
                af[3] = __float_as_uint(HT[(r + 8) * HT_STRIDE + kb + tig + 4]);
#pragma unroll
                for (int nt = 0; nt < 4; nt++)
                    mma_tf32(fac[mtf][nt], af, bf[nt]);
            }
        }
        if (ch + 1 < FCH) {
            cp_wait0();
            __syncthreads();
        }
    }

    // FFN epilogue
#pragma unroll
    for (int mtf = 0; mtf < 2; mtf++) {
        int r  = m0 + wrf * 32 + mtf * 16 + gid;
        int r2 = r + 8;
#pragma unroll
        for (int nt = 0; nt < 4; nt++) {
            int c = wcf * 32 + nt * 8 + 2 * tig;
            float2 bi = *reinterpret_cast<const float2*>(&ffnB[c]);
            if (r < M)
                *reinterpret_cast<float2*>(&outf[(size_t)r * 256 + c]) =
                    make_float2(fac[mtf][nt][0] + bi.x, fac[mtf][nt][1] + bi.y);
            if (r2 < M)
                *reinterpret_cast<float2*>(&outf[(size_t)r2 * 256 + c]) =
                    make_float2(fac[mtf][nt][2] + bi.x, fac[mtf][nt][3] + bi.y);
        }
    }
}

// ---------------- virtual-node path ----------------
__device__ __forceinline__ void ln_rows8(float (*t)[D], float (*s)[D],
                                         const float* __restrict__ gam,
                                         const float* __restrict__ bet,
                                         float* smu, float* srs)
{
    int lane = threadIdx.x & 31, w = threadIdx.x >> 5;
    float a = 0.f, b = 0.f;
#pragma unroll
    for (int i = 0; i < 8; i++) {
        float v = t[w][lane + 32 * i];
        a += v; b += v * v;
    }
#pragma unroll
    for (int o = 16; o; o >>= 1) {
        a += __shfl_down_sync(0xffffffffu, a, o);
        b += __shfl_down_sync(0xffffffffu, b, o);
    }
    if (lane == 0) {
        float mu = a * (1.f / D);
        float var = b * (1.f / D) - mu * mu;
        smu[w] = mu;
        srs[w] = rsqrtf(var + LN_EPS);
    }
    __syncthreads();
    int d = threadIdx.x;
    float gd = gam[d], bd = bet[d];
#pragma unroll
    for (int gg = 0; gg < 8; gg++) {
        float v = (t[gg][d] - smu[gg]) * srs[gg] * gd + bd;
        s[gg][d] = fmaxf(v, 0.f);
    }
}

__global__ void vn_mlp_kernel(const float* __restrict__ h2, const int* __restrict__ off,
                              const float* __restrict__ W1, const float* __restrict__ b1,
                              const float* __restrict__ g1, const float* __restrict__ be1,
                              const float* __restrict__ W2, const float* __restrict__ b2,
                              const float* __restrict__ g2, const float* __restrict__ be2,
                              float* __restrict__ vn)
{
    __shared__ float s[8][D];
    __shared__ float t[8][D];
    __shared__ float smu[8], srs[8];
    int d = threadIdx.x;
    int g0 = blockIdx.x * 8;

#pragma unroll
    for (int gg = 0; gg < 8; gg++) {
        int g = g0 + gg;
        float acc = vn[(size_t)g * D + d];
        int n1 = off[g + 1];
        for (int n = off[g]; n < n1; n++)
            acc += h2[(size_t)n * D + d];
        s[gg][d] = acc;
    }
    __syncthreads();

    float y[8];
#pragma unroll
    for (int gg = 0; gg < 8; gg++) y[gg] = b1[d];
    for (int k = 0; k < D; k++) {
        float w = W1[(size_t)k * D + d];
#pragma unroll
        for (int gg = 0; gg < 8; gg++) y[gg] = fmaf(s[gg][k], w, y[gg]);
    }
    __syncthreads();
#pragma unroll
    for (int gg = 0; gg < 8; gg++) t[gg][d] = y[gg];
    __syncthreads();
    ln_rows8(t, s, g1, be1, smu, srs);
    __syncthreads();

#pragma unroll
    for (int gg = 0; gg < 8; gg++) y[gg] = b2[d];
    for (int k = 0; k < D; k++) {
        float w = W2[(size_t)k * D + d];
#pragma unroll
        for (int gg = 0; gg < 8; gg++) y[gg] = fmaf(s[gg][k], w, y[gg]);
    }
    __syncthreads();
#pragma unroll
    for (int gg = 0; gg < 8; gg++) t[gg][d] = y[gg];
    __syncthreads();
    ln_rows8(t, s, g2, be2, smu, srs);
    __syncthreads();
#pragma unroll
    for (int gg = 0; gg < 8; gg++)
        vn[(size_t)(g0 + gg) * D + d] = s[gg][d];
}

// ---------------- launcher ----------------
extern "C" void kernel_launch(void* const* d_in, const int* in_sizes, int n_in,
                              void* d_out, int out_size)
{
    const int*   x          = (const int*)  d_in[0];
    const int*   edge_attr  = (const int*)  d_in[1];
    const int*   edge_index = (const int*)  d_in[2];
    const int*   batch      = (const int*)  d_in[3];
    const float* atom_emb   = (const float*)d_in[4];
    const float* bond_emb   = (const float*)d_in[5];
    const float* vn_emb     = (const float*)d_in[6];
    const float* gcn_w      = (const float*)d_in[7];
    const float* gcn_b      = (const float*)d_in[8];
    const float* norm_g     = (const float*)d_in[9];
    const float* norm_b     = (const float*)d_in[10];
    const float* ffn_w      = (const float*)d_in[11];
    const float* ffn_b      = (const float*)d_in[12];
    const float* vn_w1      = (const float*)d_in[13];
    const float* vn_b1      = (const float*)d_in[14];
    const float* vn_g1      = (const float*)d_in[15];
    const float* vn_be1     = (const float*)d_in[16];
    const float* vn_w2      = (const float*)d_in[17];
    const float* vn_b2      = (const float*)d_in[18];
    const float* vn_g2      = (const float*)d_in[19];
    const float* vn_be2     = (const float*)d_in[20];

    float* out       = (float*)d_out;                       // h_graph [N,256]
    float* out_hinit = out + (size_t)N_NODES * D;           // h_init  [N,256]

    float *ph, *ph2, *pagg, *pvn; int* poff;
    cudaGetSymbolAddress((void**)&ph,   g_h);
    cudaGetSymbolAddress((void**)&ph2,  g_h2);
    cudaGetSymbolAddress((void**)&pagg, g_agg);
    cudaGetSymbolAddress((void**)&pvn,  g_vn);
    cudaGetSymbolAddress((void**)&poff, g_off);

    static int smem_set = 0;
    if (!smem_set) {
        cudaFuncSetAttribute(gemm_fused, cudaFuncAttributeMaxDynamicSharedMemorySize, SM_TOTAL);
        smem_set = 1;
    }

    const int FUSED_GRID = (N_NODES + 127) / 128;   // 782
    const int AGG_GRID = (N_NODES + 3) / 4;

    // ---- CSR build (edge structure reused for all 4 layers) ----
    zero_deg_kernel<<<(N_NODES + 255) / 256, 256>>>();
    hist_kernel<<<(N_EDGES + 255) / 256, 256>>>(edge_index);
    scan_block_kernel<<<NBLK, SCAN_B>>>();
    scan_sums_kernel<<<1, 128>>>();
    add_off_kernel<<<(N_NODES + 255) / 256, 256>>>();
    fill_kernel<<<(N_EDGES + 255) / 256, 256>>>(edge_index, edge_attr);
    combo_kernel<<<512, 256>>>(bond_emb);

    node_init_kernel<<<N_NODES / 4, 256>>>(x, (const float4*)atom_emb, (const float4*)vn_emb,
                                           (float4*)ph, (float4*)pvn, (float4*)out_hinit);
    offsets_kernel<<<(NGRAPHS + 1 + 255) / 256, 256>>>(batch, poff);

    // ----- layer 0 (LN + FFN fused into GEMM) -----
    aggregate_kernel<false><<<AGG_GRID, 256>>>((const float4*)ph, nullptr, nullptr, (float4*)pagg);
    gemm_fused<<<FUSED_GRID, 256, SM_TOTAL>>>(pagg, gcn_w, gcn_b, nullptr,
                                              norm_g, norm_b, ffn_w, ffn_b,
                                              ph, ph2, out, N_NODES);

    // ----- layers 1..3 (layers 4..6 dead: only out[0..3] reach h_graph) -----
    for (int l = 1; l < 4; l++) {
        int j = l - 1;
        vn_mlp_kernel<<<NGRAPHS / 8, 256>>>(ph2, poff,
                                            vn_w1 + (size_t)j * D * D, vn_b1 + (size_t)j * D,
                                            vn_g1 + (size_t)j * D,     vn_be1 + (size_t)j * D,
                                            vn_w2 + (size_t)j * D * D, vn_b2 + (size_t)j * D,
                                            vn_g2 + (size_t)j * D,     vn_be2 + (size_t)j * D,
                                            pvn);
        aggregate_kernel<true><<<AGG_GRID, 256>>>((const float4*)ph2, (const float4*)pvn,
                                                  batch, (float4*)pagg);
        const float* gl = (l < 3) ? (norm_g + (size_t)l * D) : nullptr;
        const float* bl = (l < 3) ? (norm_b + (size_t)l * D) : nullptr;
        gemm_fused<<<FUSED_GRID, 256, SM_TOTAL>>>(pagg, gcn_w + (size_t)l * D * D,
                                                  gcn_b + (size_t)l * D, ph,
                                                  gl, bl,
                                                  ffn_w + (size_t)l * D * 64,
                                                  ffn_b + (size_t)l * 64,
                                                  ph, ph2, out + (size_t)l * 64, N_NODES);
    }
}

// round 11
// speedup vs baseline: 2.1451x; 1.0088x over previous
#include <cuda_runtime.h>
#include <stddef.h>
#include <stdint.h>

#define N_NODES 100000
#define N_EDGES 300000
#define NGRAPHS 3000
#define D 256
#define MSG_EPS 1e-7f
#define LN_EPS  1e-5f
#define SCAN_B 1024
#define NBLK ((N_NODES + SCAN_B - 1) / SCAN_B)   // 98

// ---------------- scratch (static device allocations; no cudaMalloc) ----------------
__device__ __align__(16) float g_h  [(size_t)N_NODES * D];
__device__ __align__(16) float g_hb [(size_t)N_NODES * D];   // second h buffer (ping-pong)
__device__ __align__(16) float g_h2 [(size_t)N_NODES * D];
__device__ __align__(16) float g_agg[(size_t)N_NODES * D];
__device__ __align__(16) float g_vn [(size_t)NGRAPHS * D];
__device__ __align__(16) float g_combo[512 * D];
__device__ int g_off[NGRAPHS + 1];
__device__ int g_deg[N_NODES];
__device__ int g_noff[N_NODES + 1];
__device__ int g_cursor[N_NODES];
__device__ int g_elist[N_EDGES];
__device__ int g_bsum[NBLK];

__device__ __forceinline__ void cp_async16(uint32_t smem_dst, const void* gsrc) {
    asm volatile("cp.async.cg.shared.global [%0], [%1], 16;\n"
                 :: "r"(smem_dst), "l"(gsrc));
}
__device__ __forceinline__ void cp_commit() {
    asm volatile("cp.async.commit_group;\n" ::);
}
__device__ __forceinline__ void cp_wait0() {
    asm volatile("cp.async.wait_group 0;\n" ::: "memory");
}

// ================= CSR build =================
__global__ void zero_deg_kernel() {
    int i = blockIdx.x * blockDim.x + threadIdx.x;
    if (i < N_NODES) g_deg[i] = 0;
}
__global__ void hist_kernel(const int* __restrict__ ei) {
    int e = blockIdx.x * blockDim.x + threadIdx.x;
    if (e < N_EDGES) atomicAdd(&g_deg[ei[N_EDGES + e]], 1);
}
__global__ void scan_block_kernel() {
    __shared__ int s[SCAN_B];
    int tid = threadIdx.x;
    int i = blockIdx.x * SCAN_B + tid;
    int v = (i < N_NODES) ? g_deg[i] : 0;
    s[tid] = v;
    __syncthreads();
#pragma unroll
    for (int d = 1; d < SCAN_B; d <<= 1) {
        int t = (tid >= d) ? s[tid - d] : 0;
        __syncthreads();
        s[tid] += t;
        __syncthreads();
    }
    if (i < N_NODES) g_noff[i + 1] = s[tid];
    if (tid == SCAN_B - 1) g_bsum[blockIdx.x] = s[tid];
}
__global__ void scan_sums_kernel() {
    __shared__ int s[128];
    int tid = threadIdx.x;
    int v = (tid < NBLK) ? g_bsum[tid] : 0;
    s[tid] = v;
    __syncthreads();
#pragma unroll
    for (int d = 1; d < 128; d <<= 1) {
        int t = (tid >= d) ? s[tid - d] : 0;
        __syncthreads();
        s[tid] += t;
        __syncthreads();
    }
    if (tid < NBLK) g_bsum[tid] = s[tid] - v;
    if (tid == 0) g_noff[0] = 0;
}
__global__ void add_off_kernel() {       // also seeds cursor
    int i = blockIdx.x * blockDim.x + threadIdx.x;
    if (i < N_NODES) {
        int v = g_noff[i + 1] + g_bsum[i / SCAN_B];
        g_noff[i + 1] = v;
        if (i + 1 < N_NODES) g_cursor[i + 1] = v;
        if (i == 0) g_cursor[0] = 0;
    }
}
__global__ void fill_kernel(const int* __restrict__ ei, const int* __restrict__ ea) {
    int e = blockIdx.x * blockDim.x + threadIdx.x;
    if (e >= N_EDGES) return;
    int src = ei[e];
    int dst = ei[N_EDGES + e];
    int combo = ea[3 * e + 0] | (ea[3 * e + 1] << 3) | (ea[3 * e + 2] << 6);
    int pos = atomicAdd(&g_cursor[dst], 1);
    g_elist[pos] = src | (combo << 17);
}
__global__ void combo_kernel(const float* __restrict__ bond) {
    int c = blockIdx.x;
    int d = threadIdx.x;
    int a0 = c & 7, a1 = (c >> 3) & 7, a2 = (c >> 6) & 7;
    g_combo[c * D + d] = bond[(size_t)(0 * 8 + a0) * D + d]
                       + bond[(size_t)(1 * 8 + a1) * D + d]
                       + bond[(size_t)(2 * 8 + a2) * D + d];
}

// ---------------- node init (4 nodes/block, float4) ----------------
__global__ void node_init_kernel(const int* __restrict__ x,
                                 const float4* __restrict__ atom_emb,
                                 const float4* __restrict__ vn_emb,
                                 float4* __restrict__ h,
                                 float4* __restrict__ vn,
                                 float4* __restrict__ out_hinit)
{
    int n = blockIdx.x * 4 + (threadIdx.x >> 6);
    if (n >= N_NODES) return;
    int q = threadIdx.x & 63;
    float4 s = make_float4(0.f, 0.f, 0.f, 0.f);
#pragma unroll
    for (int f = 0; f < 9; f++) {
        int xi = __ldg(&x[n * 9 + f]);
        float4 v = atom_emb[((size_t)f * 64 + xi) * 64 + q];
        s.x += v.x; s.y += v.y; s.z += v.z; s.w += v.w;
    }
    size_t idx = (size_t)n * 64 + q;
    out_hinit[idx] = s;
    float4 vv = vn_emb[q];
    h[idx] = make_float4(s.x + vv.x, s.y + vv.y, s.z + vv.z, s.w + vv.w);
    if (n < NGRAPHS) vn[(size_t)n * 64 + q] = vv;
}

// ---------------- graph segment offsets ----------------
__global__ void offsets_kernel(const int* __restrict__ batch, int* __restrict__ off)
{
    int g = blockIdx.x * blockDim.x + threadIdx.x;
    if (g > NGRAPHS) return;
    int lo = 0, hi = N_NODES;
    while (lo < hi) {
        int mid = (lo + hi) >> 1;
        if (batch[mid] < g) lo = mid + 1; else hi = mid;
    }
    off[g] = lo;
}

// ---------------- CSR gather aggregation ----------------
template<bool WITHVN>
__global__ void aggregate_kernel(const float4* __restrict__ hin,
                                 const float4* __restrict__ vn,
                                 const int* __restrict__ batch,
                                 float4* __restrict__ agg)
{
    int n = blockIdx.x * 4 + (threadIdx.x >> 6);
    if (n >= N_NODES) return;
    int q = threadIdx.x & 63;
    const float4* combo4 = reinterpret_cast<const float4*>(g_combo);
    int i0 = g_noff[n], i1 = g_noff[n + 1];
    float4 self = hin[(size_t)n * 64 + q];
    float ax = self.x, ay = self.y, az = self.z, aw = self.w;
    if (WITHVN) {
        int bg = __ldg(&batch[n]);
        float4 vv = vn[(size_t)bg * 64 + q];
        ax += vv.x; ay += vv.y; az += vv.z; aw += vv.w;
    }
    int i = i0;
    for (; i + 1 < i1; i += 2) {
        int ed0 = __ldg(&g_elist[i]);
        int ed1 = __ldg(&g_elist[i + 1]);
        int s0 = ed0 & 0x1FFFF, c0 = ed0 >> 17;
        int s1 = ed1 & 0x1FFFF, c1 = ed1 >> 17;
        float4 v0 = hin[(size_t)s0 * 64 + q];
        float4 v1 = hin[(size_t)s1 * 64 + q];
        float4 b0 = combo4[(size_t)c0 * 64 + q];
        float4 b1 = combo4[(size_t)c1 * 64 + q];
        if (WITHVN) {
            int bg0 = __ldg(&batch[s0]);
            int bg1 = __ldg(&batch[s1]);
            float4 w0 = vn[(size_t)bg0 * 64 + q];
            float4 w1 = vn[(size_t)bg1 * 64 + q];
            v0.x += w0.x; v0.y += w0.y; v0.z += w0.z; v0.w += w0.w;
            v1.x += w1.x; v1.y += w1.y; v1.z += w1.z; v1.w += w1.w;
        }
        ax += fmaxf(v0.x + b0.x, 0.f) + MSG_EPS + fmaxf(v1.x + b1.x, 0.f) + MSG_EPS;
        ay += fmaxf(v0.y + b0.y, 0.f) + MSG_EPS + fmaxf(v1.y + b1.y, 0.f) + MSG_EPS;
        az += fmaxf(v0.z + b0.z, 0.f) + MSG_EPS + fmaxf(v1.z + b1.z, 0.f) + MSG_EPS;
        aw += fmaxf(v0.w + b0.w, 0.f) + MSG_EPS + fmaxf(v1.w + b1.w, 0.f) + MSG_EPS;
    }
    if (i < i1) {
        int ed = __ldg(&g_elist[i]);
        int s0 = ed & 0x1FFFF, c0 = ed >> 17;
        float4 v = hin[(size_t)s0 * 64 + q];
        float4 b = combo4[(size_t)c0 * 64 + q];
        if (WITHVN) {
            int bg0 = __ldg(&batch[s0]);
            float4 w = vn[(size_t)bg0 * 64 + q];
            v.x += w.x; v.y += w.y; v.z += w.z; v.w += w.w;
        }
        ax += fmaxf(v.x + b.x, 0.f) + MSG_EPS;
        ay += fmaxf(v.y + b.y, 0.f) + MSG_EPS;
        az += fmaxf(v.z + b.z, 0.f) + MSG_EPS;
        aw += fmaxf(v.w + b.w, 0.f) + MSG_EPS;
    }
    agg[(size_t)n * 64 + q] = make_float4(ax, ay, az, aw);
}

// ---------------- tf32 helpers ----------------
__device__ __forceinline__ float tf32r(float x) {
    uint32_t u;
    asm("cvt.rna.tf32.f32 %0, %1;" : "=r"(u) : "f"(x));
    return __uint_as_float(u);
}
__device__ __forceinline__ uint32_t tf32u(float x) {
    uint32_t u;
    asm("cvt.rna.tf32.f32 %0, %1;" : "=r"(u) : "f"(x));
    return u;
}
__device__ __forceinline__ void mma_tf32(float* c, const uint32_t* a, const uint32_t* b) {
    asm volatile("mma.sync.aligned.m16n8k8.row.col.f32.tf32.tf32.f32 "
                 "{%0,%1,%2,%3}, {%4,%5,%6,%7}, {%8,%9}, {%0,%1,%2,%3};\n"
                 : "+f"(c[0]), "+f"(c[1]), "+f"(c[2]), "+f"(c[3])
                 : "r"(a[0]), "r"(a[1]), "r"(a[2]), "r"(a[3]),
                   "r"(b[0]), "r"(b[1]));
}

// ==================== fused GCN GEMM + residual + LN/ReLU [+ FFN] ====================
// BM=64, BN=256; FFN phase only when ffnW != nullptr (layer 3).
#define HT_STRIDE 260
#define SM_AS   0
#define SM_BS   9216
#define SM_WF   66560
#define SM_SSA  75776
#define SM_SSB  77056
#define SM_MU   78336
#define SM_RS   78592
#define SM_TOTAL 78848

__global__ __launch_bounds__(256)
void gemm_fused(const float* __restrict__ A,
                const float* __restrict__ W, const float* __restrict__ bias,
                const float* __restrict__ res,
                const float* __restrict__ gam, const float* __restrict__ bet,
                const float* __restrict__ ffnW, const float* __restrict__ ffnB,
                float* __restrict__ outh, float* __restrict__ outh2,
                float* __restrict__ outf, int M)
{
    constexpr int BM = 64, BN = 256, BK = 16, K = D;
    constexpr int NITER = K / BK;
    constexpr int MT = 2, NT = 8;
    extern __shared__ char smraw[];
    float* As = reinterpret_cast<float*>(smraw + SM_AS);   // [buf*16+k][72]
    float* Bs = reinterpret_cast<float*>(smraw + SM_BS);   // [buf*16+k][264]
    float* HT = reinterpret_cast<float*>(smraw);           // [64][HT_STRIDE]
    float* Wf = reinterpret_cast<float*>(smraw + SM_WF);   // [buf*16+k][72]
    float* ssA = reinterpret_cast<float*>(smraw + SM_SSA);
    float* ssB = reinterpret_cast<float*>(smraw + SM_SSB);
    float* smu = reinterpret_cast<float*>(smraw + SM_MU);
    float* srs = reinterpret_cast<float*>(smraw + SM_RS);
    const uint32_t smbase = (uint32_t)__cvta_generic_to_shared(smraw);

    const int tid  = threadIdx.x;
    const int lane = tid & 31;
    const int wid  = tid >> 5;
    const int wr   = wid >> 2;
    const int wc   = wid & 3;
    const int gid  = lane >> 2;
    const int tig  = lane & 3;
    const int m0   = blockIdx.x * BM;

    const int arow = tid & 63;
    const int akc  = (tid >> 6) << 2;
    const bool avalid = (m0 + arow) < M;
    const float* aptr = A + (size_t)(m0 + arow) * K + akc;

    const int bk  = tid >> 4;
    const int bnc = (tid & 15) << 4;
    const float* bptr = W + (size_t)bk * BN + bnc;

    // ---- prologue ----
    {
        uint32_t dst = smbase + SM_BS + (uint32_t)((bk * 264 + bnc) * 4);
#pragma unroll
        for (int j = 0; j < 4; j++)
            cp_async16(dst + j * 16, bptr + j * 4);
        cp_commit();
    }
    float4 a0 = make_float4(0.f, 0.f, 0.f, 0.f);
    if (avalid) a0 = *reinterpret_cast<const float4*>(aptr);
    As[(akc + 0) * 72 + arow] = tf32r(a0.x);
    As[(akc + 1) * 72 + arow] = tf32r(a0.y);
    As[(akc + 2) * 72 + arow] = tf32r(a0.z);
    As[(akc + 3) * 72 + arow] = tf32r(a0.w);
    cp_wait0();
    __syncthreads();

    float acc[MT][NT][4];
#pragma unroll
    for (int i = 0; i < MT; i++)
#pragma unroll
        for (int j = 0; j < NT; j++)
#pragma unroll
            for (int q = 0; q < 4; q++) acc[i][j][q] = 0.f;

    for (int k0 = 0; k0 < NITER; k0++) {
        const int cur = k0 & 1;
        float4 an = make_float4(0.f, 0.f, 0.f, 0.f);
        if (k0 + 1 < NITER) {
            const int nxt = cur ^ 1;
            uint32_t dst = smbase + SM_BS + (uint32_t)(((nxt * 16 + bk) * 264 + bnc) * 4);
            const float* bp = bptr + (size_t)(k0 + 1) * BK * BN;
#pragma unroll
            for (int j = 0; j < 4; j++)
                cp_async16(dst + j * 16, bp + j * 4);
            cp_commit();
            if (avalid) an = *reinterpret_cast<const float4*>(aptr + (k0 + 1) * BK);
        }
#pragma unroll
        for (int ks = 0; ks < 2; ks++) {
            uint32_t af[MT][4];
            uint32_t bf[NT][2];
#pragma unroll
            for (int mt = 0; mt < MT; mt++) {
                int r = wr * 32 + mt * 16 + gid;
                af[mt][0] = __float_as_uint(As[(cur * 16 + ks * 8 + tig) * 72 + r]);
                af[mt][1] = __float_as_uint(As[(cur * 16 + ks * 8 + tig) * 72 + r + 8]);
                af[mt][2] = __float_as_uint(As[(cur * 16 + ks * 8 + tig + 4) * 72 + r]);
                af[mt][3] = __float_as_uint(As[(cur * 16 + ks * 8 + tig + 4) * 72 + r + 8]);
            }
#pragma unroll
            for (int nt = 0; nt < NT; nt++) {
                int c = wc * 64 + nt * 8 + gid;
                bf[nt][0] = tf32u(Bs[(cur * 16 + ks * 8 + tig) * 264 + c]);
                bf[nt][1] = tf32u(Bs[(cur * 16 + ks * 8 + tig + 4) * 264 + c]);
            }
#pragma unroll
            for (int mt = 0; mt < MT; mt++)
#pragma unroll
                for (int nt = 0; nt < NT; nt++)
                    mma_tf32(acc[mt][nt], af[mt], bf[nt]);
        }
        if (k0 + 1 < NITER) {
            const int nxt = cur ^ 1;
            As[(nxt * 16 + akc + 0) * 72 + arow] = tf32r(an.x);
            As[(nxt * 16 + akc + 1) * 72 + arow] = tf32r(an.y);
            As[(nxt * 16 + akc + 2) * 72 + arow] = tf32r(an.z);
            As[(nxt * 16 + akc + 3) * 72 + arow] = tf32r(an.w);
            cp_wait0();
            __syncthreads();
        }
    }

    if (ffnW) {   // prefetch FFN W chunk 0
        int kr = tid >> 4;
        int wcol = (tid & 15) << 2;
        uint32_t dst = smbase + SM_WF + (uint32_t)((kr * 72 + wcol) * 4);
        cp_async16(dst, ffnW + (size_t)kr * 64 + wcol);
        cp_commit();
    }

    // ---- epilogue: v = acc + bias (+res); write h ----
#pragma unroll
    for (int mt = 0; mt < MT; mt++) {
        int r  = m0 + wr * 32 + mt * 16 + gid;
        int r2 = r + 8;
#pragma unroll
        for (int nt = 0; nt < NT; nt++) {
            int c = wc * 64 + nt * 8 + 2 * tig;
            float2 bi = *reinterpret_cast<const float2*>(&bias[c]);
            float v0 = acc[mt][nt][0] + bi.x;
            float v1 = acc[mt][nt][1] + bi.y;
            float v2 = acc[mt][nt][2] + bi.x;
            float v3 = acc[mt][nt][3] + bi.y;
            if (res) {
                if (r < M) {
                    float2 rr = *reinterpret_cast<const float2*>(&res[(size_t)r * D + c]);
                    v0 += rr.x; v1 += rr.y;
                }
                if (r2 < M) {
                    float2 rr = *reinterpret_cast<const float2*>(&res[(size_t)r2 * D + c]);
                    v2 += rr.x; v3 += rr.y;
                }
            }
            acc[mt][nt][0] = v0; acc[mt][nt][1] = v1;
            acc[mt][nt][2] = v2; acc[mt][nt][3] = v3;
            if (r < M)
                *reinterpret_cast<float2*>(&outh[(size_t)r * D + c]) = make_float2(v0, v1);
            if (r2 < M)
                *reinterpret_cast<float2*>(&outh[(size_t)r2 * D + c]) = make_float2(v2, v3);
        }
    }

    if (ffnW) {   // mainloop smem reads done -> h_tile
        __syncthreads();
#pragma unroll
        for (int mt = 0; mt < MT; mt++) {
            int lr  = wr * 32 + mt * 16 + gid;
            int lr2 = lr + 8;
#pragma unroll
            for (int nt = 0; nt < NT; nt++) {
                int c = wc * 64 + nt * 8 + 2 * tig;
                HT[lr  * HT_STRIDE + c    ] = tf32r(acc[mt][nt][0]);
                HT[lr  * HT_STRIDE + c + 1] = tf32r(acc[mt][nt][1]);
                HT[lr2 * HT_STRIDE + c    ] = tf32r(acc[mt][nt][2]);
                HT[lr2 * HT_STRIDE + c + 1] = tf32r(acc[mt][nt][3]);
            }
        }
    }

    // ---- LayerNorm + ReLU -> outh2 ----
    if (gam) {
#pragma unroll
        for (int mt = 0; mt < MT; mt++) {
#pragma unroll
            for (int hh = 0; hh < 2; hh++) {
                float s = 0.f, q = 0.f;
#pragma unroll
                for (int nt = 0; nt < NT; nt++) {
                    float u0 = acc[mt][nt][2 * hh];
                    float u1 = acc[mt][nt][2 * hh + 1];
                    s += u0 + u1;
                    q += u0 * u0 + u1 * u1;
                }
                s += __shfl_xor_sync(0xffffffffu, s, 1);
                q += __shfl_xor_sync(0xffffffffu, q, 1);
                s += __shfl_xor_sync(0xffffffffu, s, 2);
                q += __shfl_xor_sync(0xffffffffu, q, 2);
                if (tig == 0) {
                    int lr = wr * 32 + mt * 16 + hh * 8 + gid;
                    ssA[lr * 5 + wc] = s;
                    ssB[lr * 5 + wc] = q;
                }
            }
        }
        __syncthreads();
        if (tid < BM) {
            float s = ssA[tid * 5 + 0] + ssA[tid * 5 + 1] + ssA[tid * 5 + 2] + ssA[tid * 5 + 3];
            float q = ssB[tid * 5 + 0] + ssB[tid * 5 + 1] + ssB[tid * 5 + 2] + ssB[tid * 5 + 3];
            float mu  = s * (1.f / D);
            float var = q * (1.f / D) - mu * mu;
            smu[tid] = mu;
            srs[tid] = rsqrtf(var + LN_EPS);
        }
        __syncthreads();
#pragma unroll
        for (int mt = 0; mt < MT; mt++) {
            int lr  = wr * 32 + mt * 16 + gid;
            int lr2 = lr + 8;
            int r   = m0 + lr;
            int r2  = m0 + lr2;
            float mu0 = smu[lr],  rs0 = srs[lr];
            float mu1 = smu[lr2], rs1 = srs[lr2];
#pragma unroll
            for (int nt = 0; nt < NT; nt++) {
                int c = wc * 64 + nt * 8 + 2 * tig;
                float2 gg = *reinterpret_cast<const float2*>(&gam[c]);
                float2 bb = *reinterpret_cast<const float2*>(&bet[c]);
                if (r < M) {
                    float y0 = (acc[mt][nt][0] - mu0) * rs0 * gg.x + bb.x;
                    float y1 = (acc[mt][nt][1] - mu0) * rs0 * gg.y + bb.y;
                    *reinterpret_cast<float2*>(&outh2[(size_t)r * D + c]) =
                        make_float2(fmaxf(y0, 0.f), fmaxf(y1, 0.f));
                }
                if (r2 < M) {
                    float y2 = (acc[mt][nt][2] - mu1) * rs1 * gg.x + bb.x;
                    float y3 = (acc[mt][nt][3] - mu1) * rs1 * gg.y + bb.y;
                    *reinterpret_cast<float2*>(&outh2[(size_t)r2 * D + c]) =
                        make_float2(fmaxf(y2, 0.f), fmaxf(y3, 0.f));
                }
            }
        }
    }

    if (!ffnW) return;

    // ---- FFN phase: outf = h_tile @ ffnW + ffnB, 64x64x256 ----
    const int wrf = wid >> 1;
    const int wcf = wid & 1;
    const int fkr = tid >> 4;
    const int fwc = (tid & 15) << 2;
    cp_wait0();
    __syncthreads();

    float fac[4][4];
#pragma unroll
    for (int i = 0; i < 4; i++)
#pragma unroll
        for (int j = 0; j < 4; j++) fac[i][j] = 0.f;

    constexpr int FCH = 16;
    for (int ch = 0; ch < FCH; ch++) {
        const int cur = ch & 1;
        if (ch + 1 < FCH) {
            const int nxt = cur ^ 1;
            uint32_t dst = smbase + SM_WF + (uint32_t)(((nxt * 16 + fkr) * 72 + fwc) * 4);
            cp_async16(dst, ffnW + (size_t)((ch + 1) * 16 + fkr) * 64 + fwc);
            cp_commit();
        }
#pragma unroll
        for (int ks = 0; ks < 2; ks++) {
            int kb = ch * 16 + ks * 8;
            uint32_t af[4];
            {
                int r = wrf * 16 + gid;
                af[0] = __float_as_uint(HT[r * HT_STRIDE + kb + tig]);
                af[1] = __float_as_uint(HT[(r + 8) * HT_STRIDE + kb + tig]);
                af[2] = __float_as_uint(HT[r * HT_STRIDE + kb + tig + 4]);
                af[3] = __float_as_uint(HT[(r + 8) * HT_STRIDE + kb + tig + 4]);
            }
#pragma unroll
            for (int nt = 0; nt < 4; nt++) {
                int c = wcf * 32 + nt * 8 + gid;
                uint32_t bf[2];
                bf[0] = tf32u(Wf[(cur * 16 + ks * 8 + tig) * 72 + c]);
                bf[1] = tf32u(Wf[(cur * 16 + ks * 8 + tig + 4) * 72 + c]);
                mma_tf32(fac[nt], af, bf);
            }
        }
        if (ch + 1 < FCH) {
            cp_wait0();
            __syncthreads();
        }
    }

    {
        int r  = m0 + wrf * 16 + gid;
        int r2 = r + 8;
#pragma unroll
        for (int nt = 0; nt < 4; nt++) {
            int c = wcf * 32 + nt * 8 + 2 * tig;
            float2 bi = *reinterpret_cast<const float2*>(&ffnB[c]);
            if (r < M)
                *reinterpret_cast<float2*>(&outf[(size_t)r * 256 + c]) =
                    make_float2(fac[nt][0] + bi.x, fac[nt][1] + bi.y);
            if (r2 < M)
                *reinterpret_cast<float2*>(&outf[(size_t)r2 * 256 + c]) =
                    make_float2(fac[nt][2] + bi.x, fac[nt][3] + bi.y);
        }
    }
}

// ---------------- standalone tf32 FFN GEMM (runs on side stream) ----------------
template<int BN, int WR, int WC>
__global__ __launch_bounds__(256)
void gemm_tf32(const float* __restrict__ A,
               const float* __restrict__ W, const float* __restrict__ bias,
               float* __restrict__ out,
               int M, int ldout, int ldw)
{
    constexpr int BM = 128, BK = 16, K = D;
    constexpr int NITER = K / BK;
    constexpr int TM = BM / WR;
    constexpr int TN = BN / WC;
    constexpr int MT = TM / 16;
    constexpr int NT = TN / 8;
    constexpr int PAD = 8;
    __shared__ float As[2][BK][BM + PAD];
    __shared__ float Bs[2][BK][BN + PAD];

    const int tid  = threadIdx.x;
    const int lane = tid & 31;
    const int wid  = tid >> 5;
    const int wr   = wid / WC;
    const int wc   = wid % WC;
    const int gid  = lane >> 2;
    const int tig  = lane & 3;
    const int m0   = blockIdx.x * BM;

    const int arow = tid & 127;
    const int akc  = (tid >> 7) << 3;
    const bool avalid = (m0 + arow) < M;
    const float* aptr = A + (size_t)(m0 + arow) * K + akc;

    constexpr int BVEC = (BN == 128) ? 2 : 1;
    const int bk  = tid >> 4;
    const int bnc = (tid & 15) * (BVEC * 4);
    const float* bptr = W + (size_t)bk * ldw + bnc;

    float4 a_st[2];
    float4 b_st[BVEC];

    a_st[0] = make_float4(0.f, 0.f, 0.f, 0.f);
    a_st[1] = a_st[0];
    if (avalid) {
        a_st[0] = *reinterpret_cast<const float4*>(aptr);
        a_st[1] = *reinterpret_cast<const float4*>(aptr + 4);
    }
#pragma unroll
    for (int i = 0; i < BVEC; i++)
        b_st[i] = *reinterpret_cast<const float4*>(bptr + i * 4);

    {
        const float* av = reinterpret_cast<const float*>(a_st);
#pragma unroll
        for (int j = 0; j < 8; j++) As[0][akc + j][arow] = tf32r(av[j]);
        const float* bv = reinterpret_cast<const float*>(b_st);
#pragma unroll
        for (int j = 0; j < BVEC * 4; j++) Bs[0][bk][bnc + j] = tf32r(bv[j]);
    }
    __syncthreads();

    float acc[MT][NT][4];
#pragma unroll
    for (int i = 0; i < MT; i++)
#pragma unroll
        for (int j = 0; j < NT; j++)
#pragma unroll
            for (int q = 0; q < 4; q++) acc[i][j][q] = 0.f;

    for (int k0 = 0; k0 < NITER; k0++) {
        const int cur = k0 & 1;
        if (k0 + 1 < NITER) {
            a_st[0] = make_float4(0.f, 0.f, 0.f, 0.f);
            a_st[1] = a_st[0];
            if (avalid) {
                a_st[0] = *reinterpret_cast<const float4*>(aptr + (k0 + 1) * BK);
                a_st[1] = *reinterpret_cast<const float4*>(aptr + (k0 + 1) * BK + 4);
            }
#pragma unroll
            for (int i = 0; i < BVEC; i++)
                b_st[i] = *reinterpret_cast<const float4*>(bptr + (size_t)(k0 + 1) * BK * ldw + i * 4);
        }
#pragma unroll
        for (int ks = 0; ks < 2; ks++) {
            uint32_t af[MT][4];
            uint32_t bf[NT][2];
#pragma unroll
            for (int mt = 0; mt < MT; mt++) {
                int r = wr * TM + mt * 16 + gid;
                af[mt][0] = __float_as_uint(As[cur][ks * 8 + tig    ][r]);
                af[mt][1] = __float_as_uint(As[cur][ks * 8 + tig    ][r + 8]);
                af[mt][2] = __float_as_uint(As[cur][ks * 8 + tig + 4][r]);
                af[mt][3] = __float_as_uint(As[cur][ks * 8 + tig + 4][r + 8]);
            }
#pragma unroll
            for (int nt = 0; nt < NT; nt++) {
                int c = wc * TN + nt * 8 + gid;
                bf[nt][0] = __float_as_uint(Bs[cur][ks * 8 + tig    ][c]);
                bf[nt][1] = __float_as_uint(Bs[cur][ks * 8 + tig + 4][c]);
            }
#pragma unroll
            for (int mt = 0; mt < MT; mt++)
#pragma unroll
                for (int nt = 0; nt < NT; nt++)
                    mma_tf32(acc[mt][nt], af[mt], bf[nt]);
        }
        if (k0 + 1 < NITER) {
            const int nxt = cur ^ 1;
            const float* av = reinterpret_cast<const float*>(a_st);
#pragma unroll
            for (int j = 0; j < 8; j++) As[nxt][akc + j][arow] = tf32r(av[j]);
            const float* bv = reinterpret_cast<const float*>(b_st);
#pragma unroll
            for (int j = 0; j < BVEC * 4; j++) Bs[nxt][bk][bnc + j] = tf32r(bv[j]);
            __syncthreads();
        }
    }

#pragma unroll
    for (int mt = 0; mt < MT; mt++) {
#pragma unroll
        for (int nt = 0; nt < NT; nt++) {
            int r = m0 + wr * TM + mt * 16 + gid;
            int c = wc * TN + nt * 8 + 2 * tig;
            float2 bi = *reinterpret_cast<const float2*>(&bias[c]);
            if (r < M)
                *reinterpret_cast<float2*>(&out[(size_t)r * ldout + c]) =
                    make_float2(acc[mt][nt][0] + bi.x, acc[mt][nt][1] + bi.y);
            int r2 = r + 8;
            if (r2 < M)
                *reinterpret_cast<float2*>(&out[(size_t)r2 * ldout + c]) =
                    make_float2(acc[mt][nt][2] + bi.x, acc[mt][nt][3] + bi.y);
        }
    }
}

// ---------------- virtual-node path ----------------
__device__ __forceinline__ void ln_rows8(float (*t)[D], float (*s)[D],
                                         const float* __restrict__ gam,
                                         const float* __restrict__ bet,
                                         float* smu, float* srs)
{
    int lane = threadIdx.x & 31, w = threadIdx.x >> 5;
    float a = 0.f, b = 0.f;
#pragma unroll
    for (int i = 0; i < 8; i++) {
        float v = t[w][lane + 32 * i];
        a += v; b += v * v;
    }
#pragma unroll
    for (int o = 16; o; o >>= 1) {
        a += __shfl_down_sync(0xffffffffu, a, o);
        b += __shfl_down_sync(0xffffffffu, b, o);
    }
    if (lane == 0) {
        float mu = a * (1.f / D);
        float var = b * (1.f / D) - mu * mu;
        smu[w] = mu;
        srs[w] = rsqrtf(var + LN_EPS);
    }
    __syncthreads();
    int d = threadIdx.x;
    float gd = gam[d], bd = bet[d];
#pragma unroll
    for (int gg = 0; gg < 8; gg++) {
        float v = (t[gg][d] - smu[gg]) * srs[gg] * gd + bd;
        s[gg][d] = fmaxf(v, 0.f);
    }
}

__global__ void vn_mlp_kernel(const float* __restrict__ h2, const int* __restrict__ off,
                              const float* __restrict__ W1, const float* __restrict__ b1,
                              const float* __restrict__ g1, const float* __restrict__ be1,
                              const float* __restrict__ W2, const float* __restrict__ b2,
                              const float* __restrict__ g2, const float* __restrict__ be2,
                              float* __restrict__ vn)
{
    __shared__ float s[8][D];
    __shared__ float t[8][D];
    __shared__ float smu[8], srs[8];
    int d = threadIdx.x;
    int g0 = blockIdx.x * 8;

#pragma unroll
    for (int gg = 0; gg < 8; gg++) {
        int g = g0 + gg;
        float acc = vn[(size_t)g * D + d];
        int n1 = off[g + 1];
        for (int n = off[g]; n < n1; n++)
            acc += h2[(size_t)n * D + d];
        s[gg][d] = acc;
    }
    __syncthreads();

    float y[8];
#pragma unroll
    for (int gg = 0; gg < 8; gg++) y[gg] = b1[d];
    for (int k = 0; k < D; k++) {
        float w = W1[(size_t)k * D + d];
#pragma unroll
        for (int gg = 0; gg < 8; gg++) y[gg] = fmaf(s[gg][k], w, y[gg]);
    }
    __syncthreads();
#pragma unroll
    for (int gg = 0; gg < 8; gg++) t[gg][d] = y[gg];
    __syncthreads();
    ln_rows8(t, s, g1, be1, smu, srs);
    __syncthreads();

#pragma unroll
    for (int gg = 0; gg < 8; gg++) y[gg] = b2[d];
    for (int k = 0; k < D; k++) {
        float w = W2[(size_t)k * D + d];
#pragma unroll
        for (int gg = 0; gg < 8; gg++) y[gg] = fmaf(s[gg][k], w, y[gg]);
    }
    __syncthreads();
#pragma unroll
    for (int gg = 0; gg < 8; gg++) t[gg][d] = y[gg];
    __syncthreads();
    ln_rows8(t, s, g2, be2, smu, srs);
    __syncthreads();
#pragma unroll
    for (int gg = 0; gg < 8; gg++)
        vn[(size_t)(g0 + gg) * D + d] = s[gg][d];
}

// ---------------- launcher ----------------
extern "C" void kernel_launch(void* const* d_in, const int* in_sizes, int n_in,
                              void* d_out, int out_size)
{
    const int*   x          = (const int*)  d_in[0];
    const int*   edge_attr  = (const int*)  d_in[1];
    const int*   edge_index = (const int*)  d_in[2];
    const int*   batch      = (const int*)  d_in[3];
    const float* atom_emb   = (const float*)d_in[4];
    const float* bond_emb   = (const float*)d_in[5];
    const float* vn_emb     = (const float*)d_in[6];
    const float* gcn_w      = (const float*)d_in[7];
    const float* gcn_b      = (const float*)d_in[8];
    const float* norm_g     = (const float*)d_in[9];
    const float* norm_b     = (const float*)d_in[10];
    const float* ffn_w      = (const float*)d_in[11];
    const float* ffn_b      = (const float*)d_in[12];
    const float* vn_w1      = (const float*)d_in[13];
    const float* vn_b1      = (const float*)d_in[14];
    const float* vn_g1      = (const float*)d_in[15];
    const float* vn_be1     = (const float*)d_in[16];
    const float* vn_w2      = (const float*)d_in[17];
    const float* vn_b2      = (const float*)d_in[18];
    const float* vn_g2      = (const float*)d_in[19];
    const float* vn_be2     = (const float*)d_in[20];

    float* out       = (float*)d_out;                       // h_graph [N,256]
    float* out_hinit = out + (size_t)N_NODES * D;           // h_init  [N,256]

    float *hb0, *hb1, *ph2, *pagg, *pvn; int* poff;
    cudaGetSymbolAddress((void**)&hb0,  g_h);
    cudaGetSymbolAddress((void**)&hb1,  g_hb);
    cudaGetSymbolAddress((void**)&ph2,  g_h2);
    cudaGetSymbolAddress((void**)&pagg, g_agg);
    cudaGetSymbolAddress((void**)&pvn,  g_vn);
    cudaGetSymbolAddress((void**)&poff, g_off);

    static cudaStream_t s1 = nullptr;
    static cudaEvent_t evFork, evSide, evH[3], evF[3];
    if (!s1) {
        cudaStreamCreateWithFlags(&s1, cudaStreamNonBlocking);
        cudaEventCreateWithFlags(&evFork, cudaEventDisableTiming);
        cudaEventCreateWithFlags(&evSide, cudaEventDisableTiming);
        for (int i = 0; i < 3; i++) {
            cudaEventCreateWithFlags(&evH[i], cudaEventDisableTiming);
            cudaEventCreateWithFlags(&evF[i], cudaEventDisableTiming);
        }
        cudaFuncSetAttribute(gemm_fused, cudaFuncAttributeMaxDynamicSharedMemorySize, SM_TOTAL);
    }

    const int FUSED_GRID = (N_NODES + 63) / 64;    // 1563
    const int FFN_GRID   = (N_NODES + 127) / 128;  // 782
    const int AGG_GRID   = (N_NODES + 3) / 4;

    float* hwr[4]  = {hb0, hb1, hb0, hb1};
    float* hres[4] = {nullptr, hb0, hb1, hb0};

    // ---- fork: prologue on two streams ----
    cudaEventRecord(evFork, 0);
    cudaStreamWaitEvent(s1, evFork, 0);

    // stream 0: CSR build chain
    zero_deg_kernel<<<(N_NODES + 255) / 256, 256>>>();
    hist_kernel<<<(N_EDGES + 255) / 256, 256>>>(edge_index);
    scan_block_kernel<<<NBLK, SCAN_B>>>();
    scan_sums_kernel<<<1, 128>>>();
    add_off_kernel<<<(N_NODES + 255) / 256, 256>>>();
    fill_kernel<<<(N_EDGES + 255) / 256, 256>>>(edge_index, edge_attr);

    // stream 1: node init, combo table, graph offsets
    node_init_kernel<<<N_NODES / 4, 256, 0, s1>>>(x, (const float4*)atom_emb,
                                                  (const float4*)vn_emb,
                                                  (float4*)hb0, (float4*)pvn,
                                                  (float4*)out_hinit);
    combo_kernel<<<512, 256, 0, s1>>>(bond_emb);
    offsets_kernel<<<(NGRAPHS + 1 + 255) / 256, 256, 0, s1>>>(batch, poff);
    cudaEventRecord(evSide, s1);
    cudaStreamWaitEvent(0, evSide, 0);

    // ----- layer 0 -----
    aggregate_kernel<false><<<AGG_GRID, 256>>>((const float4*)hb0, nullptr, nullptr, (float4*)pagg);
    gemm_fused<<<FUSED_GRID, 256, SM_TOTAL>>>(pagg, gcn_w, gcn_b, nullptr,
                                              norm_g, norm_b, nullptr, nullptr,
                                              hwr[0], ph2, nullptr, N_NODES);
    cudaEventRecord(evH[0], 0);
    cudaStreamWaitEvent(s1, evH[0], 0);
    gemm_tf32<64, 4, 2><<<FFN_GRID, 256, 0, s1>>>(hwr[0], ffn_w, ffn_b, out, N_NODES, D, 64);
    cudaEventRecord(evF[0], s1);

    // ----- layers 1..2 (FFN on side stream) -----
    for (int l = 1; l < 3; l++) {
        int j = l - 1;
        vn_mlp_kernel<<<NGRAPHS / 8, 256>>>(ph2, poff,
                                            vn_w1 + (size_t)j * D * D, vn_b1 + (size_t)j * D,
                                            vn_g1 + (size_t)j * D,     vn_be1 + (size_t)j * D,
                                            vn_w2 + (size_t)j * D * D, vn_b2 + (size_t)j * D,
                                            vn_g2 + (size_t)j * D,     vn_be2 + (size_t)j * D,
                                            pvn);
        aggregate_kernel<true><<<AGG_GRID, 256>>>((const float4*)ph2, (const float4*)pvn,
                                                  batch, (float4*)pagg);
        if (l == 2) cudaStreamWaitEvent(0, evF[0], 0);    // about to rewrite hb0
        gemm_fused<<<FUSED_GRID, 256, SM_TOTAL>>>(pagg, gcn_w + (size_t)l * D * D,
                                                  gcn_b + (size_t)l * D, hres[l],
                                                  norm_g + (size_t)l * D, norm_b + (size_t)l * D,
                                                  nullptr, nullptr,
                                                  hwr[l], ph2, nullptr, N_NODES);
        cudaEventRecord(evH[l], 0);
        cudaStreamWaitEvent(s1, evH[l], 0);
        gemm_tf32<64, 4, 2><<<FFN_GRID, 256, 0, s1>>>(hwr[l], ffn_w + (size_t)l * D * 64,
                                                      ffn_b + (size_t)l * 64,
                                                      out + (size_t)l * 64, N_NODES, D, 64);
        cudaEventRecord(evF[l], s1);
    }

    // ----- layer 3 (FFN fused; nothing left to overlap) -----
    {
        int l = 3, j = 2;
        vn_mlp_kernel<<<NGRAPHS / 8, 256>>>(ph2, poff,
                                            vn_w1 + (size_t)j * D * D, vn_b1 + (size_t)j * D,
                                            vn_g1 + (size_t)j * D,     vn_be1 + (size_t)j * D,
                                            vn_w2 + (size_t)j * D * D, vn_b2 + (size_t)j * D,
                                            vn_g2 + (size_t)j * D,     vn_be2 + (size_t)j * D,
                                            pvn);
        aggregate_kernel<true><<<AGG_GRID, 256>>>((const float4*)ph2, (const float4*)pvn,
                                                  batch, (float4*)pagg);
        cudaStreamWaitEvent(0, evF[1], 0);                // about to rewrite hb1
        gemm_fused<<<FUSED_GRID, 256, SM_TOTAL>>>(pagg, gcn_w + (size_t)l * D * D,
                                                  gcn_b + (size_t)l * D, hres[l],
                                                  nullptr, nullptr,
                                                  ffn_w + (size_t)l * D * 64,
                                                  ffn_b + (size_t)l * 64,
                                                  hwr[l], ph2, out + (size_t)l * 64, N_NODES);
    }

    // ---- join side stream before returning ----
    cudaStreamWaitEvent(0, evF[2], 0);
}